// round 3
// baseline (speedup 1.0000x reference)
#include <cuda_runtime.h>
#include <math.h>

#define DIM    1024
#define BATCH  2
#define TLEN   2048
#define HEADS  16
#define HD     64
#define ROWS   (BATCH*TLEN)          // 4096
#define HROWS  (BATCH*HEADS*TLEN)    // 65536
#define THRESH 0.29514f
#define SHARP  15.0f

// ---------------- scratch (device globals: no allocations allowed) ----------
__device__ float d_xnorm[ROWS*DIM];
__device__ float d_Q[HROWS*HD];
__device__ float d_K[HROWS*HD];
__device__ float d_V[HROWS*HD];
__device__ float d_gq[HROWS];
__device__ float d_coll[ROWS*DIM];

// ---------------- LayerNorm: one block per row --------------------------------
__global__ void ln_kernel(const float* __restrict__ x,
                          const float* __restrict__ w,
                          const float* __restrict__ bvec) {
    int row = blockIdx.x;
    int tid = threadIdx.x;
    float4 v = ((const float4*)(x + (size_t)row*DIM))[tid];
    float s  = v.x + v.y + v.z + v.w;
    float ss = v.x*v.x + v.y*v.y + v.z*v.z + v.w*v.w;
    #pragma unroll
    for (int o = 16; o > 0; o >>= 1) {
        s  += __shfl_xor_sync(0xffffffffu, s,  o);
        ss += __shfl_xor_sync(0xffffffffu, ss, o);
    }
    __shared__ float rs[8], rss[8];
    int wid = tid >> 5, lane = tid & 31;
    if (lane == 0) { rs[wid] = s; rss[wid] = ss; }
    __syncthreads();
    s = 0.f; ss = 0.f;
    #pragma unroll
    for (int i = 0; i < 8; i++) { s += rs[i]; ss += rss[i]; }
    float mean = s * (1.0f/DIM);
    float var  = ss * (1.0f/DIM) - mean*mean;
    float rstd = rsqrtf(var + 1e-5f);
    float4 wv = ((const float4*)w)[tid];
    float4 bv = ((const float4*)bvec)[tid];
    float4 o;
    o.x = (v.x-mean)*rstd*wv.x + bv.x;
    o.y = (v.y-mean)*rstd*wv.y + bv.y;
    o.z = (v.z-mean)*rstd*wv.z + bv.z;
    o.w = (v.w-mean)*rstd*wv.w + bv.w;
    ((float4*)(d_xnorm + (size_t)row*DIM))[tid] = o;
}

// ---------------- 128x128x8 SGEMM for Q/K/V projections -----------------------
// z=0: xnorm@Wq -> Q(head-major), z=1: xnorm@Wk -> K, z=2: x@Wv -> V
__global__ __launch_bounds__(256)
void gemm_qkv_kernel(const float* __restrict__ x,
                     const float* __restrict__ Wq,
                     const float* __restrict__ Wk,
                     const float* __restrict__ Wv) {
    __shared__ float As[8][132];
    __shared__ float Bs[8][132];
    int z = blockIdx.z;
    const float* A = (z == 2) ? x : d_xnorm;
    const float* W = (z == 0) ? Wq : (z == 1) ? Wk : Wv;
    float* dst = (z == 0) ? d_Q : (z == 1) ? d_K : d_V;

    int tid = threadIdx.x;
    int tx = tid & 15, ty = tid >> 4;
    int m0 = blockIdx.y * 128, n0 = blockIdx.x * 128;

    float acc[8][8];
    #pragma unroll
    for (int i = 0; i < 8; i++)
        #pragma unroll
        for (int j = 0; j < 8; j++) acc[i][j] = 0.f;

    int ar = tid >> 1, ac = (tid & 1) * 4;     // A tile: 128 rows x 8 cols
    int br = tid >> 5, bc = (tid & 31) * 4;    // B tile: 8 rows x 128 cols
    const float* Aptr = A + (size_t)(m0 + ar)*DIM + ac;
    const float* Wptr = W + (size_t)br*DIM + n0 + bc;

    for (int k0 = 0; k0 < DIM; k0 += 8) {
        float4 av = *(const float4*)(Aptr + k0);
        float4 bv = *(const float4*)(Wptr + (size_t)k0*DIM);
        __syncthreads();
        As[ac+0][ar] = av.x; As[ac+1][ar] = av.y;
        As[ac+2][ar] = av.z; As[ac+3][ar] = av.w;
        *(float4*)&Bs[br][bc] = bv;
        __syncthreads();
        #pragma unroll
        for (int kk = 0; kk < 8; kk++) {
            float4 a0 = *(const float4*)&As[kk][ty*8];
            float4 a1 = *(const float4*)&As[kk][ty*8+4];
            float4 b0 = *(const float4*)&Bs[kk][tx*8];
            float4 b1 = *(const float4*)&Bs[kk][tx*8+4];
            float a[8] = {a0.x,a0.y,a0.z,a0.w,a1.x,a1.y,a1.z,a1.w};
            float bb[8] = {b0.x,b0.y,b0.z,b0.w,b1.x,b1.y,b1.z,b1.w};
            #pragma unroll
            for (int i = 0; i < 8; i++)
                #pragma unroll
                for (int j = 0; j < 8; j++)
                    acc[i][j] = fmaf(a[i], bb[j], acc[i][j]);
        }
    }

    // store head-major: [b,h,t,d]
    #pragma unroll
    for (int i = 0; i < 8; i++) {
        int m = m0 + ty*8 + i;
        int b = m >> 11, t = m & 2047;
        #pragma unroll
        for (int j = 0; j < 8; j++) {
            int n = n0 + tx*8 + j;
            int h = n >> 6, dd = n & 63;
            dst[(((size_t)(b*HEADS + h))*TLEN + t)*HD + dd] = acc[i][j];
        }
    }
}

// ---------------- per-head L2 normalize + gates, fold gate_k into V -----------
__global__ void normgate_kernel(const float* __restrict__ gqv,
                                const float* __restrict__ gkv) {
    int r = (blockIdx.x * blockDim.x + threadIdx.x) >> 5;
    int lane = threadIdx.x & 31;
    if (r >= HROWS) return;
    float* q = d_Q + (size_t)r*HD;
    float* k = d_K + (size_t)r*HD;
    float* v = d_V + (size_t)r*HD;

    float q0 = q[lane], q1 = q[lane+32];
    float ss = q0*q0 + q1*q1;
    #pragma unroll
    for (int o = 16; o > 0; o >>= 1) ss += __shfl_xor_sync(0xffffffffu, ss, o);
    float inv = 1.0f / fmaxf(sqrtf(ss), 1e-12f);
    q0 *= inv; q1 *= inv;
    q[lane] = q0; q[lane+32] = q1;
    float g = q0*gqv[lane] + q1*gqv[lane+32];
    #pragma unroll
    for (int o = 16; o > 0; o >>= 1) g += __shfl_xor_sync(0xffffffffu, g, o);
    if (lane == 0) d_gq[r] = g;

    float k0 = k[lane], k1 = k[lane+32];
    ss = k0*k0 + k1*k1;
    #pragma unroll
    for (int o = 16; o > 0; o >>= 1) ss += __shfl_xor_sync(0xffffffffu, ss, o);
    inv = 1.0f / fmaxf(sqrtf(ss), 1e-12f);
    k0 *= inv; k1 *= inv;
    k[lane] = k0; k[lane+32] = k1;
    float gk = k0*gkv[lane] + k1*gkv[lane+32];
    #pragma unroll
    for (int o = 16; o > 0; o >>= 1) gk += __shfl_xor_sync(0xffffffffu, gk, o);
    v[lane]    *= gk;
    v[lane+32] *= gk;
}

// ---------------- fused attention: 64t x 64s tiles, P in smem -----------------
// collapse[t,:] = gq[t] * sum_s sigmoid((q_t . k_s - TH)*SHARP) * (gk_s * v_s)
__global__ __launch_bounds__(128)
void attn_kernel() {
    extern __shared__ float sm[];
    float* Qs = sm;              // [d][t]  64 x 68
    float* Ks = sm + 64*68;      // [d][s]
    float* Vs = sm + 2*64*68;    // [s][d]
    float* Ps = sm + 3*64*68;    // [s][t]
    __shared__ float gqs[64];

    int tid = threadIdx.x;
    int h = blockIdx.y, b = blockIdx.z;
    int t0 = blockIdx.x * 64;
    size_t base = (size_t)(b*HEADS + h)*TLEN;
    const float* Qg = d_Q + (base + t0)*HD;
    const float* Kb = d_K + base*HD;
    const float* Vb = d_V + base*HD;

    for (int e = tid; e < 4096; e += 128) {
        int t = e >> 6, dd = e & 63;
        Qs[dd*68 + t] = Qg[e];
    }
    if (tid < 64) gqs[tid] = d_gq[base + t0 + tid];

    int tx = tid & 15, ty = tid >> 4;   // tx: 16 cols of 4, ty: 8 rows of 8
    float acc[8][4];
    #pragma unroll
    for (int i = 0; i < 8; i++)
        #pragma unroll
        for (int j = 0; j < 4; j++) acc[i][j] = 0.f;

    for (int s0 = 0; s0 < TLEN; s0 += 64) {
        __syncthreads();   // prior P.V reads of Ps/Vs done before overwrite
        const float* Kg = Kb + (size_t)s0*HD;
        const float* Vg = Vb + (size_t)s0*HD;
        for (int e = tid; e < 4096; e += 128) {
            int s = e >> 6, dd = e & 63;
            Ks[dd*68 + s] = Kg[e];
            Vs[s*68 + dd] = Vg[e];
        }
        __syncthreads();

        // P = sigmoid((Q.K^T - TH)*SHARP)
        float p[8][4];
        #pragma unroll
        for (int i = 0; i < 8; i++)
            #pragma unroll
            for (int j = 0; j < 4; j++) p[i][j] = 0.f;
        #pragma unroll 8
        for (int kk = 0; kk < 64; kk++) {
            float4 a0 = *(const float4*)&Qs[kk*68 + ty*8];
            float4 a1 = *(const float4*)&Qs[kk*68 + ty*8 + 4];
            float4 bv = *(const float4*)&Ks[kk*68 + tx*4];
            float a[8] = {a0.x,a0.y,a0.z,a0.w,a1.x,a1.y,a1.z,a1.w};
            float bb[4] = {bv.x,bv.y,bv.z,bv.w};
            #pragma unroll
            for (int i = 0; i < 8; i++)
                #pragma unroll
                for (int j = 0; j < 4; j++)
                    p[i][j] = fmaf(a[i], bb[j], p[i][j]);
        }
        #pragma unroll
        for (int i = 0; i < 8; i++)
            #pragma unroll
            for (int j = 0; j < 4; j++) {
                float zv = (p[i][j] - THRESH) * SHARP;
                float r = 1.0f / (1.0f + __expf(-zv));
                Ps[(tx*4 + j)*68 + ty*8 + i] = r;
            }
        __syncthreads();

        // acc += P @ V'
        #pragma unroll 8
        for (int ssi = 0; ssi < 64; ssi++) {
            float4 a0 = *(const float4*)&Ps[ssi*68 + ty*8];
            float4 a1 = *(const float4*)&Ps[ssi*68 + ty*8 + 4];
            float4 vv = *(const float4*)&Vs[ssi*68 + tx*4];
            float a[8] = {a0.x,a0.y,a0.z,a0.w,a1.x,a1.y,a1.z,a1.w};
            float bb[4] = {vv.x,vv.y,vv.z,vv.w};
            #pragma unroll
            for (int i = 0; i < 8; i++)
                #pragma unroll
                for (int j = 0; j < 4; j++)
                    acc[i][j] = fmaf(a[i], bb[j], acc[i][j]);
        }
    }

    // epilogue: * gate_q, scatter back to [B,T,D]
    float* Cb = d_coll + ((size_t)(b*TLEN) + t0)*DIM + h*HD;
    #pragma unroll
    for (int i = 0; i < 8; i++) {
        int t = ty*8 + i;
        float gm = gqs[t];
        #pragma unroll
        for (int j = 0; j < 4; j++)
            Cb[(size_t)t*DIM + tx*4 + j] = acc[i][j] * gm;
    }
}

// ---------------- output GEMM: collapse @ Wo + bo -----------------------------
__global__ __launch_bounds__(256)
void gemm_out_kernel(const float* __restrict__ W,
                     const float* __restrict__ bo,
                     float* __restrict__ out) {
    __shared__ float As[8][132];
    __shared__ float Bs[8][132];
    int tid = threadIdx.x;
    int tx = tid & 15, ty = tid >> 4;
    int m0 = blockIdx.y * 128, n0 = blockIdx.x * 128;

    float acc[8][8];
    #pragma unroll
    for (int i = 0; i < 8; i++)
        #pragma unroll
        for (int j = 0; j < 8; j++) acc[i][j] = 0.f;

    int ar = tid >> 1, ac = (tid & 1) * 4;
    int br = tid >> 5, bc = (tid & 31) * 4;
    const float* Aptr = d_coll + (size_t)(m0 + ar)*DIM + ac;
    const float* Wptr = W + (size_t)br*DIM + n0 + bc;

    for (int k0 = 0; k0 < DIM; k0 += 8) {
        float4 av = *(const float4*)(Aptr + k0);
        float4 bv = *(const float4*)(Wptr + (size_t)k0*DIM);
        __syncthreads();
        As[ac+0][ar] = av.x; As[ac+1][ar] = av.y;
        As[ac+2][ar] = av.z; As[ac+3][ar] = av.w;
        *(float4*)&Bs[br][bc] = bv;
        __syncthreads();
        #pragma unroll
        for (int kk = 0; kk < 8; kk++) {
            float4 a0 = *(const float4*)&As[kk][ty*8];
            float4 a1 = *(const float4*)&As[kk][ty*8+4];
            float4 b0 = *(const float4*)&Bs[kk][tx*8];
            float4 b1 = *(const float4*)&Bs[kk][tx*8+4];
            float a[8] = {a0.x,a0.y,a0.z,a0.w,a1.x,a1.y,a1.z,a1.w};
            float bb[8] = {b0.x,b0.y,b0.z,b0.w,b1.x,b1.y,b1.z,b1.w};
            #pragma unroll
            for (int i = 0; i < 8; i++)
                #pragma unroll
                for (int j = 0; j < 8; j++)
                    acc[i][j] = fmaf(a[i], bb[j], acc[i][j]);
        }
    }

    #pragma unroll
    for (int i = 0; i < 8; i++) {
        int m = m0 + ty*8 + i;
        #pragma unroll
        for (int j = 0; j < 8; j++) {
            int n = n0 + tx*8 + j;
            out[(size_t)m*DIM + n] = acc[i][j] + bo[n];
        }
    }
}

// ---------------- launch ------------------------------------------------------
extern "C" void kernel_launch(void* const* d_in, const int* in_sizes, int n_in,
                              void* d_out, int out_size) {
    const float* x   = (const float*)d_in[0];
    const float* Wq  = (const float*)d_in[1];
    const float* Wk  = (const float*)d_in[2];
    const float* Wv  = (const float*)d_in[3];
    const float* gqv = (const float*)d_in[4];
    const float* gkv = (const float*)d_in[5];
    const float* Wo  = (const float*)d_in[6];
    const float* bo  = (const float*)d_in[7];
    const float* lnw = (const float*)d_in[8];
    const float* lnb = (const float*)d_in[9];
    float* out = (float*)d_out;

    const int attn_smem = 4*64*68*4;  // 69632 B
    cudaFuncSetAttribute(attn_kernel,
                         cudaFuncAttributeMaxDynamicSharedMemorySize, attn_smem);

    ln_kernel<<<ROWS, 256>>>(x, lnw, lnb);
    gemm_qkv_kernel<<<dim3(8, 32, 3), 256>>>(x, Wq, Wk, Wv);
    normgate_kernel<<<HROWS*32/256, 256>>>(gqv, gkv);
    attn_kernel<<<dim3(TLEN/64, HEADS, BATCH), 128, attn_smem>>>();
    gemm_out_kernel<<<dim3(8, 32), 256>>>(Wo, bo, out);
}

// round 6
// speedup vs baseline: 1.8915x; 1.8915x over previous
#include <cuda_runtime.h>
#include <cstdint>
#include <math.h>

#define DIM    1024
#define BATCH  2
#define TLEN   2048
#define HEADS  16
#define HD     64
#define ROWS   (BATCH*TLEN)
#define HROWS  (BATCH*HEADS*TLEN)
#define THRESH 0.29514f
#define SHARP  15.0f

__device__ float d_xnorm[ROWS*DIM];
__device__ float d_Q[HROWS*HD];
__device__ float d_K[HROWS*HD];
__device__ float d_V[HROWS*HD];
__device__ float d_gq[HROWS];
__device__ float d_coll[ROWS*DIM];

// ---------------- mma.sync m16n8k8 tf32 (sm_80 path, works on sm_103) --------
__device__ __forceinline__ void mma_tf32(float* c, const uint32_t* a, const uint32_t* b) {
    asm volatile(
        "mma.sync.aligned.m16n8k8.row.col.f32.tf32.tf32.f32 "
        "{%0,%1,%2,%3}, {%4,%5,%6,%7}, {%8,%9}, {%0,%1,%2,%3};"
        : "+f"(c[0]), "+f"(c[1]), "+f"(c[2]), "+f"(c[3])
        : "r"(a[0]), "r"(a[1]), "r"(a[2]), "r"(a[3]), "r"(b[0]), "r"(b[1]));
}
__device__ __forceinline__ float hi_part(float v) {
    return __int_as_float(__float_as_int(v) & 0xFFFFE000);
}

// ---------------- LayerNorm ----------------
__global__ void ln_kernel(const float* __restrict__ x,
                          const float* __restrict__ w,
                          const float* __restrict__ bvec) {
    int row = blockIdx.x, tid = threadIdx.x;
    float4 v = ((const float4*)(x + (size_t)row*DIM))[tid];
    float s  = v.x+v.y+v.z+v.w;
    float ss = v.x*v.x+v.y*v.y+v.z*v.z+v.w*v.w;
    #pragma unroll
    for (int o = 16; o > 0; o >>= 1) {
        s  += __shfl_xor_sync(~0u, s, o);
        ss += __shfl_xor_sync(~0u, ss, o);
    }
    __shared__ float rs[8], rss[8];
    int wid = tid >> 5, lane = tid & 31;
    if (lane == 0) { rs[wid] = s; rss[wid] = ss; }
    __syncthreads();
    s = 0.f; ss = 0.f;
    #pragma unroll
    for (int i = 0; i < 8; i++) { s += rs[i]; ss += rss[i]; }
    float mean = s*(1.f/DIM), var = ss*(1.f/DIM) - mean*mean;
    float rstd = rsqrtf(var + 1e-5f);
    float4 wv = ((const float4*)w)[tid], bv = ((const float4*)bvec)[tid];
    float4 o;
    o.x = (v.x-mean)*rstd*wv.x + bv.x;  o.y = (v.y-mean)*rstd*wv.y + bv.y;
    o.z = (v.z-mean)*rstd*wv.z + bv.z;  o.w = (v.w-mean)*rstd*wv.w + bv.w;
    ((float4*)(d_xnorm + (size_t)row*DIM))[tid] = o;
}

// ---------------- tf32x3 tensor-core GEMM: 128x128 tile, K-chunk 32 ----------
// C[m][n] = A[m][k] * W[k][n]; 8 warps as 4(m) x 2(n), warp tile 32x64.
#define A_STRIDE 36
#define B_STRIDE 132
#define SM_AH 0
#define SM_AL (128*A_STRIDE)
#define SM_BH (2*128*A_STRIDE)
#define SM_BL (2*128*A_STRIDE + 32*B_STRIDE)
#define GEMM_SMEM ((2*128*A_STRIDE + 2*32*B_STRIDE)*4)

template<int MODE>   // 0: QKV (z = blockIdx.z), 1: out = coll@Wo + bo
__global__ __launch_bounds__(256, 1)
void gemm_ts(const float* __restrict__ x,
             const float* __restrict__ Wq, const float* __restrict__ Wk,
             const float* __restrict__ Wv, const float* __restrict__ Wo,
             const float* __restrict__ bo, float* __restrict__ outp) {
    extern __shared__ float sm[];
    int tid = threadIdx.x, lane = tid & 31;
    int warp = tid >> 5, warpM = warp >> 1, warpN = warp & 1;
    int z = (MODE == 0) ? (int)blockIdx.z : 3;
    int m0 = blockIdx.y*128, n0 = blockIdx.x*128;
    const float* A = (MODE == 0) ? ((z == 2) ? x : d_xnorm) : d_coll;
    const float* W = (MODE == 0) ? ((z == 0) ? Wq : (z == 1) ? Wk : Wv) : Wo;

    float c[2][8][4];
    #pragma unroll
    for (int mt = 0; mt < 2; mt++)
        #pragma unroll
        for (int nt = 0; nt < 8; nt++)
            #pragma unroll
            for (int i = 0; i < 4; i++) c[mt][nt][i] = 0.f;

    // A tile 128x32 = 1024 float4; B tile 32x128 = 1024 float4; 256 thr x 4 iter
    float4 pa[4], pb[4];
    const float* Abase = A + (size_t)m0*DIM;
    const float* Wbase = W + n0;

    #pragma unroll
    for (int j = 0; j < 4; j++) {
        int idx = tid + 256*j;
        pa[j] = *(const float4*)(Abase + (size_t)(idx >> 3)*DIM + (idx & 7)*4);
        pb[j] = *(const float4*)(Wbase + (size_t)(idx >> 5)*DIM + (idx & 31)*4);
    }

    for (int ch = 0; ch < DIM/32; ch++) {
        #pragma unroll
        for (int j = 0; j < 4; j++) {
            int idx = tid + 256*j;
            int r = idx >> 3, kq = idx & 7;
            float4 v = pa[j];
            float4 h = make_float4(hi_part(v.x), hi_part(v.y), hi_part(v.z), hi_part(v.w));
            *(float4*)&sm[SM_AH + r*A_STRIDE + kq*4] = h;
            *(float4*)&sm[SM_AL + r*A_STRIDE + kq*4] =
                make_float4(v.x-h.x, v.y-h.y, v.z-h.z, v.w-h.w);
            int br = idx >> 5, nq = idx & 31;
            v = pb[j];
            h = make_float4(hi_part(v.x), hi_part(v.y), hi_part(v.z), hi_part(v.w));
            *(float4*)&sm[SM_BH + br*B_STRIDE + nq*4] = h;
            *(float4*)&sm[SM_BL + br*B_STRIDE + nq*4] =
                make_float4(v.x-h.x, v.y-h.y, v.z-h.z, v.w-h.w);
        }
        __syncthreads();

        if (ch + 1 < DIM/32) {
            int k0n = (ch + 1)*32;
            #pragma unroll
            for (int j = 0; j < 4; j++) {
                int idx = tid + 256*j;
                pa[j] = *(const float4*)(Abase + (size_t)(idx >> 3)*DIM + k0n + (idx & 7)*4);
                pb[j] = *(const float4*)(Wbase + (size_t)((idx >> 5) + k0n)*DIM + (idx & 31)*4);
            }
        }

        #pragma unroll
        for (int k8 = 0; k8 < 4; k8++) {
            uint32_t ah[2][4], al[2][4];
            #pragma unroll
            for (int mt = 0; mt < 2; mt++) {
                int rA = warpM*32 + mt*16 + (lane >> 2);
                int cA = k8*8 + (lane & 3);
                ah[mt][0] = __float_as_uint(sm[SM_AH + rA*A_STRIDE + cA]);
                ah[mt][1] = __float_as_uint(sm[SM_AH + (rA+8)*A_STRIDE + cA]);
                ah[mt][2] = __float_as_uint(sm[SM_AH + rA*A_STRIDE + cA + 4]);
                ah[mt][3] = __float_as_uint(sm[SM_AH + (rA+8)*A_STRIDE + cA + 4]);
                al[mt][0] = __float_as_uint(sm[SM_AL + rA*A_STRIDE + cA]);
                al[mt][1] = __float_as_uint(sm[SM_AL + (rA+8)*A_STRIDE + cA]);
                al[mt][2] = __float_as_uint(sm[SM_AL + rA*A_STRIDE + cA + 4]);
                al[mt][3] = __float_as_uint(sm[SM_AL + (rA+8)*A_STRIDE + cA + 4]);
            }
            #pragma unroll
            for (int nt = 0; nt < 8; nt++) {
                int cB = warpN*64 + nt*8 + (lane >> 2);
                int rB = k8*8 + (lane & 3);
                uint32_t bh[2], bl[2];
                bh[0] = __float_as_uint(sm[SM_BH + rB*B_STRIDE + cB]);
                bh[1] = __float_as_uint(sm[SM_BH + (rB+4)*B_STRIDE + cB]);
                bl[0] = __float_as_uint(sm[SM_BL + rB*B_STRIDE + cB]);
                bl[1] = __float_as_uint(sm[SM_BL + (rB+4)*B_STRIDE + cB]);
                #pragma unroll
                for (int mt = 0; mt < 2; mt++) {
                    mma_tf32(c[mt][nt], ah[mt], bh);
                    mma_tf32(c[mt][nt], ah[mt], bl);
                    mma_tf32(c[mt][nt], al[mt], bh);
                }
            }
        }
        __syncthreads();
    }

    #pragma unroll
    for (int mt = 0; mt < 2; mt++) {
        #pragma unroll
        for (int nt = 0; nt < 8; nt++) {
            int row = m0 + warpM*32 + mt*16 + (lane >> 2);
            int col = n0 + warpN*64 + nt*8 + (lane & 3)*2;
            #pragma unroll
            for (int half = 0; half < 2; half++) {
                int r = row + half*8;
                float2 v = make_float2(c[mt][nt][half*2], c[mt][nt][half*2+1]);
                if (MODE == 0) {
                    float* dst = (z == 0) ? d_Q : (z == 1) ? d_K : d_V;
                    int b = r >> 11, t = r & 2047;
                    int h = col >> 6, dd = col & 63;
                    *(float2*)&dst[(((size_t)(b*HEADS + h))*TLEN + t)*HD + dd] = v;
                } else {
                    v.x += bo[col]; v.y += bo[col+1];
                    *(float2*)&outp[(size_t)r*DIM + col] = v;
                }
            }
        }
    }
}

// ---------------- L2 normalize + gates, fold gate_k into V --------------------
__global__ void normgate_kernel(const float* __restrict__ gqv,
                                const float* __restrict__ gkv) {
    int r = (blockIdx.x*blockDim.x + threadIdx.x) >> 5;
    int lane = threadIdx.x & 31;
    if (r >= HROWS) return;
    float* q = d_Q + (size_t)r*HD;
    float* k = d_K + (size_t)r*HD;
    float* v = d_V + (size_t)r*HD;

    float q0 = q[lane], q1 = q[lane+32];
    float ss = q0*q0 + q1*q1;
    #pragma unroll
    for (int o = 16; o > 0; o >>= 1) ss += __shfl_xor_sync(~0u, ss, o);
    float inv = 1.0f / fmaxf(sqrtf(ss), 1e-12f);
    q0 *= inv; q1 *= inv;
    q[lane] = q0; q[lane+32] = q1;
    float g = q0*gqv[lane] + q1*gqv[lane+32];
    #pragma unroll
    for (int o = 16; o > 0; o >>= 1) g += __shfl_xor_sync(~0u, g, o);
    if (lane == 0) d_gq[r] = g;

    float k0 = k[lane], k1 = k[lane+32];
    ss = k0*k0 + k1*k1;
    #pragma unroll
    for (int o = 16; o > 0; o >>= 1) ss += __shfl_xor_sync(~0u, ss, o);
    inv = 1.0f / fmaxf(sqrtf(ss), 1e-12f);
    k0 *= inv; k1 *= inv;
    k[lane] = k0; k[lane+32] = k1;
    float gk = k0*gkv[lane] + k1*gkv[lane+32];
    #pragma unroll
    for (int o = 16; o > 0; o >>= 1) gk += __shfl_xor_sync(~0u, gk, o);
    v[lane]    *= gk;
    v[lane+32] *= gk;
}

// ---------------- fused attention (fp32, proven) ------------------------------
__global__ __launch_bounds__(128)
void attn_kernel() {
    extern __shared__ float sm[];
    float* Qs = sm;
    float* Ks = sm + 64*68;
    float* Vs = sm + 2*64*68;
    float* Ps = sm + 3*64*68;
    __shared__ float gqs[64];

    int tid = threadIdx.x;
    int h = blockIdx.y, b = blockIdx.z;
    int t0 = blockIdx.x * 64;
    size_t base = (size_t)(b*HEADS + h)*TLEN;
    const float* Qg = d_Q + (base + t0)*HD;
    const float* Kb = d_K + base*HD;
    const float* Vb = d_V + base*HD;

    for (int e = tid; e < 4096; e += 128) {
        int t = e >> 6, dd = e & 63;
        Qs[dd*68 + t] = Qg[e];
    }
    if (tid < 64) gqs[tid] = d_gq[base + t0 + tid];

    int tx = tid & 15, ty = tid >> 4;
    float acc[8][4];
    #pragma unroll
    for (int i = 0; i < 8; i++)
        #pragma unroll
        for (int j = 0; j < 4; j++) acc[i][j] = 0.f;

    for (int s0 = 0; s0 < TLEN; s0 += 64) {
        __syncthreads();
        const float* Kg = Kb + (size_t)s0*HD;
        const float* Vg = Vb + (size_t)s0*HD;
        for (int e = tid; e < 4096; e += 128) {
            int s = e >> 6, dd = e & 63;
            Ks[dd*68 + s] = Kg[e];
            Vs[s*68 + dd] = Vg[e];
        }
        __syncthreads();

        float p[8][4];
        #pragma unroll
        for (int i = 0; i < 8; i++)
            #pragma unroll
            for (int j = 0; j < 4; j++) p[i][j] = 0.f;
        #pragma unroll 8
        for (int kk = 0; kk < 64; kk++) {
            float4 a0 = *(const float4*)&Qs[kk*68 + ty*8];
            float4 a1 = *(const float4*)&Qs[kk*68 + ty*8 + 4];
            float4 bv = *(const float4*)&Ks[kk*68 + tx*4];
            float a[8] = {a0.x,a0.y,a0.z,a0.w,a1.x,a1.y,a1.z,a1.w};
            float bb[4] = {bv.x,bv.y,bv.z,bv.w};
            #pragma unroll
            for (int i = 0; i < 8; i++)
                #pragma unroll
                for (int j = 0; j < 4; j++)
                    p[i][j] = fmaf(a[i], bb[j], p[i][j]);
        }
        #pragma unroll
        for (int i = 0; i < 8; i++)
            #pragma unroll
            for (int j = 0; j < 4; j++) {
                float zv = (p[i][j] - THRESH) * SHARP;
                float r = 1.0f / (1.0f + __expf(-zv));
                Ps[(tx*4 + j)*68 + ty*8 + i] = r;
            }
        __syncthreads();

        #pragma unroll 8
        for (int ssi = 0; ssi < 64; ssi++) {
            float4 a0 = *(const float4*)&Ps[ssi*68 + ty*8];
            float4 a1 = *(const float4*)&Ps[ssi*68 + ty*8 + 4];
            float4 vv = *(const float4*)&Vs[ssi*68 + tx*4];
            float a[8] = {a0.x,a0.y,a0.z,a0.w,a1.x,a1.y,a1.z,a1.w};
            float bb[4] = {vv.x,vv.y,vv.z,vv.w};
            #pragma unroll
            for (int i = 0; i < 8; i++)
                #pragma unroll
                for (int j = 0; j < 4; j++)
                    acc[i][j] = fmaf(a[i], bb[j], acc[i][j]);
        }
    }

    float* Cb = d_coll + ((size_t)(b*TLEN) + t0)*DIM + h*HD;
    #pragma unroll
    for (int i = 0; i < 8; i++) {
        int t = ty*8 + i;
        float gm = gqs[t];
        #pragma unroll
        for (int j = 0; j < 4; j++)
            Cb[(size_t)t*DIM + tx*4 + j] = acc[i][j] * gm;
    }
}

// ---------------- launch ------------------------------------------------------
extern "C" void kernel_launch(void* const* d_in, const int* in_sizes, int n_in,
                              void* d_out, int out_size) {
    const float* x   = (const float*)d_in[0];
    const float* Wq  = (const float*)d_in[1];
    const float* Wk  = (const float*)d_in[2];
    const float* Wv  = (const float*)d_in[3];
    const float* gqv = (const float*)d_in[4];
    const float* gkv = (const float*)d_in[5];
    const float* Wo  = (const float*)d_in[6];
    const float* bo  = (const float*)d_in[7];
    const float* lnw = (const float*)d_in[8];
    const float* lnb = (const float*)d_in[9];
    float* out = (float*)d_out;

    const int attn_smem = 4*64*68*4;
    cudaFuncSetAttribute(attn_kernel, cudaFuncAttributeMaxDynamicSharedMemorySize, attn_smem);
    cudaFuncSetAttribute(gemm_ts<0>, cudaFuncAttributeMaxDynamicSharedMemorySize, GEMM_SMEM);
    cudaFuncSetAttribute(gemm_ts<1>, cudaFuncAttributeMaxDynamicSharedMemorySize, GEMM_SMEM);

    ln_kernel<<<ROWS, 256>>>(x, lnw, lnb);
    gemm_ts<0><<<dim3(8, 32, 3), 256, GEMM_SMEM>>>(x, Wq, Wk, Wv, Wo, bo, nullptr);
    normgate_kernel<<<HROWS*32/256, 256>>>(gqv, gkv);
    attn_kernel<<<dim3(TLEN/64, HEADS, BATCH), 128, attn_smem>>>();
    gemm_ts<1><<<dim3(8, 32), 256, GEMM_SMEM>>>(nullptr, Wq, Wk, Wv, Wo, bo, out);
}

// round 7
// speedup vs baseline: 2.4974x; 1.3203x over previous
#include <cuda_runtime.h>
#include <cstdint>
#include <math.h>

#define DIM    1024
#define BATCH  2
#define TLEN   2048
#define HEADS  16
#define HD     64
#define ROWS   (BATCH*TLEN)
#define HROWS  (BATCH*HEADS*TLEN)
#define THRESH 0.29514f
#define SHARP  15.0f

__device__ float d_xnorm[ROWS*DIM];
__device__ float d_Q[HROWS*HD];
__device__ float d_K[HROWS*HD];
__device__ float d_V[HROWS*HD];
__device__ float d_gq[HROWS];
__device__ float d_coll[ROWS*DIM];

// ---------------- mma.sync m16n8k8 tf32 ----------------
__device__ __forceinline__ void mma_tf32(float* c, const uint32_t* a, const uint32_t* b) {
    asm volatile(
        "mma.sync.aligned.m16n8k8.row.col.f32.tf32.tf32.f32 "
        "{%0,%1,%2,%3}, {%4,%5,%6,%7}, {%8,%9}, {%0,%1,%2,%3};"
        : "+f"(c[0]), "+f"(c[1]), "+f"(c[2]), "+f"(c[3])
        : "r"(a[0]), "r"(a[1]), "r"(a[2]), "r"(a[3]), "r"(b[0]), "r"(b[1]));
}
__device__ __forceinline__ float hi_part(float v) {
    return __int_as_float(__float_as_int(v) & 0xFFFFE000);
}

// ---------------- LayerNorm ----------------
__global__ void ln_kernel(const float* __restrict__ x,
                          const float* __restrict__ w,
                          const float* __restrict__ bvec) {
    int row = blockIdx.x, tid = threadIdx.x;
    float4 v = ((const float4*)(x + (size_t)row*DIM))[tid];
    float s  = v.x+v.y+v.z+v.w;
    float ss = v.x*v.x+v.y*v.y+v.z*v.z+v.w*v.w;
    #pragma unroll
    for (int o = 16; o > 0; o >>= 1) {
        s  += __shfl_xor_sync(~0u, s, o);
        ss += __shfl_xor_sync(~0u, ss, o);
    }
    __shared__ float rs[8], rss[8];
    int wid = tid >> 5, lane = tid & 31;
    if (lane == 0) { rs[wid] = s; rss[wid] = ss; }
    __syncthreads();
    s = 0.f; ss = 0.f;
    #pragma unroll
    for (int i = 0; i < 8; i++) { s += rs[i]; ss += rss[i]; }
    float mean = s*(1.f/DIM), var = ss*(1.f/DIM) - mean*mean;
    float rstd = rsqrtf(var + 1e-5f);
    float4 wv = ((const float4*)w)[tid], bv = ((const float4*)bvec)[tid];
    float4 o;
    o.x = (v.x-mean)*rstd*wv.x + bv.x;  o.y = (v.y-mean)*rstd*wv.y + bv.y;
    o.z = (v.z-mean)*rstd*wv.z + bv.z;  o.w = (v.w-mean)*rstd*wv.w + bv.w;
    ((float4*)(d_xnorm + (size_t)row*DIM))[tid] = o;
}

// ---------------- tf32x3 GEMM (validated R5) ----------------
#define A_STRIDE 36
#define B_STRIDE 132
#define SM_AH 0
#define SM_AL (128*A_STRIDE)
#define SM_BH (2*128*A_STRIDE)
#define SM_BL (2*128*A_STRIDE + 32*B_STRIDE)
#define GEMM_SMEM ((2*128*A_STRIDE + 2*32*B_STRIDE)*4)

template<int MODE>
__global__ __launch_bounds__(256, 1)
void gemm_ts(const float* __restrict__ x,
             const float* __restrict__ Wq, const float* __restrict__ Wk,
             const float* __restrict__ Wv, const float* __restrict__ Wo,
             const float* __restrict__ bo, float* __restrict__ outp) {
    extern __shared__ float sm[];
    int tid = threadIdx.x, lane = tid & 31;
    int warp = tid >> 5, warpM = warp >> 1, warpN = warp & 1;
    int z = (MODE == 0) ? (int)blockIdx.z : 3;
    int m0 = blockIdx.y*128, n0 = blockIdx.x*128;
    const float* A = (MODE == 0) ? ((z == 2) ? x : d_xnorm) : d_coll;
    const float* W = (MODE == 0) ? ((z == 0) ? Wq : (z == 1) ? Wk : Wv) : Wo;

    float c[2][8][4];
    #pragma unroll
    for (int mt = 0; mt < 2; mt++)
        #pragma unroll
        for (int nt = 0; nt < 8; nt++)
            #pragma unroll
            for (int i = 0; i < 4; i++) c[mt][nt][i] = 0.f;

    float4 pa[4], pb[4];
    const float* Abase = A + (size_t)m0*DIM;
    const float* Wbase = W + n0;

    #pragma unroll
    for (int j = 0; j < 4; j++) {
        int idx = tid + 256*j;
        pa[j] = *(const float4*)(Abase + (size_t)(idx >> 3)*DIM + (idx & 7)*4);
        pb[j] = *(const float4*)(Wbase + (size_t)(idx >> 5)*DIM + (idx & 31)*4);
    }

    for (int ch = 0; ch < DIM/32; ch++) {
        #pragma unroll
        for (int j = 0; j < 4; j++) {
            int idx = tid + 256*j;
            int r = idx >> 3, kq = idx & 7;
            float4 v = pa[j];
            float4 h = make_float4(hi_part(v.x), hi_part(v.y), hi_part(v.z), hi_part(v.w));
            *(float4*)&sm[SM_AH + r*A_STRIDE + kq*4] = h;
            *(float4*)&sm[SM_AL + r*A_STRIDE + kq*4] =
                make_float4(v.x-h.x, v.y-h.y, v.z-h.z, v.w-h.w);
            int br = idx >> 5, nq = idx & 31;
            v = pb[j];
            h = make_float4(hi_part(v.x), hi_part(v.y), hi_part(v.z), hi_part(v.w));
            *(float4*)&sm[SM_BH + br*B_STRIDE + nq*4] = h;
            *(float4*)&sm[SM_BL + br*B_STRIDE + nq*4] =
                make_float4(v.x-h.x, v.y-h.y, v.z-h.z, v.w-h.w);
        }
        __syncthreads();

        if (ch + 1 < DIM/32) {
            int k0n = (ch + 1)*32;
            #pragma unroll
            for (int j = 0; j < 4; j++) {
                int idx = tid + 256*j;
                pa[j] = *(const float4*)(Abase + (size_t)(idx >> 3)*DIM + k0n + (idx & 7)*4);
                pb[j] = *(const float4*)(Wbase + (size_t)((idx >> 5) + k0n)*DIM + (idx & 31)*4);
            }
        }

        #pragma unroll
        for (int k8 = 0; k8 < 4; k8++) {
            uint32_t ah[2][4], al[2][4];
            #pragma unroll
            for (int mt = 0; mt < 2; mt++) {
                int rA = warpM*32 + mt*16 + (lane >> 2);
                int cA = k8*8 + (lane & 3);
                ah[mt][0] = __float_as_uint(sm[SM_AH + rA*A_STRIDE + cA]);
                ah[mt][1] = __float_as_uint(sm[SM_AH + (rA+8)*A_STRIDE + cA]);
                ah[mt][2] = __float_as_uint(sm[SM_AH + rA*A_STRIDE + cA + 4]);
                ah[mt][3] = __float_as_uint(sm[SM_AH + (rA+8)*A_STRIDE + cA + 4]);
                al[mt][0] = __float_as_uint(sm[SM_AL + rA*A_STRIDE + cA]);
                al[mt][1] = __float_as_uint(sm[SM_AL + (rA+8)*A_STRIDE + cA]);
                al[mt][2] = __float_as_uint(sm[SM_AL + rA*A_STRIDE + cA + 4]);
                al[mt][3] = __float_as_uint(sm[SM_AL + (rA+8)*A_STRIDE + cA + 4]);
            }
            #pragma unroll
            for (int nt = 0; nt < 8; nt++) {
                int cB = warpN*64 + nt*8 + (lane >> 2);
                int rB = k8*8 + (lane & 3);
                uint32_t bh[2], bl[2];
                bh[0] = __float_as_uint(sm[SM_BH + rB*B_STRIDE + cB]);
                bh[1] = __float_as_uint(sm[SM_BH + (rB+4)*B_STRIDE + cB]);
                bl[0] = __float_as_uint(sm[SM_BL + rB*B_STRIDE + cB]);
                bl[1] = __float_as_uint(sm[SM_BL + (rB+4)*B_STRIDE + cB]);
                #pragma unroll
                for (int mt = 0; mt < 2; mt++) {
                    mma_tf32(c[mt][nt], ah[mt], bh);
                    mma_tf32(c[mt][nt], ah[mt], bl);
                    mma_tf32(c[mt][nt], al[mt], bh);
                }
            }
        }
        __syncthreads();
    }

    #pragma unroll
    for (int mt = 0; mt < 2; mt++) {
        #pragma unroll
        for (int nt = 0; nt < 8; nt++) {
            int row = m0 + warpM*32 + mt*16 + (lane >> 2);
            int col = n0 + warpN*64 + nt*8 + (lane & 3)*2;
            #pragma unroll
            for (int half = 0; half < 2; half++) {
                int r = row + half*8;
                float2 v = make_float2(c[mt][nt][half*2], c[mt][nt][half*2+1]);
                if (MODE == 0) {
                    float* dst = (z == 0) ? d_Q : (z == 1) ? d_K : d_V;
                    int b = r >> 11, t = r & 2047;
                    int h = col >> 6, dd = col & 63;
                    *(float2*)&dst[(((size_t)(b*HEADS + h))*TLEN + t)*HD + dd] = v;
                } else {
                    v.x += bo[col]; v.y += bo[col+1];
                    *(float2*)&outp[(size_t)r*DIM + col] = v;
                }
            }
        }
    }
}

// ---------------- L2 normalize + gates ----------------
__global__ void normgate_kernel(const float* __restrict__ gqv,
                                const float* __restrict__ gkv) {
    int r = (blockIdx.x*blockDim.x + threadIdx.x) >> 5;
    int lane = threadIdx.x & 31;
    if (r >= HROWS) return;
    float* q = d_Q + (size_t)r*HD;
    float* k = d_K + (size_t)r*HD;
    float* v = d_V + (size_t)r*HD;

    float q0 = q[lane], q1 = q[lane+32];
    float ss = q0*q0 + q1*q1;
    #pragma unroll
    for (int o = 16; o > 0; o >>= 1) ss += __shfl_xor_sync(~0u, ss, o);
    float inv = 1.0f / fmaxf(sqrtf(ss), 1e-12f);
    q0 *= inv; q1 *= inv;
    q[lane] = q0; q[lane+32] = q1;
    float g = q0*gqv[lane] + q1*gqv[lane+32];
    #pragma unroll
    for (int o = 16; o > 0; o >>= 1) g += __shfl_xor_sync(~0u, g, o);
    if (lane == 0) d_gq[r] = g;

    float k0 = k[lane], k1 = k[lane+32];
    ss = k0*k0 + k1*k1;
    #pragma unroll
    for (int o = 16; o > 0; o >>= 1) ss += __shfl_xor_sync(~0u, ss, o);
    inv = 1.0f / fmaxf(sqrtf(ss), 1e-12f);
    k0 *= inv; k1 *= inv;
    k[lane] = k0; k[lane+32] = k1;
    float gk = k0*gkv[lane] + k1*gkv[lane+32];
    #pragma unroll
    for (int o = 16; o > 0; o >>= 1) gk += __shfl_xor_sync(~0u, gk, o);
    v[lane]    *= gk;
    v[lane+32] *= gk;
}

// ---------------- tensor-core attention: 128t x 64s, tf32x3 -------------------
// smem (floats): Qs[128][68] | Ks[64][68] ([d][s]) | Vs[64][68] ([s][d]) | Ps[128][68]
#define AQ 0
#define AK (128*68)
#define AV (128*68 + 64*68)
#define AP (128*68 + 2*64*68)
#define ATT_SMEM ((2*128*68 + 2*64*68)*4)

__global__ __launch_bounds__(256)
void attn_tc() {
    extern __shared__ float sm[];
    __shared__ float gqs[128];
    int tid = threadIdx.x, lane = tid & 31;
    int warp = tid >> 5, warpM = warp >> 1, warpN = warp & 1;
    int h = blockIdx.y, b = blockIdx.z;
    int t0 = blockIdx.x * 128;
    size_t base = (size_t)(b*HEADS + h)*TLEN;
    const float* Qg = d_Q + (base + t0)*HD;
    const float* Kb = d_K + base*HD;
    const float* Vb = d_V + base*HD;

    #pragma unroll
    for (int j = 0; j < 8; j++) {
        int e = tid + 256*j;                  // 2048 float4 = Q 128x64
        int t = e >> 4, d4 = (e & 15)*4;
        *(float4*)&sm[AQ + t*68 + d4] = *(const float4*)(Qg + (size_t)t*HD + d4);
    }
    if (tid < 128) gqs[tid] = d_gq[base + t0 + tid];

    float acc[2][4][4];
    #pragma unroll
    for (int mt = 0; mt < 2; mt++)
        #pragma unroll
        for (int nt = 0; nt < 4; nt++)
            #pragma unroll
            for (int i = 0; i < 4; i++) acc[mt][nt][i] = 0.f;

    for (int s0 = 0; s0 < TLEN; s0 += 64) {
        __syncthreads();
        #pragma unroll
        for (int j = 0; j < 4; j++) {
            int e = tid + 256*j;              // 1024 float4 = 64x64 tile
            int s = e >> 4, d4 = (e & 15)*4;
            float4 kv = *(const float4*)(Kb + (size_t)(s0 + s)*HD + d4);
            sm[AK + (d4+0)*68 + s] = kv.x;
            sm[AK + (d4+1)*68 + s] = kv.y;
            sm[AK + (d4+2)*68 + s] = kv.z;
            sm[AK + (d4+3)*68 + s] = kv.w;
            *(float4*)&sm[AV + s*68 + d4] = *(const float4*)(Vb + (size_t)(s0 + s)*HD + d4);
        }
        __syncthreads();

        // QK^T: M=128(t) N=64(s) K=64(d)
        float c[2][4][4];
        #pragma unroll
        for (int mt = 0; mt < 2; mt++)
            #pragma unroll
            for (int nt = 0; nt < 4; nt++)
                #pragma unroll
                for (int i = 0; i < 4; i++) c[mt][nt][i] = 0.f;

        #pragma unroll
        for (int k8 = 0; k8 < 8; k8++) {
            uint32_t ah[2][4], al[2][4];
            #pragma unroll
            for (int mt = 0; mt < 2; mt++) {
                int rA = warpM*32 + mt*16 + (lane >> 2);
                int cA = k8*8 + (lane & 3);
                float v0 = sm[AQ + rA*68 + cA];
                float v1 = sm[AQ + (rA+8)*68 + cA];
                float v2 = sm[AQ + rA*68 + cA + 4];
                float v3 = sm[AQ + (rA+8)*68 + cA + 4];
                float h0 = hi_part(v0), h1 = hi_part(v1), h2 = hi_part(v2), h3 = hi_part(v3);
                ah[mt][0] = __float_as_uint(h0); al[mt][0] = __float_as_uint(v0 - h0);
                ah[mt][1] = __float_as_uint(h1); al[mt][1] = __float_as_uint(v1 - h1);
                ah[mt][2] = __float_as_uint(h2); al[mt][2] = __float_as_uint(v2 - h2);
                ah[mt][3] = __float_as_uint(h3); al[mt][3] = __float_as_uint(v3 - h3);
            }
            #pragma unroll
            for (int nt = 0; nt < 4; nt++) {
                int cB = warpN*32 + nt*8 + (lane >> 2);
                int rB = k8*8 + (lane & 3);
                float b0 = sm[AK + rB*68 + cB];
                float b1 = sm[AK + (rB+4)*68 + cB];
                float h0 = hi_part(b0), h1 = hi_part(b1);
                uint32_t bh[2] = { __float_as_uint(h0), __float_as_uint(h1) };
                uint32_t bl[2] = { __float_as_uint(b0 - h0), __float_as_uint(b1 - h1) };
                #pragma unroll
                for (int mt = 0; mt < 2; mt++) {
                    mma_tf32(c[mt][nt], ah[mt], bh);
                    mma_tf32(c[mt][nt], ah[mt], bl);
                    mma_tf32(c[mt][nt], al[mt], bh);
                }
            }
        }

        // sigmoid -> Ps[t][s]
        #pragma unroll
        for (int mt = 0; mt < 2; mt++)
            #pragma unroll
            for (int nt = 0; nt < 4; nt++)
                #pragma unroll
                for (int half = 0; half < 2; half++) {
                    int row = warpM*32 + mt*16 + (lane >> 2) + half*8;
                    int col = warpN*32 + nt*8 + (lane & 3)*2;
                    float z0 = (c[mt][nt][half*2]   - THRESH) * SHARP;
                    float z1 = (c[mt][nt][half*2+1] - THRESH) * SHARP;
                    float p0 = __fdividef(1.0f, 1.0f + __expf(-z0));
                    float p1 = __fdividef(1.0f, 1.0f + __expf(-z1));
                    *(float2*)&sm[AP + row*68 + col] = make_float2(p0, p1);
                }
        __syncthreads();

        // P @ V: M=128(t) N=64(d) K=64(s)
        #pragma unroll
        for (int k8 = 0; k8 < 8; k8++) {
            uint32_t ah[2][4], al[2][4];
            #pragma unroll
            for (int mt = 0; mt < 2; mt++) {
                int rA = warpM*32 + mt*16 + (lane >> 2);
                int cA = k8*8 + (lane & 3);
                float v0 = sm[AP + rA*68 + cA];
                float v1 = sm[AP + (rA+8)*68 + cA];
                float v2 = sm[AP + rA*68 + cA + 4];
                float v3 = sm[AP + (rA+8)*68 + cA + 4];
                float h0 = hi_part(v0), h1 = hi_part(v1), h2 = hi_part(v2), h3 = hi_part(v3);
                ah[mt][0] = __float_as_uint(h0); al[mt][0] = __float_as_uint(v0 - h0);
                ah[mt][1] = __float_as_uint(h1); al[mt][1] = __float_as_uint(v1 - h1);
                ah[mt][2] = __float_as_uint(h2); al[mt][2] = __float_as_uint(v2 - h2);
                ah[mt][3] = __float_as_uint(h3); al[mt][3] = __float_as_uint(v3 - h3);
            }
            #pragma unroll
            for (int nt = 0; nt < 4; nt++) {
                int cB = warpN*32 + nt*8 + (lane >> 2);
                int rB = k8*8 + (lane & 3);
                float b0 = sm[AV + rB*68 + cB];
                float b1 = sm[AV + (rB+4)*68 + cB];
                float h0 = hi_part(b0), h1 = hi_part(b1);
                uint32_t bh[2] = { __float_as_uint(h0), __float_as_uint(h1) };
                uint32_t bl[2] = { __float_as_uint(b0 - h0), __float_as_uint(b1 - h1) };
                #pragma unroll
                for (int mt = 0; mt < 2; mt++) {
                    mma_tf32(acc[mt][nt], ah[mt], bh);
                    mma_tf32(acc[mt][nt], ah[mt], bl);
                    mma_tf32(acc[mt][nt], al[mt], bh);
                }
            }
        }
    }

    // epilogue: * gq, write to d_coll[b][t][h*64+d]
    float* Cb = d_coll + ((size_t)(b*TLEN) + t0)*DIM + h*HD;
    #pragma unroll
    for (int mt = 0; mt < 2; mt++)
        #pragma unroll
        for (int nt = 0; nt < 4; nt++)
            #pragma unroll
            for (int half = 0; half < 2; half++) {
                int row = warpM*32 + mt*16 + (lane >> 2) + half*8;
                int col = warpN*32 + nt*8 + (lane & 3)*2;
                float g = gqs[row];
                float2 v = make_float2(acc[mt][nt][half*2]*g, acc[mt][nt][half*2+1]*g);
                *(float2*)&Cb[(size_t)row*DIM + col] = v;
            }
}

// ---------------- launch ------------------------------------------------------
extern "C" void kernel_launch(void* const* d_in, const int* in_sizes, int n_in,
                              void* d_out, int out_size) {
    const float* x   = (const float*)d_in[0];
    const float* Wq  = (const float*)d_in[1];
    const float* Wk  = (const float*)d_in[2];
    const float* Wv  = (const float*)d_in[3];
    const float* gqv = (const float*)d_in[4];
    const float* gkv = (const float*)d_in[5];
    const float* Wo  = (const float*)d_in[6];
    const float* bo  = (const float*)d_in[7];
    const float* lnw = (const float*)d_in[8];
    const float* lnb = (const float*)d_in[9];
    float* out = (float*)d_out;

    cudaFuncSetAttribute(attn_tc, cudaFuncAttributeMaxDynamicSharedMemorySize, ATT_SMEM);
    cudaFuncSetAttribute(gemm_ts<0>, cudaFuncAttributeMaxDynamicSharedMemorySize, GEMM_SMEM);
    cudaFuncSetAttribute(gemm_ts<1>, cudaFuncAttributeMaxDynamicSharedMemorySize, GEMM_SMEM);

    ln_kernel<<<ROWS, 256>>>(x, lnw, lnb);
    gemm_ts<0><<<dim3(8, 32, 3), 256, GEMM_SMEM>>>(x, Wq, Wk, Wv, Wo, bo, nullptr);
    normgate_kernel<<<HROWS*32/256, 256>>>(gqv, gkv);
    attn_tc<<<dim3(TLEN/128, HEADS, BATCH), 256, ATT_SMEM>>>();
    gemm_ts<1><<<dim3(8, 32), 256, GEMM_SMEM>>>(nullptr, Wq, Wk, Wv, Wo, bo, out);
}

// round 8
// speedup vs baseline: 3.1118x; 1.2460x over previous
#include <cuda_runtime.h>
#include <cuda_bf16.h>
#include <cstdint>
#include <math.h>

#define DIM    1024
#define BATCH  2
#define TLEN   2048
#define HEADS  16
#define HD     64
#define ROWS   (BATCH*TLEN)
#define HROWS  (BATCH*HEADS*TLEN)
#define THRESH 0.29514f
#define SHARP  15.0f

__device__ float d_xnorm[ROWS*DIM];
__device__ float d_Q[HROWS*HD];
__device__ float d_K[HROWS*HD];
__device__ float d_V[HROWS*HD];
__device__ float d_gq[HROWS];
__device__ float d_coll[ROWS*DIM];
// bf16 hi/lo split operands for attention (layouts are MMA-native)
__device__ __align__(16) __nv_bfloat16 d_Qh[HROWS*HD];   // [b,h,t][d]
__device__ __align__(16) __nv_bfloat16 d_Ql[HROWS*HD];
__device__ __align__(16) __nv_bfloat16 d_Kh[HROWS*HD];   // [b,h,s][d]
__device__ __align__(16) __nv_bfloat16 d_Kl[HROWS*HD];
__device__ __align__(16) __nv_bfloat16 d_Vth[HROWS*HD];  // transposed: [b,h][d][s]
__device__ __align__(16) __nv_bfloat16 d_Vtl[HROWS*HD];

// ---------------- mma.sync ----------------
__device__ __forceinline__ void mma_tf32(float* c, const uint32_t* a, const uint32_t* b) {
    asm volatile(
        "mma.sync.aligned.m16n8k8.row.col.f32.tf32.tf32.f32 "
        "{%0,%1,%2,%3}, {%4,%5,%6,%7}, {%8,%9}, {%0,%1,%2,%3};"
        : "+f"(c[0]), "+f"(c[1]), "+f"(c[2]), "+f"(c[3])
        : "r"(a[0]), "r"(a[1]), "r"(a[2]), "r"(a[3]), "r"(b[0]), "r"(b[1]));
}
__device__ __forceinline__ void mma_bf16(float* c, const uint32_t* a, const uint32_t* b) {
    asm volatile(
        "mma.sync.aligned.m16n8k16.row.col.f32.bf16.bf16.f32 "
        "{%0,%1,%2,%3}, {%4,%5,%6,%7}, {%8,%9}, {%0,%1,%2,%3};"
        : "+f"(c[0]), "+f"(c[1]), "+f"(c[2]), "+f"(c[3])
        : "r"(a[0]), "r"(a[1]), "r"(a[2]), "r"(a[3]), "r"(b[0]), "r"(b[1]));
}
__device__ __forceinline__ float hi_part(float v) {
    return __int_as_float(__float_as_int(v) & 0xFFFFE000);
}

// ---------------- LayerNorm ----------------
__global__ void ln_kernel(const float* __restrict__ x,
                          const float* __restrict__ w,
                          const float* __restrict__ bvec) {
    int row = blockIdx.x, tid = threadIdx.x;
    float4 v = ((const float4*)(x + (size_t)row*DIM))[tid];
    float s  = v.x+v.y+v.z+v.w;
    float ss = v.x*v.x+v.y*v.y+v.z*v.z+v.w*v.w;
    #pragma unroll
    for (int o = 16; o > 0; o >>= 1) {
        s  += __shfl_xor_sync(~0u, s, o);
        ss += __shfl_xor_sync(~0u, ss, o);
    }
    __shared__ float rs[8], rss[8];
    int wid = tid >> 5, lane = tid & 31;
    if (lane == 0) { rs[wid] = s; rss[wid] = ss; }
    __syncthreads();
    s = 0.f; ss = 0.f;
    #pragma unroll
    for (int i = 0; i < 8; i++) { s += rs[i]; ss += rss[i]; }
    float mean = s*(1.f/DIM), var = ss*(1.f/DIM) - mean*mean;
    float rstd = rsqrtf(var + 1e-5f);
    float4 wv = ((const float4*)w)[tid], bv = ((const float4*)bvec)[tid];
    float4 o;
    o.x = (v.x-mean)*rstd*wv.x + bv.x;  o.y = (v.y-mean)*rstd*wv.y + bv.y;
    o.z = (v.z-mean)*rstd*wv.z + bv.z;  o.w = (v.w-mean)*rstd*wv.w + bv.w;
    ((float4*)(d_xnorm + (size_t)row*DIM))[tid] = o;
}

// ---------------- tf32x3 GEMM (validated R5/R6) ----------------
#define A_STRIDE 36
#define B_STRIDE 132
#define SM_AH 0
#define SM_AL (128*A_STRIDE)
#define SM_BH (2*128*A_STRIDE)
#define SM_BL (2*128*A_STRIDE + 32*B_STRIDE)
#define GEMM_SMEM ((2*128*A_STRIDE + 2*32*B_STRIDE)*4)

template<int MODE>
__global__ __launch_bounds__(256, 1)
void gemm_ts(const float* __restrict__ x,
             const float* __restrict__ Wq, const float* __restrict__ Wk,
             const float* __restrict__ Wv, const float* __restrict__ Wo,
             const float* __restrict__ bo, float* __restrict__ outp) {
    extern __shared__ float sm[];
    int tid = threadIdx.x, lane = tid & 31;
    int warp = tid >> 5, warpM = warp >> 1, warpN = warp & 1;
    int z = (MODE == 0) ? (int)blockIdx.z : 3;
    int m0 = blockIdx.y*128, n0 = blockIdx.x*128;
    const float* A = (MODE == 0) ? ((z == 2) ? x : d_xnorm) : d_coll;
    const float* W = (MODE == 0) ? ((z == 0) ? Wq : (z == 1) ? Wk : Wv) : Wo;

    float c[2][8][4];
    #pragma unroll
    for (int mt = 0; mt < 2; mt++)
        #pragma unroll
        for (int nt = 0; nt < 8; nt++)
            #pragma unroll
            for (int i = 0; i < 4; i++) c[mt][nt][i] = 0.f;

    float4 pa[4], pb[4];
    const float* Abase = A + (size_t)m0*DIM;
    const float* Wbase = W + n0;

    #pragma unroll
    for (int j = 0; j < 4; j++) {
        int idx = tid + 256*j;
        pa[j] = *(const float4*)(Abase + (size_t)(idx >> 3)*DIM + (idx & 7)*4);
        pb[j] = *(const float4*)(Wbase + (size_t)(idx >> 5)*DIM + (idx & 31)*4);
    }

    for (int ch = 0; ch < DIM/32; ch++) {
        #pragma unroll
        for (int j = 0; j < 4; j++) {
            int idx = tid + 256*j;
            int r = idx >> 3, kq = idx & 7;
            float4 v = pa[j];
            float4 h = make_float4(hi_part(v.x), hi_part(v.y), hi_part(v.z), hi_part(v.w));
            *(float4*)&sm[SM_AH + r*A_STRIDE + kq*4] = h;
            *(float4*)&sm[SM_AL + r*A_STRIDE + kq*4] =
                make_float4(v.x-h.x, v.y-h.y, v.z-h.z, v.w-h.w);
            int br = idx >> 5, nq = idx & 31;
            v = pb[j];
            h = make_float4(hi_part(v.x), hi_part(v.y), hi_part(v.z), hi_part(v.w));
            *(float4*)&sm[SM_BH + br*B_STRIDE + nq*4] = h;
            *(float4*)&sm[SM_BL + br*B_STRIDE + nq*4] =
                make_float4(v.x-h.x, v.y-h.y, v.z-h.z, v.w-h.w);
        }
        __syncthreads();

        if (ch + 1 < DIM/32) {
            int k0n = (ch + 1)*32;
            #pragma unroll
            for (int j = 0; j < 4; j++) {
                int idx = tid + 256*j;
                pa[j] = *(const float4*)(Abase + (size_t)(idx >> 3)*DIM + k0n + (idx & 7)*4);
                pb[j] = *(const float4*)(Wbase + (size_t)((idx >> 5) + k0n)*DIM + (idx & 31)*4);
            }
        }

        #pragma unroll
        for (int k8 = 0; k8 < 4; k8++) {
            uint32_t ah[2][4], al[2][4];
            #pragma unroll
            for (int mt = 0; mt < 2; mt++) {
                int rA = warpM*32 + mt*16 + (lane >> 2);
                int cA = k8*8 + (lane & 3);
                ah[mt][0] = __float_as_uint(sm[SM_AH + rA*A_STRIDE + cA]);
                ah[mt][1] = __float_as_uint(sm[SM_AH + (rA+8)*A_STRIDE + cA]);
                ah[mt][2] = __float_as_uint(sm[SM_AH + rA*A_STRIDE + cA + 4]);
                ah[mt][3] = __float_as_uint(sm[SM_AH + (rA+8)*A_STRIDE + cA + 4]);
                al[mt][0] = __float_as_uint(sm[SM_AL + rA*A_STRIDE + cA]);
                al[mt][1] = __float_as_uint(sm[SM_AL + (rA+8)*A_STRIDE + cA]);
                al[mt][2] = __float_as_uint(sm[SM_AL + rA*A_STRIDE + cA + 4]);
                al[mt][3] = __float_as_uint(sm[SM_AL + (rA+8)*A_STRIDE + cA + 4]);
            }
            #pragma unroll
            for (int nt = 0; nt < 8; nt++) {
                int cB = warpN*64 + nt*8 + (lane >> 2);
                int rB = k8*8 + (lane & 3);
                uint32_t bh[2], bl[2];
                bh[0] = __float_as_uint(sm[SM_BH + rB*B_STRIDE + cB]);
                bh[1] = __float_as_uint(sm[SM_BH + (rB+4)*B_STRIDE + cB]);
                bl[0] = __float_as_uint(sm[SM_BL + rB*B_STRIDE + cB]);
                bl[1] = __float_as_uint(sm[SM_BL + (rB+4)*B_STRIDE + cB]);
                #pragma unroll
                for (int mt = 0; mt < 2; mt++) {
                    mma_tf32(c[mt][nt], ah[mt], bh);
                    mma_tf32(c[mt][nt], ah[mt], bl);
                    mma_tf32(c[mt][nt], al[mt], bh);
                }
            }
        }
        __syncthreads();
    }

    #pragma unroll
    for (int mt = 0; mt < 2; mt++) {
        #pragma unroll
        for (int nt = 0; nt < 8; nt++) {
            int row = m0 + warpM*32 + mt*16 + (lane >> 2);
            int col = n0 + warpN*64 + nt*8 + (lane & 3)*2;
            #pragma unroll
            for (int half = 0; half < 2; half++) {
                int r = row + half*8;
                float2 v = make_float2(c[mt][nt][half*2], c[mt][nt][half*2+1]);
                if (MODE == 0) {
                    float* dst = (z == 0) ? d_Q : (z == 1) ? d_K : d_V;
                    int b = r >> 11, t = r & 2047;
                    int h = col >> 6, dd = col & 63;
                    *(float2*)&dst[(((size_t)(b*HEADS + h))*TLEN + t)*HD + dd] = v;
                } else {
                    v.x += bo[col]; v.y += bo[col+1];
                    *(float2*)&outp[(size_t)r*DIM + col] = v;
                }
            }
        }
    }
}

// ------- L2 normalize + gates + bf16 hi/lo split into MMA-native layouts -----
__device__ __forceinline__ void bf_split(float v, __nv_bfloat16& h, __nv_bfloat16& l) {
    h = __float2bfloat16_rn(v);
    l = __float2bfloat16_rn(v - __bfloat162float(h));
}
__global__ void normgate_kernel(const float* __restrict__ gqv,
                                const float* __restrict__ gkv) {
    int r = (blockIdx.x*blockDim.x + threadIdx.x) >> 5;
    int lane = threadIdx.x & 31;
    if (r >= HROWS) return;
    const float* q = d_Q + (size_t)r*HD;
    const float* k = d_K + (size_t)r*HD;
    const float* v = d_V + (size_t)r*HD;

    float q0 = q[lane], q1 = q[lane+32];
    float ss = q0*q0 + q1*q1;
    #pragma unroll
    for (int o = 16; o > 0; o >>= 1) ss += __shfl_xor_sync(~0u, ss, o);
    float inv = 1.0f / fmaxf(sqrtf(ss), 1e-12f);
    q0 *= inv; q1 *= inv;
    __nv_bfloat16 h0, l0, h1, l1;
    bf_split(q0, h0, l0); bf_split(q1, h1, l1);
    d_Qh[(size_t)r*HD + lane] = h0;       d_Ql[(size_t)r*HD + lane] = l0;
    d_Qh[(size_t)r*HD + lane + 32] = h1;  d_Ql[(size_t)r*HD + lane + 32] = l1;
    float g = q0*gqv[lane] + q1*gqv[lane+32];
    #pragma unroll
    for (int o = 16; o > 0; o >>= 1) g += __shfl_xor_sync(~0u, g, o);
    if (lane == 0) d_gq[r] = g;

    float k0 = k[lane], k1 = k[lane+32];
    ss = k0*k0 + k1*k1;
    #pragma unroll
    for (int o = 16; o > 0; o >>= 1) ss += __shfl_xor_sync(~0u, ss, o);
    inv = 1.0f / fmaxf(sqrtf(ss), 1e-12f);
    k0 *= inv; k1 *= inv;
    bf_split(k0, h0, l0); bf_split(k1, h1, l1);
    d_Kh[(size_t)r*HD + lane] = h0;       d_Kl[(size_t)r*HD + lane] = l0;
    d_Kh[(size_t)r*HD + lane + 32] = h1;  d_Kl[(size_t)r*HD + lane + 32] = l1;
    float gk = k0*gkv[lane] + k1*gkv[lane+32];
    #pragma unroll
    for (int o = 16; o > 0; o >>= 1) gk += __shfl_xor_sync(~0u, gk, o);

    // V: fold gk, split, store TRANSPOSED [head][d][s]
    int head = r >> 11, sl = r & 2047;
    size_t vbase = (size_t)head*HD*TLEN;
    float v0 = v[lane]*gk, v1 = v[lane+32]*gk;
    bf_split(v0, h0, l0); bf_split(v1, h1, l1);
    d_Vth[vbase + (size_t)lane*TLEN + sl] = h0;
    d_Vtl[vbase + (size_t)lane*TLEN + sl] = l0;
    d_Vth[vbase + (size_t)(lane+32)*TLEN + sl] = h1;
    d_Vtl[vbase + (size_t)(lane+32)*TLEN + sl] = l1;
}

// ---------------- bf16x3 tensor-core attention: 128t x 64s --------------------
// smem uint32 words, stride 36 (32 data words = 64 bf16 + pad)
#define ST 36
#define WQH 0
#define WQL (128*ST)
#define WKH (2*128*ST)
#define WKL (2*128*ST + 64*ST)
#define WVH (2*128*ST + 2*64*ST)
#define WVL (2*128*ST + 3*64*ST)
#define WPH (2*128*ST + 4*64*ST)
#define WPL (3*128*ST + 4*64*ST)
#define ATT_SMEM ((4*128*ST + 4*64*ST)*4)

__global__ __launch_bounds__(256)
void attn_tc() {
    extern __shared__ uint32_t smw[];
    __shared__ float gqs[128];
    int tid = threadIdx.x, lane = tid & 31;
    int warp = tid >> 5, warpM = warp >> 1, warpN = warp & 1;
    int h = blockIdx.y, b = blockIdx.z;
    int t0 = blockIdx.x * 128;
    int head = b*HEADS + h;
    size_t base = (size_t)head*TLEN;

    // stage Q (hi/lo): 128 rows x 8 uint4 each
    {
        const uint4* qh = (const uint4*)(d_Qh + (base + t0)*HD);
        const uint4* ql = (const uint4*)(d_Ql + (base + t0)*HD);
        #pragma unroll
        for (int j = 0; j < 4; j++) {
            int e = tid + 256*j;
            int t = e >> 3, q4 = (e & 7)*4;
            *(uint4*)&smw[WQH + t*ST + q4] = qh[e];
            *(uint4*)&smw[WQL + t*ST + q4] = ql[e];
        }
    }
    if (tid < 128) gqs[tid] = d_gq[base + t0 + tid];

    float acc[2][4][4];
    #pragma unroll
    for (int mt = 0; mt < 2; mt++)
        #pragma unroll
        for (int nt = 0; nt < 4; nt++)
            #pragma unroll
            for (int i = 0; i < 4; i++) acc[mt][nt][i] = 0.f;

    for (int s0 = 0; s0 < TLEN; s0 += 64) {
        __syncthreads();
        // stage K [s][d] (natural) and V [d][s] (pre-transposed): 64 rows x 8 uint4
        {
            const uint4* kh = (const uint4*)(d_Kh + (base + s0)*HD);
            const uint4* kl = (const uint4*)(d_Kl + (base + s0)*HD);
            const uint4* vh = (const uint4*)(d_Vth + (size_t)head*HD*TLEN + s0);
            const uint4* vl = (const uint4*)(d_Vtl + (size_t)head*HD*TLEN + s0);
            #pragma unroll
            for (int j = 0; j < 2; j++) {
                int e = tid + 256*j;
                int rr = e >> 3, q4 = (e & 7)*4;
                *(uint4*)&smw[WKH + rr*ST + q4] = kh[e];
                *(uint4*)&smw[WKL + rr*ST + q4] = kl[e];
                // V row d=rr: global row stride TLEN bf16 = TLEN/8 uint4
                *(uint4*)&smw[WVH + rr*ST + q4] = vh[(size_t)rr*(TLEN/8) + (e & 7)];
                *(uint4*)&smw[WVL + rr*ST + q4] = vl[(size_t)rr*(TLEN/8) + (e & 7)];
            }
        }
        __syncthreads();

        // QK^T: M=128 N=64 K=64(d), 4 k16 steps
        float c[2][4][4];
        #pragma unroll
        for (int mt = 0; mt < 2; mt++)
            #pragma unroll
            for (int nt = 0; nt < 4; nt++)
                #pragma unroll
                for (int i = 0; i < 4; i++) c[mt][nt][i] = 0.f;

        #pragma unroll
        for (int k16 = 0; k16 < 4; k16++) {
            int cw = k16*8 + (lane & 3);
            uint32_t ah[2][4], al[2][4];
            #pragma unroll
            for (int mt = 0; mt < 2; mt++) {
                int rA = warpM*32 + mt*16 + (lane >> 2);
                ah[mt][0] = smw[WQH + rA*ST + cw];
                ah[mt][1] = smw[WQH + (rA+8)*ST + cw];
                ah[mt][2] = smw[WQH + rA*ST + cw + 4];
                ah[mt][3] = smw[WQH + (rA+8)*ST + cw + 4];
                al[mt][0] = smw[WQL + rA*ST + cw];
                al[mt][1] = smw[WQL + (rA+8)*ST + cw];
                al[mt][2] = smw[WQL + rA*ST + cw + 4];
                al[mt][3] = smw[WQL + (rA+8)*ST + cw + 4];
            }
            #pragma unroll
            for (int nt = 0; nt < 4; nt++) {
                int cB = warpN*32 + nt*8 + (lane >> 2);
                uint32_t bh[2] = { smw[WKH + cB*ST + cw], smw[WKH + cB*ST + cw + 4] };
                uint32_t bl[2] = { smw[WKL + cB*ST + cw], smw[WKL + cB*ST + cw + 4] };
                #pragma unroll
                for (int mt = 0; mt < 2; mt++) {
                    mma_bf16(c[mt][nt], ah[mt], bh);
                    mma_bf16(c[mt][nt], ah[mt], bl);
                    mma_bf16(c[mt][nt], al[mt], bh);
                }
            }
        }

        // sigmoid -> P packed bf16x2 hi/lo (accumulator pairs are adjacent in s)
        #pragma unroll
        for (int mt = 0; mt < 2; mt++)
            #pragma unroll
            for (int nt = 0; nt < 4; nt++)
                #pragma unroll
                for (int half = 0; half < 2; half++) {
                    int row = warpM*32 + mt*16 + (lane >> 2) + half*8;
                    int col2 = warpN*16 + nt*4 + (lane & 3);
                    float z0 = (c[mt][nt][half*2]   - THRESH) * SHARP;
                    float z1 = (c[mt][nt][half*2+1] - THRESH) * SHARP;
                    float p0 = __fdividef(1.0f, 1.0f + __expf(-z0));
                    float p1 = __fdividef(1.0f, 1.0f + __expf(-z1));
                    __nv_bfloat162 hh = __floats2bfloat162_rn(p0, p1);
                    float r0 = p0 - __bfloat162float(hh.x);
                    float r1 = p1 - __bfloat162float(hh.y);
                    __nv_bfloat162 ll = __floats2bfloat162_rn(r0, r1);
                    smw[WPH + row*ST + col2] = *reinterpret_cast<uint32_t*>(&hh);
                    smw[WPL + row*ST + col2] = *reinterpret_cast<uint32_t*>(&ll);
                }
        __syncthreads();

        // P @ V: M=128 N=64(d) K=64(s), 4 k16 steps
        #pragma unroll
        for (int k16 = 0; k16 < 4; k16++) {
            int cw = k16*8 + (lane & 3);
            uint32_t ah[2][4], al[2][4];
            #pragma unroll
            for (int mt = 0; mt < 2; mt++) {
                int rA = warpM*32 + mt*16 + (lane >> 2);
                ah[mt][0] = smw[WPH + rA*ST + cw];
                ah[mt][1] = smw[WPH + (rA+8)*ST + cw];
                ah[mt][2] = smw[WPH + rA*ST + cw + 4];
                ah[mt][3] = smw[WPH + (rA+8)*ST + cw + 4];
                al[mt][0] = smw[WPL + rA*ST + cw];
                al[mt][1] = smw[WPL + (rA+8)*ST + cw];
                al[mt][2] = smw[WPL + rA*ST + cw + 4];
                al[mt][3] = smw[WPL + (rA+8)*ST + cw + 4];
            }
            #pragma unroll
            for (int nt = 0; nt < 4; nt++) {
                int cB = warpN*32 + nt*8 + (lane >> 2);
                uint32_t bh[2] = { smw[WVH + cB*ST + cw], smw[WVH + cB*ST + cw + 4] };
                uint32_t bl[2] = { smw[WVL + cB*ST + cw], smw[WVL + cB*ST + cw + 4] };
                #pragma unroll
                for (int mt = 0; mt < 2; mt++) {
                    mma_bf16(acc[mt][nt], ah[mt], bh);
                    mma_bf16(acc[mt][nt], ah[mt], bl);
                    mma_bf16(acc[mt][nt], al[mt], bh);
                }
            }
        }
    }

    // epilogue: * gq, write to d_coll[b][t][h*64+d]
    float* Cb = d_coll + ((size_t)(b*TLEN) + t0)*DIM + h*HD;
    #pragma unroll
    for (int mt = 0; mt < 2; mt++)
        #pragma unroll
        for (int nt = 0; nt < 4; nt++)
            #pragma unroll
            for (int half = 0; half < 2; half++) {
                int row = warpM*32 + mt*16 + (lane >> 2) + half*8;
                int col = warpN*32 + nt*8 + (lane & 3)*2;
                float g = gqs[row];
                float2 v = make_float2(acc[mt][nt][half*2]*g, acc[mt][nt][half*2+1]*g);
                *(float2*)&Cb[(size_t)row*DIM + col] = v;
            }
}

// ---------------- launch ------------------------------------------------------
extern "C" void kernel_launch(void* const* d_in, const int* in_sizes, int n_in,
                              void* d_out, int out_size) {
    const float* x   = (const float*)d_in[0];
    const float* Wq  = (const float*)d_in[1];
    const float* Wk  = (const float*)d_in[2];
    const float* Wv  = (const float*)d_in[3];
    const float* gqv = (const float*)d_in[4];
    const float* gkv = (const float*)d_in[5];
    const float* Wo  = (const float*)d_in[6];
    const float* bo  = (const float*)d_in[7];
    const float* lnw = (const float*)d_in[8];
    const float* lnb = (const float*)d_in[9];
    float* out = (float*)d_out;

    cudaFuncSetAttribute(attn_tc, cudaFuncAttributeMaxDynamicSharedMemorySize, ATT_SMEM);
    cudaFuncSetAttribute(gemm_ts<0>, cudaFuncAttributeMaxDynamicSharedMemorySize, GEMM_SMEM);
    cudaFuncSetAttribute(gemm_ts<1>, cudaFuncAttributeMaxDynamicSharedMemorySize, GEMM_SMEM);

    ln_kernel<<<ROWS, 256>>>(x, lnw, lnb);
    gemm_ts<0><<<dim3(8, 32, 3), 256, GEMM_SMEM>>>(x, Wq, Wk, Wv, Wo, bo, nullptr);
    normgate_kernel<<<HROWS*32/256, 256>>>(gqv, gkv);
    attn_tc<<<dim3(TLEN/128, HEADS, BATCH), 256, ATT_SMEM>>>();
    gemm_ts<1><<<dim3(8, 32), 256, GEMM_SMEM>>>(nullptr, Wq, Wk, Wv, Wo, bo, out);
}

// round 9
// speedup vs baseline: 3.9640x; 1.2738x over previous
#include <cuda_runtime.h>
#include <cuda_bf16.h>
#include <cstdint>
#include <math.h>

#define DIM    1024
#define BATCH  2
#define TLEN   2048
#define HEADS  16
#define HD     64
#define ROWS   (BATCH*TLEN)
#define HROWS  (BATCH*HEADS*TLEN)
#define THRESH 0.29514f
#define SHARP  15.0f

__device__ float d_xnorm[ROWS*DIM];
__device__ float d_Q[HROWS*HD];
__device__ float d_K[HROWS*HD];
__device__ float d_V[HROWS*HD];
__device__ float d_gq[HROWS];
__device__ float d_coll[ROWS*DIM];
__device__ __align__(16) __nv_bfloat16 d_Qh[HROWS*HD];
__device__ __align__(16) __nv_bfloat16 d_Ql[HROWS*HD];
__device__ __align__(16) __nv_bfloat16 d_Kh[HROWS*HD];
__device__ __align__(16) __nv_bfloat16 d_Kl[HROWS*HD];
__device__ __align__(16) __nv_bfloat16 d_Vth[HROWS*HD];  // [b,h][d][s]
__device__ __align__(16) __nv_bfloat16 d_Vtl[HROWS*HD];

// ---------------- mma.sync ----------------
__device__ __forceinline__ void mma_bf16(float* c, const uint32_t* a, const uint32_t* b) {
    asm volatile(
        "mma.sync.aligned.m16n8k16.row.col.f32.bf16.bf16.f32 "
        "{%0,%1,%2,%3}, {%4,%5,%6,%7}, {%8,%9}, {%0,%1,%2,%3};"
        : "+f"(c[0]), "+f"(c[1]), "+f"(c[2]), "+f"(c[3])
        : "r"(a[0]), "r"(a[1]), "r"(a[2]), "r"(a[3]), "r"(b[0]), "r"(b[1]));
}
__device__ __forceinline__ uint32_t bfpack2(float a, float b) {
    __nv_bfloat162 p = __floats2bfloat162_rn(a, b);   // x=a(low), y=b(high)
    return *reinterpret_cast<uint32_t*>(&p);
}
__device__ __forceinline__ float bflo(float v) {
    return v - __bfloat162float(__float2bfloat16_rn(v));
}

// ---------------- LayerNorm ----------------
__global__ void ln_kernel(const float* __restrict__ x,
                          const float* __restrict__ w,
                          const float* __restrict__ bvec) {
    int row = blockIdx.x, tid = threadIdx.x;
    float4 v = ((const float4*)(x + (size_t)row*DIM))[tid];
    float s  = v.x+v.y+v.z+v.w;
    float ss = v.x*v.x+v.y*v.y+v.z*v.z+v.w*v.w;
    #pragma unroll
    for (int o = 16; o > 0; o >>= 1) {
        s  += __shfl_xor_sync(~0u, s, o);
        ss += __shfl_xor_sync(~0u, ss, o);
    }
    __shared__ float rs[8], rss[8];
    int wid = tid >> 5, lane = tid & 31;
    if (lane == 0) { rs[wid] = s; rss[wid] = ss; }
    __syncthreads();
    s = 0.f; ss = 0.f;
    #pragma unroll
    for (int i = 0; i < 8; i++) { s += rs[i]; ss += rss[i]; }
    float mean = s*(1.f/DIM), var = ss*(1.f/DIM) - mean*mean;
    float rstd = rsqrtf(var + 1e-5f);
    float4 wv = ((const float4*)w)[tid], bv = ((const float4*)bvec)[tid];
    float4 o;
    o.x = (v.x-mean)*rstd*wv.x + bv.x;  o.y = (v.y-mean)*rstd*wv.y + bv.y;
    o.z = (v.z-mean)*rstd*wv.z + bv.z;  o.w = (v.w-mean)*rstd*wv.w + bv.w;
    ((float4*)(d_xnorm + (size_t)row*DIM))[tid] = o;
}

// ---------------- bf16x3 GEMM: 128x128 tile, K-chunk 32 ----------------------
// smem word layout: As[m=128][kpair=16] stride 20; Bs[kpair=16][n=128] stride 136
#define GA_ST 20
#define GB_ST 136
#define GAH 0
#define GAL (128*GA_ST)
#define GBH (2*128*GA_ST)
#define GBL (2*128*GA_ST + 16*GB_ST)
#define GEMM_SMEM ((2*128*GA_ST + 2*16*GB_ST)*4)

template<int MODE>   // 0: QKV (z = blockIdx.z), 1: out = coll@Wo + bo
__global__ __launch_bounds__(256, 1)
void gemm_ts(const float* __restrict__ x,
             const float* __restrict__ Wq, const float* __restrict__ Wk,
             const float* __restrict__ Wv, const float* __restrict__ Wo,
             const float* __restrict__ bo, float* __restrict__ outp) {
    extern __shared__ uint32_t smw[];
    int tid = threadIdx.x, lane = tid & 31;
    int warp = tid >> 5, warpM = warp >> 1, warpN = warp & 1;
    int z = (MODE == 0) ? (int)blockIdx.z : 3;
    int m0 = blockIdx.y*128, n0 = blockIdx.x*128;
    const float* A = (MODE == 0) ? ((z == 2) ? x : d_xnorm) : d_coll;
    const float* W = (MODE == 0) ? ((z == 0) ? Wq : (z == 1) ? Wk : Wv) : Wo;

    float c[2][8][4];
    #pragma unroll
    for (int mt = 0; mt < 2; mt++)
        #pragma unroll
        for (int nt = 0; nt < 8; nt++)
            #pragma unroll
            for (int i = 0; i < 4; i++) c[mt][nt][i] = 0.f;

    const float* Abase = A + (size_t)m0*DIM;
    const float* Wbase = W + n0;

    // prefetch regs: A 1024 f4 (4 iters), B 512 row-pairs (2 iters x 2 rows)
    float4 pa[4], pb0[2], pb1[2];
    #pragma unroll
    for (int j = 0; j < 4; j++) {
        int idx = tid + 256*j;
        pa[j] = *(const float4*)(Abase + (size_t)(idx >> 3)*DIM + (idx & 7)*4);
    }
    #pragma unroll
    for (int j = 0; j < 2; j++) {
        int idx = tid + 256*j;
        int kp = idx >> 5, nq = (idx & 31)*4;
        pb0[j] = *(const float4*)(Wbase + (size_t)(2*kp)*DIM + nq);
        pb1[j] = *(const float4*)(Wbase + (size_t)(2*kp + 1)*DIM + nq);
    }

    for (int ch = 0; ch < DIM/32; ch++) {
        // split + store to smem
        #pragma unroll
        for (int j = 0; j < 4; j++) {
            int idx = tid + 256*j;
            int r = idx >> 3, k4 = idx & 7;
            float4 v = pa[j];
            uint2 hh = make_uint2(bfpack2(v.x, v.y), bfpack2(v.z, v.w));
            uint2 ll = make_uint2(bfpack2(bflo(v.x), bflo(v.y)), bfpack2(bflo(v.z), bflo(v.w)));
            *(uint2*)&smw[GAH + r*GA_ST + k4*2] = hh;
            *(uint2*)&smw[GAL + r*GA_ST + k4*2] = ll;
        }
        #pragma unroll
        for (int j = 0; j < 2; j++) {
            int idx = tid + 256*j;
            int kp = idx >> 5, nq = (idx & 31)*4;
            float4 r0 = pb0[j], r1 = pb1[j];
            uint4 hh = make_uint4(bfpack2(r0.x, r1.x), bfpack2(r0.y, r1.y),
                                  bfpack2(r0.z, r1.z), bfpack2(r0.w, r1.w));
            uint4 ll = make_uint4(bfpack2(bflo(r0.x), bflo(r1.x)), bfpack2(bflo(r0.y), bflo(r1.y)),
                                  bfpack2(bflo(r0.z), bflo(r1.z)), bfpack2(bflo(r0.w), bflo(r1.w)));
            *(uint4*)&smw[GBH + kp*GB_ST + nq] = hh;
            *(uint4*)&smw[GBL + kp*GB_ST + nq] = ll;
        }
        __syncthreads();

        if (ch + 1 < DIM/32) {
            int k0n = (ch + 1)*32;
            #pragma unroll
            for (int j = 0; j < 4; j++) {
                int idx = tid + 256*j;
                pa[j] = *(const float4*)(Abase + (size_t)(idx >> 3)*DIM + k0n + (idx & 7)*4);
            }
            #pragma unroll
            for (int j = 0; j < 2; j++) {
                int idx = tid + 256*j;
                int kp = idx >> 5, nq = (idx & 31)*4;
                pb0[j] = *(const float4*)(Wbase + (size_t)(k0n + 2*kp)*DIM + nq);
                pb1[j] = *(const float4*)(Wbase + (size_t)(k0n + 2*kp + 1)*DIM + nq);
            }
        }

        #pragma unroll
        for (int k16 = 0; k16 < 2; k16++) {
            int cw = k16*8 + (lane & 3);
            uint32_t ah[2][4], al[2][4];
            #pragma unroll
            for (int mt = 0; mt < 2; mt++) {
                int rA = warpM*32 + mt*16 + (lane >> 2);
                ah[mt][0] = smw[GAH + rA*GA_ST + cw];
                ah[mt][1] = smw[GAH + (rA+8)*GA_ST + cw];
                ah[mt][2] = smw[GAH + rA*GA_ST + cw + 4];
                ah[mt][3] = smw[GAH + (rA+8)*GA_ST + cw + 4];
                al[mt][0] = smw[GAL + rA*GA_ST + cw];
                al[mt][1] = smw[GAL + (rA+8)*GA_ST + cw];
                al[mt][2] = smw[GAL + rA*GA_ST + cw + 4];
                al[mt][3] = smw[GAL + (rA+8)*GA_ST + cw + 4];
            }
            #pragma unroll
            for (int nt = 0; nt < 8; nt++) {
                int cB = warpN*64 + nt*8 + (lane >> 2);
                uint32_t bh[2] = { smw[GBH + cw*GB_ST + cB], smw[GBH + (cw+4)*GB_ST + cB] };
                uint32_t bl[2] = { smw[GBL + cw*GB_ST + cB], smw[GBL + (cw+4)*GB_ST + cB] };
                #pragma unroll
                for (int mt = 0; mt < 2; mt++) {
                    mma_bf16(c[mt][nt], ah[mt], bh);
                    mma_bf16(c[mt][nt], ah[mt], bl);
                    mma_bf16(c[mt][nt], al[mt], bh);
                }
            }
        }
        __syncthreads();
    }

    #pragma unroll
    for (int mt = 0; mt < 2; mt++) {
        #pragma unroll
        for (int nt = 0; nt < 8; nt++) {
            int row = m0 + warpM*32 + mt*16 + (lane >> 2);
            int col = n0 + warpN*64 + nt*8 + (lane & 3)*2;
            #pragma unroll
            for (int half = 0; half < 2; half++) {
                int r = row + half*8;
                float2 v = make_float2(c[mt][nt][half*2], c[mt][nt][half*2+1]);
                if (MODE == 0) {
                    float* dst = (z == 0) ? d_Q : (z == 1) ? d_K : d_V;
                    int b = r >> 11, t = r & 2047;
                    int h = col >> 6, dd = col & 63;
                    *(float2*)&dst[(((size_t)(b*HEADS + h))*TLEN + t)*HD + dd] = v;
                } else {
                    v.x += bo[col]; v.y += bo[col+1];
                    *(float2*)&outp[(size_t)r*DIM + col] = v;
                }
            }
        }
    }
}

// ------- L2 normalize + gates + bf16 hi/lo split (validated R7) --------------
__device__ __forceinline__ void bf_split(float v, __nv_bfloat16& h, __nv_bfloat16& l) {
    h = __float2bfloat16_rn(v);
    l = __float2bfloat16_rn(v - __bfloat162float(h));
}
__global__ void normgate_kernel(const float* __restrict__ gqv,
                                const float* __restrict__ gkv) {
    int r = (blockIdx.x*blockDim.x + threadIdx.x) >> 5;
    int lane = threadIdx.x & 31;
    if (r >= HROWS) return;
    const float* q = d_Q + (size_t)r*HD;
    const float* k = d_K + (size_t)r*HD;
    const float* v = d_V + (size_t)r*HD;

    float q0 = q[lane], q1 = q[lane+32];
    float ss = q0*q0 + q1*q1;
    #pragma unroll
    for (int o = 16; o > 0; o >>= 1) ss += __shfl_xor_sync(~0u, ss, o);
    float inv = 1.0f / fmaxf(sqrtf(ss), 1e-12f);
    q0 *= inv; q1 *= inv;
    __nv_bfloat16 h0, l0, h1, l1;
    bf_split(q0, h0, l0); bf_split(q1, h1, l1);
    d_Qh[(size_t)r*HD + lane] = h0;       d_Ql[(size_t)r*HD + lane] = l0;
    d_Qh[(size_t)r*HD + lane + 32] = h1;  d_Ql[(size_t)r*HD + lane + 32] = l1;
    float g = q0*gqv[lane] + q1*gqv[lane+32];
    #pragma unroll
    for (int o = 16; o > 0; o >>= 1) g += __shfl_xor_sync(~0u, g, o);
    if (lane == 0) d_gq[r] = g;

    float k0 = k[lane], k1 = k[lane+32];
    ss = k0*k0 + k1*k1;
    #pragma unroll
    for (int o = 16; o > 0; o >>= 1) ss += __shfl_xor_sync(~0u, ss, o);
    inv = 1.0f / fmaxf(sqrtf(ss), 1e-12f);
    k0 *= inv; k1 *= inv;
    bf_split(k0, h0, l0); bf_split(k1, h1, l1);
    d_Kh[(size_t)r*HD + lane] = h0;       d_Kl[(size_t)r*HD + lane] = l0;
    d_Kh[(size_t)r*HD + lane + 32] = h1;  d_Kl[(size_t)r*HD + lane + 32] = l1;
    float gk = k0*gkv[lane] + k1*gkv[lane+32];
    #pragma unroll
    for (int o = 16; o > 0; o >>= 1) gk += __shfl_xor_sync(~0u, gk, o);

    int head = r >> 11, sl = r & 2047;
    size_t vbase = (size_t)head*HD*TLEN;
    float v0 = v[lane]*gk, v1 = v[lane+32]*gk;
    bf_split(v0, h0, l0); bf_split(v1, h1, l1);
    d_Vth[vbase + (size_t)lane*TLEN + sl] = h0;
    d_Vtl[vbase + (size_t)lane*TLEN + sl] = l0;
    d_Vth[vbase + (size_t)(lane+32)*TLEN + sl] = h1;
    d_Vtl[vbase + (size_t)(lane+32)*TLEN + sl] = l1;
}

// ---------------- bf16x3 tensor-core attention (validated R7) -----------------
#define ST 36
#define WQH 0
#define WQL (128*ST)
#define WKH (2*128*ST)
#define WKL (2*128*ST + 64*ST)
#define WVH (2*128*ST + 2*64*ST)
#define WVL (2*128*ST + 3*64*ST)
#define WPH (2*128*ST + 4*64*ST)
#define WPL (3*128*ST + 4*64*ST)
#define ATT_SMEM ((4*128*ST + 4*64*ST)*4)

__global__ __launch_bounds__(256)
void attn_tc() {
    extern __shared__ uint32_t smw[];
    __shared__ float gqs[128];
    int tid = threadIdx.x, lane = tid & 31;
    int warp = tid >> 5, warpM = warp >> 1, warpN = warp & 1;
    int h = blockIdx.y, b = blockIdx.z;
    int t0 = blockIdx.x * 128;
    int head = b*HEADS + h;
    size_t base = (size_t)head*TLEN;

    {
        const uint4* qh = (const uint4*)(d_Qh + (base + t0)*HD);
        const uint4* ql = (const uint4*)(d_Ql + (base + t0)*HD);
        #pragma unroll
        for (int j = 0; j < 4; j++) {
            int e = tid + 256*j;
            int t = e >> 3, q4 = (e & 7)*4;
            *(uint4*)&smw[WQH + t*ST + q4] = qh[e];
            *(uint4*)&smw[WQL + t*ST + q4] = ql[e];
        }
    }
    if (tid < 128) gqs[tid] = d_gq[base + t0 + tid];

    float acc[2][4][4];
    #pragma unroll
    for (int mt = 0; mt < 2; mt++)
        #pragma unroll
        for (int nt = 0; nt < 4; nt++)
            #pragma unroll
            for (int i = 0; i < 4; i++) acc[mt][nt][i] = 0.f;

    for (int s0 = 0; s0 < TLEN; s0 += 64) {
        __syncthreads();
        {
            const uint4* kh = (const uint4*)(d_Kh + (base + s0)*HD);
            const uint4* kl = (const uint4*)(d_Kl + (base + s0)*HD);
            const uint4* vh = (const uint4*)(d_Vth + (size_t)head*HD*TLEN + s0);
            const uint4* vl = (const uint4*)(d_Vtl + (size_t)head*HD*TLEN + s0);
            #pragma unroll
            for (int j = 0; j < 2; j++) {
                int e = tid + 256*j;
                int rr = e >> 3, q4 = (e & 7)*4;
                *(uint4*)&smw[WKH + rr*ST + q4] = kh[e];
                *(uint4*)&smw[WKL + rr*ST + q4] = kl[e];
                *(uint4*)&smw[WVH + rr*ST + q4] = vh[(size_t)rr*(TLEN/8) + (e & 7)];
                *(uint4*)&smw[WVL + rr*ST + q4] = vl[(size_t)rr*(TLEN/8) + (e & 7)];
            }
        }
        __syncthreads();

        float c[2][4][4];
        #pragma unroll
        for (int mt = 0; mt < 2; mt++)
            #pragma unroll
            for (int nt = 0; nt < 4; nt++)
                #pragma unroll
                for (int i = 0; i < 4; i++) c[mt][nt][i] = 0.f;

        #pragma unroll
        for (int k16 = 0; k16 < 4; k16++) {
            int cw = k16*8 + (lane & 3);
            uint32_t ah[2][4], al[2][4];
            #pragma unroll
            for (int mt = 0; mt < 2; mt++) {
                int rA = warpM*32 + mt*16 + (lane >> 2);
                ah[mt][0] = smw[WQH + rA*ST + cw];
                ah[mt][1] = smw[WQH + (rA+8)*ST + cw];
                ah[mt][2] = smw[WQH + rA*ST + cw + 4];
                ah[mt][3] = smw[WQH + (rA+8)*ST + cw + 4];
                al[mt][0] = smw[WQL + rA*ST + cw];
                al[mt][1] = smw[WQL + (rA+8)*ST + cw];
                al[mt][2] = smw[WQL + rA*ST + cw + 4];
                al[mt][3] = smw[WQL + (rA+8)*ST + cw + 4];
            }
            #pragma unroll
            for (int nt = 0; nt < 4; nt++) {
                int cB = warpN*32 + nt*8 + (lane >> 2);
                uint32_t bh[2] = { smw[WKH + cB*ST + cw], smw[WKH + cB*ST + cw + 4] };
                uint32_t bl[2] = { smw[WKL + cB*ST + cw], smw[WKL + cB*ST + cw + 4] };
                #pragma unroll
                for (int mt = 0; mt < 2; mt++) {
                    mma_bf16(c[mt][nt], ah[mt], bh);
                    mma_bf16(c[mt][nt], ah[mt], bl);
                    mma_bf16(c[mt][nt], al[mt], bh);
                }
            }
        }

        #pragma unroll
        for (int mt = 0; mt < 2; mt++)
            #pragma unroll
            for (int nt = 0; nt < 4; nt++)
                #pragma unroll
                for (int half = 0; half < 2; half++) {
                    int row = warpM*32 + mt*16 + (lane >> 2) + half*8;
                    int col2 = warpN*16 + nt*4 + (lane & 3);
                    float z0 = (c[mt][nt][half*2]   - THRESH) * SHARP;
                    float z1 = (c[mt][nt][half*2+1] - THRESH) * SHARP;
                    float p0 = __fdividef(1.0f, 1.0f + __expf(-z0));
                    float p1 = __fdividef(1.0f, 1.0f + __expf(-z1));
                    __nv_bfloat162 hh = __floats2bfloat162_rn(p0, p1);
                    float r0 = p0 - __bfloat162float(hh.x);
                    float r1 = p1 - __bfloat162float(hh.y);
                    __nv_bfloat162 ll = __floats2bfloat162_rn(r0, r1);
                    smw[WPH + row*ST + col2] = *reinterpret_cast<uint32_t*>(&hh);
                    smw[WPL + row*ST + col2] = *reinterpret_cast<uint32_t*>(&ll);
                }
        __syncthreads();

        #pragma unroll
        for (int k16 = 0; k16 < 4; k16++) {
            int cw = k16*8 + (lane & 3);
            uint32_t ah[2][4], al[2][4];
            #pragma unroll
            for (int mt = 0; mt < 2; mt++) {
                int rA = warpM*32 + mt*16 + (lane >> 2);
                ah[mt][0] = smw[WPH + rA*ST + cw];
                ah[mt][1] = smw[WPH + (rA+8)*ST + cw];
                ah[mt][2] = smw[WPH + rA*ST + cw + 4];
                ah[mt][3] = smw[WPH + (rA+8)*ST + cw + 4];
                al[mt][0] = smw[WPL + rA*ST + cw];
                al[mt][1] = smw[WPL + (rA+8)*ST + cw];
                al[mt][2] = smw[WPL + rA*ST + cw + 4];
                al[mt][3] = smw[WPL + (rA+8)*ST + cw + 4];
            }
            #pragma unroll
            for (int nt = 0; nt < 4; nt++) {
                int cB = warpN*32 + nt*8 + (lane >> 2);
                uint32_t bh[2] = { smw[WVH + cB*ST + cw], smw[WVH + cB*ST + cw + 4] };
                uint32_t bl[2] = { smw[WVL + cB*ST + cw], smw[WVL + cB*ST + cw + 4] };
                #pragma unroll
                for (int mt = 0; mt < 2; mt++) {
                    mma_bf16(acc[mt][nt], ah[mt], bh);
                    mma_bf16(acc[mt][nt], ah[mt], bl);
                    mma_bf16(acc[mt][nt], al[mt], bh);
                }
            }
        }
    }

    float* Cb = d_coll + ((size_t)(b*TLEN) + t0)*DIM + h*HD;
    #pragma unroll
    for (int mt = 0; mt < 2; mt++)
        #pragma unroll
        for (int nt = 0; nt < 4; nt++)
            #pragma unroll
            for (int half = 0; half < 2; half++) {
                int row = warpM*32 + mt*16 + (lane >> 2) + half*8;
                int col = warpN*32 + nt*8 + (lane & 3)*2;
                float g = gqs[row];
                float2 v = make_float2(acc[mt][nt][half*2]*g, acc[mt][nt][half*2+1]*g);
                *(float2*)&Cb[(size_t)row*DIM + col] = v;
            }
}

// ---------------- launch ------------------------------------------------------
extern "C" void kernel_launch(void* const* d_in, const int* in_sizes, int n_in,
                              void* d_out, int out_size) {
    const float* x   = (const float*)d_in[0];
    const float* Wq  = (const float*)d_in[1];
    const float* Wk  = (const float*)d_in[2];
    const float* Wv  = (const float*)d_in[3];
    const float* gqv = (const float*)d_in[4];
    const float* gkv = (const float*)d_in[5];
    const float* Wo  = (const float*)d_in[6];
    const float* bo  = (const float*)d_in[7];
    const float* lnw = (const float*)d_in[8];
    const float* lnb = (const float*)d_in[9];
    float* out = (float*)d_out;

    cudaFuncSetAttribute(attn_tc, cudaFuncAttributeMaxDynamicSharedMemorySize, ATT_SMEM);
    cudaFuncSetAttribute(gemm_ts<0>, cudaFuncAttributeMaxDynamicSharedMemorySize, GEMM_SMEM);
    cudaFuncSetAttribute(gemm_ts<1>, cudaFuncAttributeMaxDynamicSharedMemorySize, GEMM_SMEM);

    ln_kernel<<<ROWS, 256>>>(x, lnw, lnb);
    gemm_ts<0><<<dim3(8, 32, 3), 256, GEMM_SMEM>>>(x, Wq, Wk, Wv, Wo, bo, nullptr);
    normgate_kernel<<<HROWS*32/256, 256>>>(gqv, gkv);
    attn_tc<<<dim3(TLEN/128, HEADS, BATCH), 256, ATT_SMEM>>>();
    gemm_ts<1><<<dim3(8, 32), 256, GEMM_SMEM>>>(nullptr, Wq, Wk, Wv, Wo, bo, out);
}

// round 10
// speedup vs baseline: 4.0794x; 1.0291x over previous
#include <cuda_runtime.h>
#include <cuda_bf16.h>
#include <cstdint>
#include <math.h>

#define DIM    1024
#define BATCH  2
#define TLEN   2048
#define HEADS  16
#define HD     64
#define ROWS   (BATCH*TLEN)
#define HROWS  (BATCH*HEADS*TLEN)
#define THRESH 0.29514f
#define SHARP  15.0f

__device__ float d_xnorm[ROWS*DIM];
__device__ float d_Q[HROWS*HD];
__device__ float d_K[HROWS*HD];
__device__ float d_V[HROWS*HD];
__device__ float d_gq[HROWS];
__device__ float d_coll[ROWS*DIM];
__device__ __align__(16) __nv_bfloat16 d_Qh[HROWS*HD];
__device__ __align__(16) __nv_bfloat16 d_Ql[HROWS*HD];
__device__ __align__(16) __nv_bfloat16 d_Kh[HROWS*HD];
__device__ __align__(16) __nv_bfloat16 d_Kl[HROWS*HD];
__device__ __align__(16) __nv_bfloat16 d_Vth[HROWS*HD];  // [b,h][d][s]
__device__ __align__(16) __nv_bfloat16 d_Vtl[HROWS*HD];

// ---------------- mma.sync ----------------
__device__ __forceinline__ void mma_bf16(float* c, const uint32_t* a, const uint32_t* b) {
    asm volatile(
        "mma.sync.aligned.m16n8k16.row.col.f32.bf16.bf16.f32 "
        "{%0,%1,%2,%3}, {%4,%5,%6,%7}, {%8,%9}, {%0,%1,%2,%3};"
        : "+f"(c[0]), "+f"(c[1]), "+f"(c[2]), "+f"(c[3])
        : "r"(a[0]), "r"(a[1]), "r"(a[2]), "r"(a[3]), "r"(b[0]), "r"(b[1]));
}
__device__ __forceinline__ uint32_t bfpack2(float a, float b) {
    __nv_bfloat162 p = __floats2bfloat162_rn(a, b);
    return *reinterpret_cast<uint32_t*>(&p);
}
__device__ __forceinline__ float bflo(float v) {
    return v - __bfloat162float(__float2bfloat16_rn(v));
}

// ---------------- LayerNorm ----------------
__global__ void ln_kernel(const float* __restrict__ x,
                          const float* __restrict__ w,
                          const float* __restrict__ bvec) {
    int row = blockIdx.x, tid = threadIdx.x;
    float4 v = ((const float4*)(x + (size_t)row*DIM))[tid];
    float s  = v.x+v.y+v.z+v.w;
    float ss = v.x*v.x+v.y*v.y+v.z*v.z+v.w*v.w;
    #pragma unroll
    for (int o = 16; o > 0; o >>= 1) {
        s  += __shfl_xor_sync(~0u, s, o);
        ss += __shfl_xor_sync(~0u, ss, o);
    }
    __shared__ float rs[8], rss[8];
    int wid = tid >> 5, lane = tid & 31;
    if (lane == 0) { rs[wid] = s; rss[wid] = ss; }
    __syncthreads();
    s = 0.f; ss = 0.f;
    #pragma unroll
    for (int i = 0; i < 8; i++) { s += rs[i]; ss += rss[i]; }
    float mean = s*(1.f/DIM), var = ss*(1.f/DIM) - mean*mean;
    float rstd = rsqrtf(var + 1e-5f);
    float4 wv = ((const float4*)w)[tid], bv = ((const float4*)bvec)[tid];
    float4 o;
    o.x = (v.x-mean)*rstd*wv.x + bv.x;  o.y = (v.y-mean)*rstd*wv.y + bv.y;
    o.z = (v.z-mean)*rstd*wv.z + bv.z;  o.w = (v.w-mean)*rstd*wv.w + bv.w;
    ((float4*)(d_xnorm + (size_t)row*DIM))[tid] = o;
}

// ---------------- bf16x3 GEMM (validated R8) ----------------
#define GA_ST 20
#define GB_ST 136
#define GAH 0
#define GAL (128*GA_ST)
#define GBH (2*128*GA_ST)
#define GBL (2*128*GA_ST + 16*GB_ST)
#define GEMM_SMEM ((2*128*GA_ST + 2*16*GB_ST)*4)

template<int MODE>
__global__ __launch_bounds__(256, 1)
void gemm_ts(const float* __restrict__ x,
             const float* __restrict__ Wq, const float* __restrict__ Wk,
             const float* __restrict__ Wv, const float* __restrict__ Wo,
             const float* __restrict__ bo, float* __restrict__ outp) {
    extern __shared__ uint32_t smw[];
    int tid = threadIdx.x, lane = tid & 31;
    int warp = tid >> 5, warpM = warp >> 1, warpN = warp & 1;
    int z = (MODE == 0) ? (int)blockIdx.z : 3;
    int m0 = blockIdx.y*128, n0 = blockIdx.x*128;
    const float* A = (MODE == 0) ? ((z == 2) ? x : d_xnorm) : d_coll;
    const float* W = (MODE == 0) ? ((z == 0) ? Wq : (z == 1) ? Wk : Wv) : Wo;

    float c[2][8][4];
    #pragma unroll
    for (int mt = 0; mt < 2; mt++)
        #pragma unroll
        for (int nt = 0; nt < 8; nt++)
            #pragma unroll
            for (int i = 0; i < 4; i++) c[mt][nt][i] = 0.f;

    const float* Abase = A + (size_t)m0*DIM;
    const float* Wbase = W + n0;

    float4 pa[4], pb0[2], pb1[2];
    #pragma unroll
    for (int j = 0; j < 4; j++) {
        int idx = tid + 256*j;
        pa[j] = *(const float4*)(Abase + (size_t)(idx >> 3)*DIM + (idx & 7)*4);
    }
    #pragma unroll
    for (int j = 0; j < 2; j++) {
        int idx = tid + 256*j;
        int kp = idx >> 5, nq = (idx & 31)*4;
        pb0[j] = *(const float4*)(Wbase + (size_t)(2*kp)*DIM + nq);
        pb1[j] = *(const float4*)(Wbase + (size_t)(2*kp + 1)*DIM + nq);
    }

    for (int ch = 0; ch < DIM/32; ch++) {
        #pragma unroll
        for (int j = 0; j < 4; j++) {
            int idx = tid + 256*j;
            int r = idx >> 3, k4 = idx & 7;
            float4 v = pa[j];
            uint2 hh = make_uint2(bfpack2(v.x, v.y), bfpack2(v.z, v.w));
            uint2 ll = make_uint2(bfpack2(bflo(v.x), bflo(v.y)), bfpack2(bflo(v.z), bflo(v.w)));
            *(uint2*)&smw[GAH + r*GA_ST + k4*2] = hh;
            *(uint2*)&smw[GAL + r*GA_ST + k4*2] = ll;
        }
        #pragma unroll
        for (int j = 0; j < 2; j++) {
            int idx = tid + 256*j;
            int kp = idx >> 5, nq = (idx & 31)*4;
            float4 r0 = pb0[j], r1 = pb1[j];
            uint4 hh = make_uint4(bfpack2(r0.x, r1.x), bfpack2(r0.y, r1.y),
                                  bfpack2(r0.z, r1.z), bfpack2(r0.w, r1.w));
            uint4 ll = make_uint4(bfpack2(bflo(r0.x), bflo(r1.x)), bfpack2(bflo(r0.y), bflo(r1.y)),
                                  bfpack2(bflo(r0.z), bflo(r1.z)), bfpack2(bflo(r0.w), bflo(r1.w)));
            *(uint4*)&smw[GBH + kp*GB_ST + nq] = hh;
            *(uint4*)&smw[GBL + kp*GB_ST + nq] = ll;
        }
        __syncthreads();

        if (ch + 1 < DIM/32) {
            int k0n = (ch + 1)*32;
            #pragma unroll
            for (int j = 0; j < 4; j++) {
                int idx = tid + 256*j;
                pa[j] = *(const float4*)(Abase + (size_t)(idx >> 3)*DIM + k0n + (idx & 7)*4);
            }
            #pragma unroll
            for (int j = 0; j < 2; j++) {
                int idx = tid + 256*j;
                int kp = idx >> 5, nq = (idx & 31)*4;
                pb0[j] = *(const float4*)(Wbase + (size_t)(k0n + 2*kp)*DIM + nq);
                pb1[j] = *(const float4*)(Wbase + (size_t)(k0n + 2*kp + 1)*DIM + nq);
            }
        }

        #pragma unroll
        for (int k16 = 0; k16 < 2; k16++) {
            int cw = k16*8 + (lane & 3);
            uint32_t ah[2][4], al[2][4];
            #pragma unroll
            for (int mt = 0; mt < 2; mt++) {
                int rA = warpM*32 + mt*16 + (lane >> 2);
                ah[mt][0] = smw[GAH + rA*GA_ST + cw];
                ah[mt][1] = smw[GAH + (rA+8)*GA_ST + cw];
                ah[mt][2] = smw[GAH + rA*GA_ST + cw + 4];
                ah[mt][3] = smw[GAH + (rA+8)*GA_ST + cw + 4];
                al[mt][0] = smw[GAL + rA*GA_ST + cw];
                al[mt][1] = smw[GAL + (rA+8)*GA_ST + cw];
                al[mt][2] = smw[GAL + rA*GA_ST + cw + 4];
                al[mt][3] = smw[GAL + (rA+8)*GA_ST + cw + 4];
            }
            #pragma unroll
            for (int nt = 0; nt < 8; nt++) {
                int cB = warpN*64 + nt*8 + (lane >> 2);
                uint32_t bh[2] = { smw[GBH + cw*GB_ST + cB], smw[GBH + (cw+4)*GB_ST + cB] };
                uint32_t bl[2] = { smw[GBL + cw*GB_ST + cB], smw[GBL + (cw+4)*GB_ST + cB] };
                #pragma unroll
                for (int mt = 0; mt < 2; mt++) {
                    mma_bf16(c[mt][nt], ah[mt], bh);
                    mma_bf16(c[mt][nt], ah[mt], bl);
                    mma_bf16(c[mt][nt], al[mt], bh);
                }
            }
        }
        __syncthreads();
    }

    #pragma unroll
    for (int mt = 0; mt < 2; mt++) {
        #pragma unroll
        for (int nt = 0; nt < 8; nt++) {
            int row = m0 + warpM*32 + mt*16 + (lane >> 2);
            int col = n0 + warpN*64 + nt*8 + (lane & 3)*2;
            #pragma unroll
            for (int half = 0; half < 2; half++) {
                int r = row + half*8;
                float2 v = make_float2(c[mt][nt][half*2], c[mt][nt][half*2+1]);
                if (MODE == 0) {
                    float* dst = (z == 0) ? d_Q : (z == 1) ? d_K : d_V;
                    int b = r >> 11, t = r & 2047;
                    int h = col >> 6, dd = col & 63;
                    *(float2*)&dst[(((size_t)(b*HEADS + h))*TLEN + t)*HD + dd] = v;
                } else {
                    v.x += bo[col]; v.y += bo[col+1];
                    *(float2*)&outp[(size_t)r*DIM + col] = v;
                }
            }
        }
    }
}

// ------- L2 normalize + gates + bf16 hi/lo split (validated R7) --------------
__device__ __forceinline__ void bf_split(float v, __nv_bfloat16& h, __nv_bfloat16& l) {
    h = __float2bfloat16_rn(v);
    l = __float2bfloat16_rn(v - __bfloat162float(h));
}
__global__ void normgate_kernel(const float* __restrict__ gqv,
                                const float* __restrict__ gkv) {
    int r = (blockIdx.x*blockDim.x + threadIdx.x) >> 5;
    int lane = threadIdx.x & 31;
    if (r >= HROWS) return;
    const float* q = d_Q + (size_t)r*HD;
    const float* k = d_K + (size_t)r*HD;
    const float* v = d_V + (size_t)r*HD;

    float q0 = q[lane], q1 = q[lane+32];
    float ss = q0*q0 + q1*q1;
    #pragma unroll
    for (int o = 16; o > 0; o >>= 1) ss += __shfl_xor_sync(~0u, ss, o);
    float inv = 1.0f / fmaxf(sqrtf(ss), 1e-12f);
    q0 *= inv; q1 *= inv;
    __nv_bfloat16 h0, l0, h1, l1;
    bf_split(q0, h0, l0); bf_split(q1, h1, l1);
    d_Qh[(size_t)r*HD + lane] = h0;       d_Ql[(size_t)r*HD + lane] = l0;
    d_Qh[(size_t)r*HD + lane + 32] = h1;  d_Ql[(size_t)r*HD + lane + 32] = l1;
    float g = q0*gqv[lane] + q1*gqv[lane+32];
    #pragma unroll
    for (int o = 16; o > 0; o >>= 1) g += __shfl_xor_sync(~0u, g, o);
    if (lane == 0) d_gq[r] = g;

    float k0 = k[lane], k1 = k[lane+32];
    ss = k0*k0 + k1*k1;
    #pragma unroll
    for (int o = 16; o > 0; o >>= 1) ss += __shfl_xor_sync(~0u, ss, o);
    inv = 1.0f / fmaxf(sqrtf(ss), 1e-12f);
    k0 *= inv; k1 *= inv;
    bf_split(k0, h0, l0); bf_split(k1, h1, l1);
    d_Kh[(size_t)r*HD + lane] = h0;       d_Kl[(size_t)r*HD + lane] = l0;
    d_Kh[(size_t)r*HD + lane + 32] = h1;  d_Kl[(size_t)r*HD + lane + 32] = l1;
    float gk = k0*gkv[lane] + k1*gkv[lane+32];
    #pragma unroll
    for (int o = 16; o > 0; o >>= 1) gk += __shfl_xor_sync(~0u, gk, o);

    int head = r >> 11, sl = r & 2047;
    size_t vbase = (size_t)head*HD*TLEN;
    float v0 = v[lane]*gk, v1 = v[lane+32]*gk;
    bf_split(v0, h0, l0); bf_split(v1, h1, l1);
    d_Vth[vbase + (size_t)lane*TLEN + sl] = h0;
    d_Vtl[vbase + (size_t)lane*TLEN + sl] = l0;
    d_Vth[vbase + (size_t)(lane+32)*TLEN + sl] = h1;
    d_Vtl[vbase + (size_t)(lane+32)*TLEN + sl] = l1;
}

// ------ bf16x3 attention, warp-local P: 8 warps x (16t x 64s), no P smem -----
#define ST 36
#define WQH 0
#define WQL (128*ST)
#define WKH (2*128*ST)
#define WKL (2*128*ST + 64*ST)
#define WVH (2*128*ST + 2*64*ST)
#define WVL (2*128*ST + 3*64*ST)
#define ATT_SMEM ((2*128*ST + 4*64*ST)*4)

__global__ __launch_bounds__(256, 2)
void attn_tc() {
    extern __shared__ uint32_t smw[];
    __shared__ float gqs[128];
    int tid = threadIdx.x, lane = tid & 31;
    int warp = tid >> 5;
    int h = blockIdx.y, b = blockIdx.z;
    int t0 = blockIdx.x * 128;
    int head = b*HEADS + h;
    size_t base = (size_t)head*TLEN;

    {
        const uint4* qh = (const uint4*)(d_Qh + (base + t0)*HD);
        const uint4* ql = (const uint4*)(d_Ql + (base + t0)*HD);
        #pragma unroll
        for (int j = 0; j < 4; j++) {
            int e = tid + 256*j;
            int t = e >> 3, q4 = (e & 7)*4;
            *(uint4*)&smw[WQH + t*ST + q4] = qh[e];
            *(uint4*)&smw[WQL + t*ST + q4] = ql[e];
        }
    }
    if (tid < 128) gqs[tid] = d_gq[base + t0 + tid];

    float acc[8][4];
    #pragma unroll
    for (int nt = 0; nt < 8; nt++)
        #pragma unroll
        for (int i = 0; i < 4; i++) acc[nt][i] = 0.f;

    int rA = warp*16 + (lane >> 2);

    for (int s0 = 0; s0 < TLEN; s0 += 64) {
        __syncthreads();
        {
            const uint4* kh = (const uint4*)(d_Kh + (base + s0)*HD);
            const uint4* kl = (const uint4*)(d_Kl + (base + s0)*HD);
            const uint4* vh = (const uint4*)(d_Vth + (size_t)head*HD*TLEN + s0);
            const uint4* vl = (const uint4*)(d_Vtl + (size_t)head*HD*TLEN + s0);
            #pragma unroll
            for (int j = 0; j < 2; j++) {
                int e = tid + 256*j;
                int rr = e >> 3, q4 = (e & 7)*4;
                *(uint4*)&smw[WKH + rr*ST + q4] = kh[e];
                *(uint4*)&smw[WKL + rr*ST + q4] = kl[e];
                *(uint4*)&smw[WVH + rr*ST + q4] = vh[(size_t)rr*(TLEN/8) + (e & 7)];
                *(uint4*)&smw[WVL + rr*ST + q4] = vl[(size_t)rr*(TLEN/8) + (e & 7)];
            }
        }
        __syncthreads();

        // QK^T: per-warp 16 t x 64 s
        float c[8][4];
        #pragma unroll
        for (int nt = 0; nt < 8; nt++)
            #pragma unroll
            for (int i = 0; i < 4; i++) c[nt][i] = 0.f;

        #pragma unroll
        for (int k16 = 0; k16 < 4; k16++) {
            int cw = k16*8 + (lane & 3);
            uint32_t ah[4], al[4];
            ah[0] = smw[WQH + rA*ST + cw];
            ah[1] = smw[WQH + (rA+8)*ST + cw];
            ah[2] = smw[WQH + rA*ST + cw + 4];
            ah[3] = smw[WQH + (rA+8)*ST + cw + 4];
            al[0] = smw[WQL + rA*ST + cw];
            al[1] = smw[WQL + (rA+8)*ST + cw];
            al[2] = smw[WQL + rA*ST + cw + 4];
            al[3] = smw[WQL + (rA+8)*ST + cw + 4];
            #pragma unroll
            for (int nt = 0; nt < 8; nt++) {
                int cB = nt*8 + (lane >> 2);
                uint32_t bh[2] = { smw[WKH + cB*ST + cw], smw[WKH + cB*ST + cw + 4] };
                uint32_t bl[2] = { smw[WKL + cB*ST + cw], smw[WKL + cB*ST + cw + 4] };
                mma_bf16(c[nt], ah, bh);
                mma_bf16(c[nt], ah, bl);
                mma_bf16(c[nt], al, bh);
            }
        }

        // sigmoid + hi/lo pack IN REGISTERS (acc layout == PV A-fragment layout)
        uint32_t ph[8][2], pl[8][2];
        #pragma unroll
        for (int nt = 0; nt < 8; nt++)
            #pragma unroll
            for (int half = 0; half < 2; half++) {
                float z0 = (c[nt][half*2]   - THRESH) * SHARP;
                float z1 = (c[nt][half*2+1] - THRESH) * SHARP;
                float p0 = __fdividef(1.0f, 1.0f + __expf(-z0));
                float p1 = __fdividef(1.0f, 1.0f + __expf(-z1));
                ph[nt][half] = bfpack2(p0, p1);
                pl[nt][half] = bfpack2(bflo(p0), bflo(p1));
            }

        // P @ V: per-warp 16 t x 64 d, A from registers
        #pragma unroll
        for (int k16 = 0; k16 < 4; k16++) {
            int cw = k16*8 + (lane & 3);
            uint32_t ah[4] = { ph[2*k16][0], ph[2*k16][1], ph[2*k16+1][0], ph[2*k16+1][1] };
            uint32_t al[4] = { pl[2*k16][0], pl[2*k16][1], pl[2*k16+1][0], pl[2*k16+1][1] };
            #pragma unroll
            for (int nt = 0; nt < 8; nt++) {
                int cB = nt*8 + (lane >> 2);
                uint32_t bh[2] = { smw[WVH + cB*ST + cw], smw[WVH + cB*ST + cw + 4] };
                uint32_t bl[2] = { smw[WVL + cB*ST + cw], smw[WVL + cB*ST + cw + 4] };
                mma_bf16(acc[nt], ah, bh);
                mma_bf16(acc[nt], ah, bl);
                mma_bf16(acc[nt], al, bh);
            }
        }
    }

    // epilogue: * gq -> d_coll[b][t][h*64+d]
    float* Cb = d_coll + ((size_t)(b*TLEN) + t0)*DIM + h*HD;
    #pragma unroll
    for (int nt = 0; nt < 8; nt++)
        #pragma unroll
        for (int half = 0; half < 2; half++) {
            int row = warp*16 + (lane >> 2) + half*8;
            int col = nt*8 + (lane & 3)*2;
            float g = gqs[row];
            float2 v = make_float2(acc[nt][half*2]*g, acc[nt][half*2+1]*g);
            *(float2*)&Cb[(size_t)row*DIM + col] = v;
        }
}

// ---------------- launch ------------------------------------------------------
extern "C" void kernel_launch(void* const* d_in, const int* in_sizes, int n_in,
                              void* d_out, int out_size) {
    const float* x   = (const float*)d_in[0];
    const float* Wq  = (const float*)d_in[1];
    const float* Wk  = (const float*)d_in[2];
    const float* Wv  = (const float*)d_in[3];
    const float* gqv = (const float*)d_in[4];
    const float* gkv = (const float*)d_in[5];
    const float* Wo  = (const float*)d_in[6];
    const float* bo  = (const float*)d_in[7];
    const float* lnw = (const float*)d_in[8];
    const float* lnb = (const float*)d_in[9];
    float* out = (float*)d_out;

    cudaFuncSetAttribute(attn_tc, cudaFuncAttributeMaxDynamicSharedMemorySize, ATT_SMEM);
    cudaFuncSetAttribute(gemm_ts<0>, cudaFuncAttributeMaxDynamicSharedMemorySize, GEMM_SMEM);
    cudaFuncSetAttribute(gemm_ts<1>, cudaFuncAttributeMaxDynamicSharedMemorySize, GEMM_SMEM);

    ln_kernel<<<ROWS, 256>>>(x, lnw, lnb);
    gemm_ts<0><<<dim3(8, 32, 3), 256, GEMM_SMEM>>>(x, Wq, Wk, Wv, Wo, bo, nullptr);
    normgate_kernel<<<HROWS*32/256, 256>>>(gqv, gkv);
    attn_tc<<<dim3(TLEN/128, HEADS, BATCH), 256, ATT_SMEM>>>();
    gemm_ts<1><<<dim3(8, 32), 256, GEMM_SMEM>>>(nullptr, Wq, Wk, Wv, Wo, bo, out);
}

// round 11
// speedup vs baseline: 4.1266x; 1.0116x over previous
#include <cuda_runtime.h>
#include <cuda_bf16.h>
#include <cstdint>
#include <math.h>

#define DIM    1024
#define BATCH  2
#define TLEN   2048
#define HEADS  16
#define HD     64
#define ROWS   (BATCH*TLEN)
#define HROWS  (BATCH*HEADS*TLEN)
#define THRESH 0.29514f
#define SHARP  15.0f

__device__ float d_xnorm[ROWS*DIM];
__device__ float d_Q[HROWS*HD];
__device__ float d_K[HROWS*HD];
__device__ float d_V[HROWS*HD];
__device__ float d_gq[HROWS];
__device__ float d_coll[ROWS*DIM];
__device__ __align__(16) __nv_bfloat16 d_Qh[HROWS*HD];
__device__ __align__(16) __nv_bfloat16 d_Ql[HROWS*HD];
__device__ __align__(16) __nv_bfloat16 d_Kh[HROWS*HD];
__device__ __align__(16) __nv_bfloat16 d_Kl[HROWS*HD];
__device__ __align__(16) __nv_bfloat16 d_Vth[HROWS*HD];  // [b,h][d][s]
__device__ __align__(16) __nv_bfloat16 d_Vtl[HROWS*HD];

// ---------------- mma.sync / helpers ----------------
__device__ __forceinline__ void mma_bf16(float* c, const uint32_t* a, const uint32_t* b) {
    asm volatile(
        "mma.sync.aligned.m16n8k16.row.col.f32.bf16.bf16.f32 "
        "{%0,%1,%2,%3}, {%4,%5,%6,%7}, {%8,%9}, {%0,%1,%2,%3};"
        : "+f"(c[0]), "+f"(c[1]), "+f"(c[2]), "+f"(c[3])
        : "r"(a[0]), "r"(a[1]), "r"(a[2]), "r"(a[3]), "r"(b[0]), "r"(b[1]));
}
__device__ __forceinline__ uint32_t bfpack2(float a, float b) {
    __nv_bfloat162 p = __floats2bfloat162_rn(a, b);
    return *reinterpret_cast<uint32_t*>(&p);
}
__device__ __forceinline__ float bflo(float v) {
    return v - __bfloat162float(__float2bfloat16_rn(v));
}
__device__ __forceinline__ void cp16(uint32_t smem_addr, const void* gptr) {
    asm volatile("cp.async.cg.shared.global [%0], [%1], 16;"
                 :: "r"(smem_addr), "l"(gptr) : "memory");
}
#define CP_COMMIT() asm volatile("cp.async.commit_group;" ::: "memory")
#define CP_WAIT0()  asm volatile("cp.async.wait_group 0;" ::: "memory")

// ---------------- LayerNorm ----------------
__global__ void ln_kernel(const float* __restrict__ x,
                          const float* __restrict__ w,
                          const float* __restrict__ bvec) {
    int row = blockIdx.x, tid = threadIdx.x;
    float4 v = ((const float4*)(x + (size_t)row*DIM))[tid];
    float s  = v.x+v.y+v.z+v.w;
    float ss = v.x*v.x+v.y*v.y+v.z*v.z+v.w*v.w;
    #pragma unroll
    for (int o = 16; o > 0; o >>= 1) {
        s  += __shfl_xor_sync(~0u, s, o);
        ss += __shfl_xor_sync(~0u, ss, o);
    }
    __shared__ float rs[8], rss[8];
    int wid = tid >> 5, lane = tid & 31;
    if (lane == 0) { rs[wid] = s; rss[wid] = ss; }
    __syncthreads();
    s = 0.f; ss = 0.f;
    #pragma unroll
    for (int i = 0; i < 8; i++) { s += rs[i]; ss += rss[i]; }
    float mean = s*(1.f/DIM), var = ss*(1.f/DIM) - mean*mean;
    float rstd = rsqrtf(var + 1e-5f);
    float4 wv = ((const float4*)w)[tid], bv = ((const float4*)bvec)[tid];
    float4 o;
    o.x = (v.x-mean)*rstd*wv.x + bv.x;  o.y = (v.y-mean)*rstd*wv.y + bv.y;
    o.z = (v.z-mean)*rstd*wv.z + bv.z;  o.w = (v.w-mean)*rstd*wv.w + bv.w;
    ((float4*)(d_xnorm + (size_t)row*DIM))[tid] = o;
}

// ---------------- bf16x3 GEMM (validated R8) ----------------
#define GA_ST 20
#define GB_ST 136
#define GAH 0
#define GAL (128*GA_ST)
#define GBH (2*128*GA_ST)
#define GBL (2*128*GA_ST + 16*GB_ST)
#define GEMM_SMEM ((2*128*GA_ST + 2*16*GB_ST)*4)

template<int MODE>
__global__ __launch_bounds__(256, 1)
void gemm_ts(const float* __restrict__ x,
             const float* __restrict__ Wq, const float* __restrict__ Wk,
             const float* __restrict__ Wv, const float* __restrict__ Wo,
             const float* __restrict__ bo, float* __restrict__ outp) {
    extern __shared__ uint32_t smw[];
    int tid = threadIdx.x, lane = tid & 31;
    int warp = tid >> 5, warpM = warp >> 1, warpN = warp & 1;
    int z = (MODE == 0) ? (int)blockIdx.z : 3;
    int m0 = blockIdx.y*128, n0 = blockIdx.x*128;
    const float* A = (MODE == 0) ? ((z == 2) ? x : d_xnorm) : d_coll;
    const float* W = (MODE == 0) ? ((z == 0) ? Wq : (z == 1) ? Wk : Wv) : Wo;

    float c[2][8][4];
    #pragma unroll
    for (int mt = 0; mt < 2; mt++)
        #pragma unroll
        for (int nt = 0; nt < 8; nt++)
            #pragma unroll
            for (int i = 0; i < 4; i++) c[mt][nt][i] = 0.f;

    const float* Abase = A + (size_t)m0*DIM;
    const float* Wbase = W + n0;

    float4 pa[4], pb0[2], pb1[2];
    #pragma unroll
    for (int j = 0; j < 4; j++) {
        int idx = tid + 256*j;
        pa[j] = *(const float4*)(Abase + (size_t)(idx >> 3)*DIM + (idx & 7)*4);
    }
    #pragma unroll
    for (int j = 0; j < 2; j++) {
        int idx = tid + 256*j;
        int kp = idx >> 5, nq = (idx & 31)*4;
        pb0[j] = *(const float4*)(Wbase + (size_t)(2*kp)*DIM + nq);
        pb1[j] = *(const float4*)(Wbase + (size_t)(2*kp + 1)*DIM + nq);
    }

    for (int ch = 0; ch < DIM/32; ch++) {
        #pragma unroll
        for (int j = 0; j < 4; j++) {
            int idx = tid + 256*j;
            int r = idx >> 3, k4 = idx & 7;
            float4 v = pa[j];
            uint2 hh = make_uint2(bfpack2(v.x, v.y), bfpack2(v.z, v.w));
            uint2 ll = make_uint2(bfpack2(bflo(v.x), bflo(v.y)), bfpack2(bflo(v.z), bflo(v.w)));
            *(uint2*)&smw[GAH + r*GA_ST + k4*2] = hh;
            *(uint2*)&smw[GAL + r*GA_ST + k4*2] = ll;
        }
        #pragma unroll
        for (int j = 0; j < 2; j++) {
            int idx = tid + 256*j;
            int kp = idx >> 5, nq = (idx & 31)*4;
            float4 r0 = pb0[j], r1 = pb1[j];
            uint4 hh = make_uint4(bfpack2(r0.x, r1.x), bfpack2(r0.y, r1.y),
                                  bfpack2(r0.z, r1.z), bfpack2(r0.w, r1.w));
            uint4 ll = make_uint4(bfpack2(bflo(r0.x), bflo(r1.x)), bfpack2(bflo(r0.y), bflo(r1.y)),
                                  bfpack2(bflo(r0.z), bflo(r1.z)), bfpack2(bflo(r0.w), bflo(r1.w)));
            *(uint4*)&smw[GBH + kp*GB_ST + nq] = hh;
            *(uint4*)&smw[GBL + kp*GB_ST + nq] = ll;
        }
        __syncthreads();

        if (ch + 1 < DIM/32) {
            int k0n = (ch + 1)*32;
            #pragma unroll
            for (int j = 0; j < 4; j++) {
                int idx = tid + 256*j;
                pa[j] = *(const float4*)(Abase + (size_t)(idx >> 3)*DIM + k0n + (idx & 7)*4);
            }
            #pragma unroll
            for (int j = 0; j < 2; j++) {
                int idx = tid + 256*j;
                int kp = idx >> 5, nq = (idx & 31)*4;
                pb0[j] = *(const float4*)(Wbase + (size_t)(k0n + 2*kp)*DIM + nq);
                pb1[j] = *(const float4*)(Wbase + (size_t)(k0n + 2*kp + 1)*DIM + nq);
            }
        }

        #pragma unroll
        for (int k16 = 0; k16 < 2; k16++) {
            int cw = k16*8 + (lane & 3);
            uint32_t ah[2][4], al[2][4];
            #pragma unroll
            for (int mt = 0; mt < 2; mt++) {
                int rA = warpM*32 + mt*16 + (lane >> 2);
                ah[mt][0] = smw[GAH + rA*GA_ST + cw];
                ah[mt][1] = smw[GAH + (rA+8)*GA_ST + cw];
                ah[mt][2] = smw[GAH + rA*GA_ST + cw + 4];
                ah[mt][3] = smw[GAH + (rA+8)*GA_ST + cw + 4];
                al[mt][0] = smw[GAL + rA*GA_ST + cw];
                al[mt][1] = smw[GAL + (rA+8)*GA_ST + cw];
                al[mt][2] = smw[GAL + rA*GA_ST + cw + 4];
                al[mt][3] = smw[GAL + (rA+8)*GA_ST + cw + 4];
            }
            #pragma unroll
            for (int nt = 0; nt < 8; nt++) {
                int cB = warpN*64 + nt*8 + (lane >> 2);
                uint32_t bh[2] = { smw[GBH + cw*GB_ST + cB], smw[GBH + (cw+4)*GB_ST + cB] };
                uint32_t bl[2] = { smw[GBL + cw*GB_ST + cB], smw[GBL + (cw+4)*GB_ST + cB] };
                #pragma unroll
                for (int mt = 0; mt < 2; mt++) {
                    mma_bf16(c[mt][nt], ah[mt], bh);
                    mma_bf16(c[mt][nt], ah[mt], bl);
                    mma_bf16(c[mt][nt], al[mt], bh);
                }
            }
        }
        __syncthreads();
    }

    #pragma unroll
    for (int mt = 0; mt < 2; mt++) {
        #pragma unroll
        for (int nt = 0; nt < 8; nt++) {
            int row = m0 + warpM*32 + mt*16 + (lane >> 2);
            int col = n0 + warpN*64 + nt*8 + (lane & 3)*2;
            #pragma unroll
            for (int half = 0; half < 2; half++) {
                int r = row + half*8;
                float2 v = make_float2(c[mt][nt][half*2], c[mt][nt][half*2+1]);
                if (MODE == 0) {
                    float* dst = (z == 0) ? d_Q : (z == 1) ? d_K : d_V;
                    int b = r >> 11, t = r & 2047;
                    int h = col >> 6, dd = col & 63;
                    *(float2*)&dst[(((size_t)(b*HEADS + h))*TLEN + t)*HD + dd] = v;
                } else {
                    v.x += bo[col]; v.y += bo[col+1];
                    *(float2*)&outp[(size_t)r*DIM + col] = v;
                }
            }
        }
    }
}

// ------- L2 normalize + gates + bf16 hi/lo split (validated R7) --------------
__device__ __forceinline__ void bf_split(float v, __nv_bfloat16& h, __nv_bfloat16& l) {
    h = __float2bfloat16_rn(v);
    l = __float2bfloat16_rn(v - __bfloat162float(h));
}
__global__ void normgate_kernel(const float* __restrict__ gqv,
                                const float* __restrict__ gkv) {
    int r = (blockIdx.x*blockDim.x + threadIdx.x) >> 5;
    int lane = threadIdx.x & 31;
    if (r >= HROWS) return;
    const float* q = d_Q + (size_t)r*HD;
    const float* k = d_K + (size_t)r*HD;
    const float* v = d_V + (size_t)r*HD;

    float q0 = q[lane], q1 = q[lane+32];
    float ss = q0*q0 + q1*q1;
    #pragma unroll
    for (int o = 16; o > 0; o >>= 1) ss += __shfl_xor_sync(~0u, ss, o);
    float inv = 1.0f / fmaxf(sqrtf(ss), 1e-12f);
    q0 *= inv; q1 *= inv;
    __nv_bfloat16 h0, l0, h1, l1;
    bf_split(q0, h0, l0); bf_split(q1, h1, l1);
    d_Qh[(size_t)r*HD + lane] = h0;       d_Ql[(size_t)r*HD + lane] = l0;
    d_Qh[(size_t)r*HD + lane + 32] = h1;  d_Ql[(size_t)r*HD + lane + 32] = l1;
    float g = q0*gqv[lane] + q1*gqv[lane+32];
    #pragma unroll
    for (int o = 16; o > 0; o >>= 1) g += __shfl_xor_sync(~0u, g, o);
    if (lane == 0) d_gq[r] = g;

    float k0 = k[lane], k1 = k[lane+32];
    ss = k0*k0 + k1*k1;
    #pragma unroll
    for (int o = 16; o > 0; o >>= 1) ss += __shfl_xor_sync(~0u, ss, o);
    inv = 1.0f / fmaxf(sqrtf(ss), 1e-12f);
    k0 *= inv; k1 *= inv;
    bf_split(k0, h0, l0); bf_split(k1, h1, l1);
    d_Kh[(size_t)r*HD + lane] = h0;       d_Kl[(size_t)r*HD + lane] = l0;
    d_Kh[(size_t)r*HD + lane + 32] = h1;  d_Kl[(size_t)r*HD + lane + 32] = l1;
    float gk = k0*gkv[lane] + k1*gkv[lane+32];
    #pragma unroll
    for (int o = 16; o > 0; o >>= 1) gk += __shfl_xor_sync(~0u, gk, o);

    int head = r >> 11, sl = r & 2047;
    size_t vbase = (size_t)head*HD*TLEN;
    float v0 = v[lane]*gk, v1 = v[lane+32]*gk;
    bf_split(v0, h0, l0); bf_split(v1, h1, l1);
    d_Vth[vbase + (size_t)lane*TLEN + sl] = h0;
    d_Vtl[vbase + (size_t)lane*TLEN + sl] = l0;
    d_Vth[vbase + (size_t)(lane+32)*TLEN + sl] = h1;
    d_Vtl[vbase + (size_t)(lane+32)*TLEN + sl] = l1;
}

// --- bf16x3 attention: warp-local P, Q frags in regs, cp.async 2-stage KV ----
#define ST 36
#define WQH 0
#define WQL (128*ST)
#define KV0 (2*128*ST)
#define KVSTAGE (4*64*ST)
#define ATT_SMEM ((2*128*ST + 2*KVSTAGE)*4)   // 110592 B

__global__ __launch_bounds__(256, 2)
void attn_tc() {
    extern __shared__ uint32_t smw[];
    __shared__ float gqs[128];
    int tid = threadIdx.x, lane = tid & 31;
    int warp = tid >> 5;
    int h = blockIdx.y, b = blockIdx.z;
    int t0 = blockIdx.x * 128;
    int head = b*HEADS + h;
    size_t base = (size_t)head*TLEN;
    uint32_t smbase = (uint32_t)__cvta_generic_to_shared(smw);

    // stage Q into smem (plain stores)
    {
        const uint4* qh = (const uint4*)(d_Qh + (base + t0)*HD);
        const uint4* ql = (const uint4*)(d_Ql + (base + t0)*HD);
        #pragma unroll
        for (int j = 0; j < 4; j++) {
            int e = tid + 256*j;
            int t = e >> 3, q4 = (e & 7)*4;
            *(uint4*)&smw[WQH + t*ST + q4] = qh[e];
            *(uint4*)&smw[WQL + t*ST + q4] = ql[e];
        }
    }
    if (tid < 128) gqs[tid] = d_gq[base + t0 + tid];

    // prologue: async-load KV stage 0
    const char* khg = (const char*)(d_Kh + base*HD);
    const char* klg = (const char*)(d_Kl + base*HD);
    const char* vhg = (const char*)(d_Vth + (size_t)head*HD*TLEN);
    const char* vlg = (const char*)(d_Vtl + (size_t)head*HD*TLEN);
    int e0 = tid, e1 = tid + 256;
    int rr0 = e0 >> 3, q40 = (e0 & 7), rr1 = e1 >> 3, q41 = (e1 & 7);
    uint32_t soff0 = (rr0*ST + q40*4)*4, soff1 = (rr1*ST + q41*4)*4;
    size_t voff0 = ((size_t)rr0*(TLEN/8) + q40)*16;
    size_t voff1 = ((size_t)rr1*(TLEN/8) + q41)*16;

    {
        uint32_t kvb = smbase + KV0*4;
        cp16(kvb + soff0, khg + (size_t)e0*16);
        cp16(kvb + soff1, khg + (size_t)e1*16);
        cp16(kvb + 64*ST*4 + soff0, klg + (size_t)e0*16);
        cp16(kvb + 64*ST*4 + soff1, klg + (size_t)e1*16);
        cp16(kvb + 2*64*ST*4 + soff0, vhg + voff0);
        cp16(kvb + 2*64*ST*4 + soff1, vhg + voff1);
        cp16(kvb + 3*64*ST*4 + soff0, vlg + voff0);
        cp16(kvb + 3*64*ST*4 + soff1, vlg + voff1);
        CP_COMMIT();
    }
    __syncthreads();   // Q smem visible

    // hoist Q fragments into registers (warp-local rows)
    int rA = warp*16 + (lane >> 2);
    uint32_t qfh[4][4], qfl[4][4];
    #pragma unroll
    for (int k16 = 0; k16 < 4; k16++) {
        int cw = k16*8 + (lane & 3);
        qfh[k16][0] = smw[WQH + rA*ST + cw];
        qfh[k16][1] = smw[WQH + (rA+8)*ST + cw];
        qfh[k16][2] = smw[WQH + rA*ST + cw + 4];
        qfh[k16][3] = smw[WQH + (rA+8)*ST + cw + 4];
        qfl[k16][0] = smw[WQL + rA*ST + cw];
        qfl[k16][1] = smw[WQL + (rA+8)*ST + cw];
        qfl[k16][2] = smw[WQL + rA*ST + cw + 4];
        qfl[k16][3] = smw[WQL + (rA+8)*ST + cw + 4];
    }

    float acc[8][4];
    #pragma unroll
    for (int nt = 0; nt < 8; nt++)
        #pragma unroll
        for (int i = 0; i < 4; i++) acc[nt][i] = 0.f;

    for (int it = 0; it < TLEN/64; it++) {
        CP_WAIT0();
        __syncthreads();   // KV stage (it&1) visible to all; prev compute done

        if (it + 1 < TLEN/64) {
            size_t s0n = (size_t)(it + 1)*64;
            uint32_t kvb = smbase + (KV0 + ((it+1)&1)*KVSTAGE)*4;
            size_t koff = s0n*HD*2;   // bytes: 64 rows x 64 bf16
            cp16(kvb + soff0, khg + koff + (size_t)e0*16);
            cp16(kvb + soff1, khg + koff + (size_t)e1*16);
            cp16(kvb + 64*ST*4 + soff0, klg + koff + (size_t)e0*16);
            cp16(kvb + 64*ST*4 + soff1, klg + koff + (size_t)e1*16);
            size_t vcoff = s0n*2;     // bytes: column offset in [d][s]
            cp16(kvb + 2*64*ST*4 + soff0, vhg + vcoff + voff0);
            cp16(kvb + 2*64*ST*4 + soff1, vhg + vcoff + voff1);
            cp16(kvb + 3*64*ST*4 + soff0, vlg + vcoff + voff0);
            cp16(kvb + 3*64*ST*4 + soff1, vlg + vcoff + voff1);
            CP_COMMIT();
        }

        int kvw = KV0 + (it & 1)*KVSTAGE;
        int KH = kvw, KL = kvw + 64*ST, VH = kvw + 2*64*ST, VL = kvw + 3*64*ST;

        // QK^T: per-warp 16t x 64s
        float c[8][4];
        #pragma unroll
        for (int nt = 0; nt < 8; nt++)
            #pragma unroll
            for (int i = 0; i < 4; i++) c[nt][i] = 0.f;

        #pragma unroll
        for (int k16 = 0; k16 < 4; k16++) {
            int cw = k16*8 + (lane & 3);
            #pragma unroll
            for (int nt = 0; nt < 8; nt++) {
                int cB = nt*8 + (lane >> 2);
                uint32_t bh[2] = { smw[KH + cB*ST + cw], smw[KH + cB*ST + cw + 4] };
                uint32_t bl[2] = { smw[KL + cB*ST + cw], smw[KL + cB*ST + cw + 4] };
                mma_bf16(c[nt], qfh[k16], bh);
                mma_bf16(c[nt], qfh[k16], bl);
                mma_bf16(c[nt], qfl[k16], bh);
            }
        }

        // sigmoid + hi/lo pack in registers (acc layout == PV A-fragment)
        uint32_t ph[8][2], pl[8][2];
        #pragma unroll
        for (int nt = 0; nt < 8; nt++)
            #pragma unroll
            for (int half = 0; half < 2; half++) {
                float z0 = (c[nt][half*2]   - THRESH) * SHARP;
                float z1 = (c[nt][half*2+1] - THRESH) * SHARP;
                float p0 = __fdividef(1.0f, 1.0f + __expf(-z0));
                float p1 = __fdividef(1.0f, 1.0f + __expf(-z1));
                ph[nt][half] = bfpack2(p0, p1);
                pl[nt][half] = bfpack2(bflo(p0), bflo(p1));
            }

        // P @ V: per-warp 16t x 64d, A from registers
        #pragma unroll
        for (int k16 = 0; k16 < 4; k16++) {
            int cw = k16*8 + (lane & 3);
            uint32_t ah[4] = { ph[2*k16][0], ph[2*k16][1], ph[2*k16+1][0], ph[2*k16+1][1] };
            uint32_t al[4] = { pl[2*k16][0], pl[2*k16][1], pl[2*k16+1][0], pl[2*k16+1][1] };
            #pragma unroll
            for (int nt = 0; nt < 8; nt++) {
                int cB = nt*8 + (lane >> 2);
                uint32_t bh[2] = { smw[VH + cB*ST + cw], smw[VH + cB*ST + cw + 4] };
                uint32_t bl[2] = { smw[VL + cB*ST + cw], smw[VL + cB*ST + cw + 4] };
                mma_bf16(acc[nt], ah, bh);
                mma_bf16(acc[nt], ah, bl);
                mma_bf16(acc[nt], al, bh);
            }
        }
    }

    // epilogue: * gq -> d_coll[b][t][h*64+d]
    float* Cb = d_coll + ((size_t)(b*TLEN) + t0)*DIM + h*HD;
    #pragma unroll
    for (int nt = 0; nt < 8; nt++)
        #pragma unroll
        for (int half = 0; half < 2; half++) {
            int row = warp*16 + (lane >> 2) + half*8;
            int col = nt*8 + (lane & 3)*2;
            float g = gqs[row];
            float2 v = make_float2(acc[nt][half*2]*g, acc[nt][half*2+1]*g);
            *(float2*)&Cb[(size_t)row*DIM + col] = v;
        }
}

// ---------------- launch ------------------------------------------------------
extern "C" void kernel_launch(void* const* d_in, const int* in_sizes, int n_in,
                              void* d_out, int out_size) {
    const float* x   = (const float*)d_in[0];
    const float* Wq  = (const float*)d_in[1];
    const float* Wk  = (const float*)d_in[2];
    const float* Wv  = (const float*)d_in[3];
    const float* gqv = (const float*)d_in[4];
    const float* gkv = (const float*)d_in[5];
    const float* Wo  = (const float*)d_in[6];
    const float* bo  = (const float*)d_in[7];
    const float* lnw = (const float*)d_in[8];
    const float* lnb = (const float*)d_in[9];
    float* out = (float*)d_out;

    cudaFuncSetAttribute(attn_tc, cudaFuncAttributeMaxDynamicSharedMemorySize, ATT_SMEM);
    cudaFuncSetAttribute(gemm_ts<0>, cudaFuncAttributeMaxDynamicSharedMemorySize, GEMM_SMEM);
    cudaFuncSetAttribute(gemm_ts<1>, cudaFuncAttributeMaxDynamicSharedMemorySize, GEMM_SMEM);

    ln_kernel<<<ROWS, 256>>>(x, lnw, lnb);
    gemm_ts<0><<<dim3(8, 32, 3), 256, GEMM_SMEM>>>(x, Wq, Wk, Wv, Wo, bo, nullptr);
    normgate_kernel<<<HROWS*32/256, 256>>>(gqv, gkv);
    attn_tc<<<dim3(TLEN/128, HEADS, BATCH), 256, ATT_SMEM>>>();
    gemm_ts<1><<<dim3(8, 32), 256, GEMM_SMEM>>>(nullptr, Wq, Wk, Wv, Wo, bo, out);
}

// round 12
// speedup vs baseline: 4.2307x; 1.0252x over previous
#include <cuda_runtime.h>
#include <cuda_bf16.h>
#include <cstdint>
#include <math.h>

#define DIM    1024
#define BATCH  2
#define TLEN   2048
#define HEADS  16
#define HD     64
#define ROWS   (BATCH*TLEN)
#define HROWS  (BATCH*HEADS*TLEN)
#define THRESH 0.29514f
#define SHARP  15.0f

__device__ float d_xnorm[ROWS*DIM];
__device__ float d_Q[HROWS*HD];
__device__ float d_K[HROWS*HD];
__device__ float d_V[HROWS*HD];
__device__ float d_gq[HROWS];
__device__ float d_coll[ROWS*DIM];
__device__ __align__(16) __nv_bfloat16 d_Qh[HROWS*HD];
__device__ __align__(16) __nv_bfloat16 d_Ql[HROWS*HD];
__device__ __align__(16) __nv_bfloat16 d_Kh[HROWS*HD];
__device__ __align__(16) __nv_bfloat16 d_Kl[HROWS*HD];
__device__ __align__(16) __nv_bfloat16 d_Vth[HROWS*HD];  // [b,h][d][s]
__device__ __align__(16) __nv_bfloat16 d_Vtl[HROWS*HD];

// ---------------- mma.sync / helpers ----------------
__device__ __forceinline__ void mma_bf16(float* c, const uint32_t* a, const uint32_t* b) {
    asm volatile(
        "mma.sync.aligned.m16n8k16.row.col.f32.bf16.bf16.f32 "
        "{%0,%1,%2,%3}, {%4,%5,%6,%7}, {%8,%9}, {%0,%1,%2,%3};"
        : "+f"(c[0]), "+f"(c[1]), "+f"(c[2]), "+f"(c[3])
        : "r"(a[0]), "r"(a[1]), "r"(a[2]), "r"(a[3]), "r"(b[0]), "r"(b[1]));
}
__device__ __forceinline__ void ldsm4(uint32_t* r, uint32_t addr) {
    asm volatile("ldmatrix.sync.aligned.m8n8.x4.shared.b16 {%0,%1,%2,%3}, [%4];"
                 : "=r"(r[0]), "=r"(r[1]), "=r"(r[2]), "=r"(r[3]) : "r"(addr));
}
__device__ __forceinline__ uint32_t bfpack2(float a, float b) {
    __nv_bfloat162 p = __floats2bfloat162_rn(a, b);
    return *reinterpret_cast<uint32_t*>(&p);
}
__device__ __forceinline__ float bflo(float v) {
    return v - __bfloat162float(__float2bfloat16_rn(v));
}
__device__ __forceinline__ void cp16(uint32_t smem_addr, const void* gptr) {
    asm volatile("cp.async.cg.shared.global [%0], [%1], 16;"
                 :: "r"(smem_addr), "l"(gptr) : "memory");
}
#define CP_COMMIT() asm volatile("cp.async.commit_group;" ::: "memory")
#define CP_WAIT0()  asm volatile("cp.async.wait_group 0;" ::: "memory")

// ---------------- LayerNorm ----------------
__global__ void ln_kernel(const float* __restrict__ x,
                          const float* __restrict__ w,
                          const float* __restrict__ bvec) {
    int row = blockIdx.x, tid = threadIdx.x;
    float4 v = ((const float4*)(x + (size_t)row*DIM))[tid];
    float s  = v.x+v.y+v.z+v.w;
    float ss = v.x*v.x+v.y*v.y+v.z*v.z+v.w*v.w;
    #pragma unroll
    for (int o = 16; o > 0; o >>= 1) {
        s  += __shfl_xor_sync(~0u, s, o);
        ss += __shfl_xor_sync(~0u, ss, o);
    }
    __shared__ float rs[8], rss[8];
    int wid = tid >> 5, lane = tid & 31;
    if (lane == 0) { rs[wid] = s; rss[wid] = ss; }
    __syncthreads();
    s = 0.f; ss = 0.f;
    #pragma unroll
    for (int i = 0; i < 8; i++) { s += rs[i]; ss += rss[i]; }
    float mean = s*(1.f/DIM), var = ss*(1.f/DIM) - mean*mean;
    float rstd = rsqrtf(var + 1e-5f);
    float4 wv = ((const float4*)w)[tid], bv = ((const float4*)bvec)[tid];
    float4 o;
    o.x = (v.x-mean)*rstd*wv.x + bv.x;  o.y = (v.y-mean)*rstd*wv.y + bv.y;
    o.z = (v.z-mean)*rstd*wv.z + bv.z;  o.w = (v.w-mean)*rstd*wv.w + bv.w;
    ((float4*)(d_xnorm + (size_t)row*DIM))[tid] = o;
}

// ---------------- bf16x3 GEMM (validated R8) ----------------
#define GA_ST 20
#define GB_ST 136
#define GAH 0
#define GAL (128*GA_ST)
#define GBH (2*128*GA_ST)
#define GBL (2*128*GA_ST + 16*GB_ST)
#define GEMM_SMEM ((2*128*GA_ST + 2*16*GB_ST)*4)

template<int MODE>
__global__ __launch_bounds__(256, 1)
void gemm_ts(const float* __restrict__ x,
             const float* __restrict__ Wq, const float* __restrict__ Wk,
             const float* __restrict__ Wv, const float* __restrict__ Wo,
             const float* __restrict__ bo, float* __restrict__ outp) {
    extern __shared__ uint32_t smw[];
    int tid = threadIdx.x, lane = tid & 31;
    int warp = tid >> 5, warpM = warp >> 1, warpN = warp & 1;
    int z = (MODE == 0) ? (int)blockIdx.z : 3;
    int m0 = blockIdx.y*128, n0 = blockIdx.x*128;
    const float* A = (MODE == 0) ? ((z == 2) ? x : d_xnorm) : d_coll;
    const float* W = (MODE == 0) ? ((z == 0) ? Wq : (z == 1) ? Wk : Wv) : Wo;

    float c[2][8][4];
    #pragma unroll
    for (int mt = 0; mt < 2; mt++)
        #pragma unroll
        for (int nt = 0; nt < 8; nt++)
            #pragma unroll
            for (int i = 0; i < 4; i++) c[mt][nt][i] = 0.f;

    const float* Abase = A + (size_t)m0*DIM;
    const float* Wbase = W + n0;

    float4 pa[4], pb0[2], pb1[2];
    #pragma unroll
    for (int j = 0; j < 4; j++) {
        int idx = tid + 256*j;
        pa[j] = *(const float4*)(Abase + (size_t)(idx >> 3)*DIM + (idx & 7)*4);
    }
    #pragma unroll
    for (int j = 0; j < 2; j++) {
        int idx = tid + 256*j;
        int kp = idx >> 5, nq = (idx & 31)*4;
        pb0[j] = *(const float4*)(Wbase + (size_t)(2*kp)*DIM + nq);
        pb1[j] = *(const float4*)(Wbase + (size_t)(2*kp + 1)*DIM + nq);
    }

    for (int ch = 0; ch < DIM/32; ch++) {
        #pragma unroll
        for (int j = 0; j < 4; j++) {
            int idx = tid + 256*j;
            int r = idx >> 3, k4 = idx & 7;
            float4 v = pa[j];
            uint2 hh = make_uint2(bfpack2(v.x, v.y), bfpack2(v.z, v.w));
            uint2 ll = make_uint2(bfpack2(bflo(v.x), bflo(v.y)), bfpack2(bflo(v.z), bflo(v.w)));
            *(uint2*)&smw[GAH + r*GA_ST + k4*2] = hh;
            *(uint2*)&smw[GAL + r*GA_ST + k4*2] = ll;
        }
        #pragma unroll
        for (int j = 0; j < 2; j++) {
            int idx = tid + 256*j;
            int kp = idx >> 5, nq = (idx & 31)*4;
            float4 r0 = pb0[j], r1 = pb1[j];
            uint4 hh = make_uint4(bfpack2(r0.x, r1.x), bfpack2(r0.y, r1.y),
                                  bfpack2(r0.z, r1.z), bfpack2(r0.w, r1.w));
            uint4 ll = make_uint4(bfpack2(bflo(r0.x), bflo(r1.x)), bfpack2(bflo(r0.y), bflo(r1.y)),
                                  bfpack2(bflo(r0.z), bflo(r1.z)), bfpack2(bflo(r0.w), bflo(r1.w)));
            *(uint4*)&smw[GBH + kp*GB_ST + nq] = hh;
            *(uint4*)&smw[GBL + kp*GB_ST + nq] = ll;
        }
        __syncthreads();

        if (ch + 1 < DIM/32) {
            int k0n = (ch + 1)*32;
            #pragma unroll
            for (int j = 0; j < 4; j++) {
                int idx = tid + 256*j;
                pa[j] = *(const float4*)(Abase + (size_t)(idx >> 3)*DIM + k0n + (idx & 7)*4);
            }
            #pragma unroll
            for (int j = 0; j < 2; j++) {
                int idx = tid + 256*j;
                int kp = idx >> 5, nq = (idx & 31)*4;
                pb0[j] = *(const float4*)(Wbase + (size_t)(k0n + 2*kp)*DIM + nq);
                pb1[j] = *(const float4*)(Wbase + (size_t)(k0n + 2*kp + 1)*DIM + nq);
            }
        }

        #pragma unroll
        for (int k16 = 0; k16 < 2; k16++) {
            int cw = k16*8 + (lane & 3);
            uint32_t ah[2][4], al[2][4];
            #pragma unroll
            for (int mt = 0; mt < 2; mt++) {
                int rA = warpM*32 + mt*16 + (lane >> 2);
                ah[mt][0] = smw[GAH + rA*GA_ST + cw];
                ah[mt][1] = smw[GAH + (rA+8)*GA_ST + cw];
                ah[mt][2] = smw[GAH + rA*GA_ST + cw + 4];
                ah[mt][3] = smw[GAH + (rA+8)*GA_ST + cw + 4];
                al[mt][0] = smw[GAL + rA*GA_ST + cw];
                al[mt][1] = smw[GAL + (rA+8)*GA_ST + cw];
                al[mt][2] = smw[GAL + rA*GA_ST + cw + 4];
                al[mt][3] = smw[GAL + (rA+8)*GA_ST + cw + 4];
            }
            #pragma unroll
            for (int nt = 0; nt < 8; nt++) {
                int cB = warpN*64 + nt*8 + (lane >> 2);
                uint32_t bh[2] = { smw[GBH + cw*GB_ST + cB], smw[GBH + (cw+4)*GB_ST + cB] };
                uint32_t bl[2] = { smw[GBL + cw*GB_ST + cB], smw[GBL + (cw+4)*GB_ST + cB] };
                #pragma unroll
                for (int mt = 0; mt < 2; mt++) {
                    mma_bf16(c[mt][nt], ah[mt], bh);
                    mma_bf16(c[mt][nt], ah[mt], bl);
                    mma_bf16(c[mt][nt], al[mt], bh);
                }
            }
        }
        __syncthreads();
    }

    #pragma unroll
    for (int mt = 0; mt < 2; mt++) {
        #pragma unroll
        for (int nt = 0; nt < 8; nt++) {
            int row = m0 + warpM*32 + mt*16 + (lane >> 2);
            int col = n0 + warpN*64 + nt*8 + (lane & 3)*2;
            #pragma unroll
            for (int half = 0; half < 2; half++) {
                int r = row + half*8;
                float2 v = make_float2(c[mt][nt][half*2], c[mt][nt][half*2+1]);
                if (MODE == 0) {
                    float* dst = (z == 0) ? d_Q : (z == 1) ? d_K : d_V;
                    int b = r >> 11, t = r & 2047;
                    int h = col >> 6, dd = col & 63;
                    *(float2*)&dst[(((size_t)(b*HEADS + h))*TLEN + t)*HD + dd] = v;
                } else {
                    v.x += bo[col]; v.y += bo[col+1];
                    *(float2*)&outp[(size_t)r*DIM + col] = v;
                }
            }
        }
    }
}

// ------- L2 normalize + gates + bf16 hi/lo split (validated R7) --------------
__device__ __forceinline__ void bf_split(float v, __nv_bfloat16& h, __nv_bfloat16& l) {
    h = __float2bfloat16_rn(v);
    l = __float2bfloat16_rn(v - __bfloat162float(h));
}
__global__ void normgate_kernel(const float* __restrict__ gqv,
                                const float* __restrict__ gkv) {
    int r = (blockIdx.x*blockDim.x + threadIdx.x) >> 5;
    int lane = threadIdx.x & 31;
    if (r >= HROWS) return;
    const float* q = d_Q + (size_t)r*HD;
    const float* k = d_K + (size_t)r*HD;
    const float* v = d_V + (size_t)r*HD;

    float q0 = q[lane], q1 = q[lane+32];
    float ss = q0*q0 + q1*q1;
    #pragma unroll
    for (int o = 16; o > 0; o >>= 1) ss += __shfl_xor_sync(~0u, ss, o);
    float inv = 1.0f / fmaxf(sqrtf(ss), 1e-12f);
    q0 *= inv; q1 *= inv;
    __nv_bfloat16 h0, l0, h1, l1;
    bf_split(q0, h0, l0); bf_split(q1, h1, l1);
    d_Qh[(size_t)r*HD + lane] = h0;       d_Ql[(size_t)r*HD + lane] = l0;
    d_Qh[(size_t)r*HD + lane + 32] = h1;  d_Ql[(size_t)r*HD + lane + 32] = l1;
    float g = q0*gqv[lane] + q1*gqv[lane+32];
    #pragma unroll
    for (int o = 16; o > 0; o >>= 1) g += __shfl_xor_sync(~0u, g, o);
    if (lane == 0) d_gq[r] = g;

    float k0 = k[lane], k1 = k[lane+32];
    ss = k0*k0 + k1*k1;
    #pragma unroll
    for (int o = 16; o > 0; o >>= 1) ss += __shfl_xor_sync(~0u, ss, o);
    inv = 1.0f / fmaxf(sqrtf(ss), 1e-12f);
    k0 *= inv; k1 *= inv;
    bf_split(k0, h0, l0); bf_split(k1, h1, l1);
    d_Kh[(size_t)r*HD + lane] = h0;       d_Kl[(size_t)r*HD + lane] = l0;
    d_Kh[(size_t)r*HD + lane + 32] = h1;  d_Kl[(size_t)r*HD + lane + 32] = l1;
    float gk = k0*gkv[lane] + k1*gkv[lane+32];
    #pragma unroll
    for (int o = 16; o > 0; o >>= 1) gk += __shfl_xor_sync(~0u, gk, o);

    int head = r >> 11, sl = r & 2047;
    size_t vbase = (size_t)head*HD*TLEN;
    float v0 = v[lane]*gk, v1 = v[lane+32]*gk;
    bf_split(v0, h0, l0); bf_split(v1, h1, l1);
    d_Vth[vbase + (size_t)lane*TLEN + sl] = h0;
    d_Vtl[vbase + (size_t)lane*TLEN + sl] = l0;
    d_Vth[vbase + (size_t)(lane+32)*TLEN + sl] = h1;
    d_Vtl[vbase + (size_t)(lane+32)*TLEN + sl] = l1;
}

// --- bf16x3 attention: ldmatrix B-frags, reg P, cp.async 2-stage KV ----------
#define ST 36
#define WQH 0
#define WQL (128*ST)
#define KV0 (2*128*ST)
#define KVSTAGE (4*64*ST)
#define ATT_SMEM ((2*128*ST + 2*KVSTAGE)*4)   // 110592 B

__global__ __launch_bounds__(256, 2)
void attn_tc() {
    extern __shared__ uint32_t smw[];
    __shared__ float gqs[128];
    int tid = threadIdx.x, lane = tid & 31;
    int warp = tid >> 5;
    int h = blockIdx.y, b = blockIdx.z;
    int t0 = blockIdx.x * 128;
    int head = b*HEADS + h;
    size_t base = (size_t)head*TLEN;
    uint32_t smbase = (uint32_t)__cvta_generic_to_shared(smw);

    // ldmatrix x4 per-thread row/col selector (4 m8n8 matrices per op)
    int g = lane >> 3;
    int rowsel = (g >> 1)*8 + (lane & 7);
    int colsel = (g & 1)*4;

    // stage Q into smem
    {
        const uint4* qh = (const uint4*)(d_Qh + (base + t0)*HD);
        const uint4* ql = (const uint4*)(d_Ql + (base + t0)*HD);
        #pragma unroll
        for (int j = 0; j < 4; j++) {
            int e = tid + 256*j;
            int t = e >> 3, q4 = (e & 7)*4;
            *(uint4*)&smw[WQH + t*ST + q4] = qh[e];
            *(uint4*)&smw[WQL + t*ST + q4] = ql[e];
        }
    }
    if (tid < 128) gqs[tid] = d_gq[base + t0 + tid];

    // prologue: async-load KV stage 0
    const char* khg = (const char*)(d_Kh + base*HD);
    const char* klg = (const char*)(d_Kl + base*HD);
    const char* vhg = (const char*)(d_Vth + (size_t)head*HD*TLEN);
    const char* vlg = (const char*)(d_Vtl + (size_t)head*HD*TLEN);
    int e0 = tid, e1 = tid + 256;
    int rr0 = e0 >> 3, q40 = (e0 & 7), rr1 = e1 >> 3, q41 = (e1 & 7);
    uint32_t soff0 = (rr0*ST + q40*4)*4, soff1 = (rr1*ST + q41*4)*4;
    size_t voff0 = ((size_t)rr0*(TLEN/8) + q40)*16;
    size_t voff1 = ((size_t)rr1*(TLEN/8) + q41)*16;

    {
        uint32_t kvb = smbase + KV0*4;
        cp16(kvb + soff0, khg + (size_t)e0*16);
        cp16(kvb + soff1, khg + (size_t)e1*16);
        cp16(kvb + 64*ST*4 + soff0, klg + (size_t)e0*16);
        cp16(kvb + 64*ST*4 + soff1, klg + (size_t)e1*16);
        cp16(kvb + 2*64*ST*4 + soff0, vhg + voff0);
        cp16(kvb + 2*64*ST*4 + soff1, vhg + voff1);
        cp16(kvb + 3*64*ST*4 + soff0, vlg + voff0);
        cp16(kvb + 3*64*ST*4 + soff1, vlg + voff1);
        CP_COMMIT();
    }
    __syncthreads();

    // hoist Q fragments into registers
    int rA = warp*16 + (lane >> 2);
    uint32_t qfh[4][4], qfl[4][4];
    #pragma unroll
    for (int k16 = 0; k16 < 4; k16++) {
        int cw = k16*8 + (lane & 3);
        qfh[k16][0] = smw[WQH + rA*ST + cw];
        qfh[k16][1] = smw[WQH + (rA+8)*ST + cw];
        qfh[k16][2] = smw[WQH + rA*ST + cw + 4];
        qfh[k16][3] = smw[WQH + (rA+8)*ST + cw + 4];
        qfl[k16][0] = smw[WQL + rA*ST + cw];
        qfl[k16][1] = smw[WQL + (rA+8)*ST + cw];
        qfl[k16][2] = smw[WQL + rA*ST + cw + 4];
        qfl[k16][3] = smw[WQL + (rA+8)*ST + cw + 4];
    }

    float acc[8][4];
    #pragma unroll
    for (int nt = 0; nt < 8; nt++)
        #pragma unroll
        for (int i = 0; i < 4; i++) acc[nt][i] = 0.f;

    const float ZOFF = -THRESH * SHARP;

    for (int it = 0; it < TLEN/64; it++) {
        CP_WAIT0();
        __syncthreads();

        if (it + 1 < TLEN/64) {
            size_t s0n = (size_t)(it + 1)*64;
            uint32_t kvb = smbase + (KV0 + ((it+1)&1)*KVSTAGE)*4;
            size_t koff = s0n*HD*2;
            cp16(kvb + soff0, khg + koff + (size_t)e0*16);
            cp16(kvb + soff1, khg + koff + (size_t)e1*16);
            cp16(kvb + 64*ST*4 + soff0, klg + koff + (size_t)e0*16);
            cp16(kvb + 64*ST*4 + soff1, klg + koff + (size_t)e1*16);
            size_t vcoff = s0n*2;
            cp16(kvb + 2*64*ST*4 + soff0, vhg + vcoff + voff0);
            cp16(kvb + 2*64*ST*4 + soff1, vhg + vcoff + voff1);
            cp16(kvb + 3*64*ST*4 + soff0, vlg + vcoff + voff0);
            cp16(kvb + 3*64*ST*4 + soff1, vlg + vcoff + voff1);
            CP_COMMIT();
        }

        int kvw = KV0 + (it & 1)*KVSTAGE;
        uint32_t KHb = smbase + kvw*4;
        uint32_t KLb = KHb + 64*ST*4;
        uint32_t VHb = KHb + 2*64*ST*4;
        uint32_t VLb = KHb + 3*64*ST*4;

        // QK^T: per-warp 16t x 64s, B frags via ldmatrix.x4 (2 nt per op)
        float c[8][4];
        #pragma unroll
        for (int nt = 0; nt < 8; nt++)
            #pragma unroll
            for (int i = 0; i < 4; i++) c[nt][i] = 0.f;

        #pragma unroll
        for (int k16 = 0; k16 < 4; k16++) {
            #pragma unroll
            for (int ntp = 0; ntp < 4; ntp++) {
                uint32_t aoff = ((ntp*16 + rowsel)*ST + k16*8 + colsel)*4;
                uint32_t bh[4], bl[4];
                ldsm4(bh, KHb + aoff);
                ldsm4(bl, KLb + aoff);
                mma_bf16(c[2*ntp],   qfh[k16], bh);
                mma_bf16(c[2*ntp],   qfh[k16], bl);
                mma_bf16(c[2*ntp],   qfl[k16], bh);
                mma_bf16(c[2*ntp+1], qfh[k16], bh + 2);
                mma_bf16(c[2*ntp+1], qfh[k16], bl + 2);
                mma_bf16(c[2*ntp+1], qfl[k16], bh + 2);
            }
        }

        // sigmoid + hi/lo pack in registers
        uint32_t ph[8][2], pl[8][2];
        #pragma unroll
        for (int nt = 0; nt < 8; nt++)
            #pragma unroll
            for (int half = 0; half < 2; half++) {
                float z0 = fmaf(c[nt][half*2],   SHARP, ZOFF);
                float z1 = fmaf(c[nt][half*2+1], SHARP, ZOFF);
                float p0 = __fdividef(1.0f, 1.0f + __expf(-z0));
                float p1 = __fdividef(1.0f, 1.0f + __expf(-z1));
                ph[nt][half] = bfpack2(p0, p1);
                pl[nt][half] = bfpack2(bflo(p0), bflo(p1));
            }

        // P @ V: per-warp 16t x 64d, A from regs, B via ldmatrix.x4
        #pragma unroll
        for (int k16 = 0; k16 < 4; k16++) {
            uint32_t ah[4] = { ph[2*k16][0], ph[2*k16][1], ph[2*k16+1][0], ph[2*k16+1][1] };
            uint32_t al[4] = { pl[2*k16][0], pl[2*k16][1], pl[2*k16+1][0], pl[2*k16+1][1] };
            #pragma unroll
            for (int ntp = 0; ntp < 4; ntp++) {
                uint32_t aoff = ((ntp*16 + rowsel)*ST + k16*8 + colsel)*4;
                uint32_t bh[4], bl[4];
                ldsm4(bh, VHb + aoff);
                ldsm4(bl, VLb + aoff);
                mma_bf16(acc[2*ntp],   ah, bh);
                mma_bf16(acc[2*ntp],   ah, bl);
                mma_bf16(acc[2*ntp],   al, bh);
                mma_bf16(acc[2*ntp+1], ah, bh + 2);
                mma_bf16(acc[2*ntp+1], ah, bl + 2);
                mma_bf16(acc[2*ntp+1], al, bh + 2);
            }
        }
    }

    // epilogue: * gq -> d_coll[b][t][h*64+d]
    float* Cb = d_coll + ((size_t)(b*TLEN) + t0)*DIM + h*HD;
    #pragma unroll
    for (int nt = 0; nt < 8; nt++)
        #pragma unroll
        for (int half = 0; half < 2; half++) {
            int row = warp*16 + (lane >> 2) + half*8;
            int col = nt*8 + (lane & 3)*2;
            float g2 = gqs[row];
            float2 v = make_float2(acc[nt][half*2]*g2, acc[nt][half*2+1]*g2);
            *(float2*)&Cb[(size_t)row*DIM + col] = v;
        }
}

// ---------------- launch ------------------------------------------------------
extern "C" void kernel_launch(void* const* d_in, const int* in_sizes, int n_in,
                              void* d_out, int out_size) {
    const float* x   = (const float*)d_in[0];
    const float* Wq  = (const float*)d_in[1];
    const float* Wk  = (const float*)d_in[2];
    const float* Wv  = (const float*)d_in[3];
    const float* gqv = (const float*)d_in[4];
    const float* gkv = (const float*)d_in[5];
    const float* Wo  = (const float*)d_in[6];
    const float* bo  = (const float*)d_in[7];
    const float* lnw = (const float*)d_in[8];
    const float* lnb = (const float*)d_in[9];
    float* out = (float*)d_out;

    cudaFuncSetAttribute(attn_tc, cudaFuncAttributeMaxDynamicSharedMemorySize, ATT_SMEM);
    cudaFuncSetAttribute(gemm_ts<0>, cudaFuncAttributeMaxDynamicSharedMemorySize, GEMM_SMEM);
    cudaFuncSetAttribute(gemm_ts<1>, cudaFuncAttributeMaxDynamicSharedMemorySize, GEMM_SMEM);

    ln_kernel<<<ROWS, 256>>>(x, lnw, lnb);
    gemm_ts<0><<<dim3(8, 32, 3), 256, GEMM_SMEM>>>(x, Wq, Wk, Wv, Wo, bo, nullptr);
    normgate_kernel<<<HROWS*32/256, 256>>>(gqv, gkv);
    attn_tc<<<dim3(TLEN/128, HEADS, BATCH), 256, ATT_SMEM>>>();
    gemm_ts<1><<<dim3(8, 32), 256, GEMM_SMEM>>>(nullptr, Wq, Wk, Wv, Wo, bo, out);
}

// round 13
// speedup vs baseline: 4.2628x; 1.0076x over previous
#include <cuda_runtime.h>
#include <cuda_bf16.h>
#include <cstdint>
#include <math.h>

#define DIM    1024
#define BATCH  2
#define TLEN   2048
#define HEADS  16
#define HD     64
#define ROWS   (BATCH*TLEN)
#define HROWS  (BATCH*HEADS*TLEN)
#define THRESH 0.29514f
#define SHARP  15.0f

__device__ float d_Q[HROWS*HD];
__device__ float d_K[HROWS*HD];
__device__ float d_V[HROWS*HD];
__device__ float d_gq[HROWS];
// attention operands (bf16 hi/lo, MMA-native layouts)
__device__ __align__(16) __nv_bfloat16 d_Qh[HROWS*HD];
__device__ __align__(16) __nv_bfloat16 d_Ql[HROWS*HD];
__device__ __align__(16) __nv_bfloat16 d_Kh[HROWS*HD];
__device__ __align__(16) __nv_bfloat16 d_Kl[HROWS*HD];
__device__ __align__(16) __nv_bfloat16 d_Vth[HROWS*HD];  // [b,h][d][s]
__device__ __align__(16) __nv_bfloat16 d_Vtl[HROWS*HD];
// GEMM operands (bf16 hi/lo): weights transposed to [n][k]
__device__ __align__(16) __nv_bfloat16 d_Wth[4][DIM*DIM];
__device__ __align__(16) __nv_bfloat16 d_Wtl[4][DIM*DIM];
__device__ __align__(16) __nv_bfloat16 d_Xnh[ROWS*DIM];  // layernorm(x)
__device__ __align__(16) __nv_bfloat16 d_Xnl[ROWS*DIM];
__device__ __align__(16) __nv_bfloat16 d_Xh[ROWS*DIM];   // raw x
__device__ __align__(16) __nv_bfloat16 d_Xl[ROWS*DIM];
__device__ __align__(16) __nv_bfloat16 d_Ch[ROWS*DIM];   // collapse
__device__ __align__(16) __nv_bfloat16 d_Cl[ROWS*DIM];

// ---------------- mma.sync / helpers ----------------
__device__ __forceinline__ void mma_bf16(float* c, const uint32_t* a, const uint32_t* b) {
    asm volatile(
        "mma.sync.aligned.m16n8k16.row.col.f32.bf16.bf16.f32 "
        "{%0,%1,%2,%3}, {%4,%5,%6,%7}, {%8,%9}, {%0,%1,%2,%3};"
        : "+f"(c[0]), "+f"(c[1]), "+f"(c[2]), "+f"(c[3])
        : "r"(a[0]), "r"(a[1]), "r"(a[2]), "r"(a[3]), "r"(b[0]), "r"(b[1]));
}
__device__ __forceinline__ void ldsm4(uint32_t* r, uint32_t addr) {
    asm volatile("ldmatrix.sync.aligned.m8n8.x4.shared.b16 {%0,%1,%2,%3}, [%4];"
                 : "=r"(r[0]), "=r"(r[1]), "=r"(r[2]), "=r"(r[3]) : "r"(addr));
}
__device__ __forceinline__ uint32_t bfpack2(float a, float b) {
    __nv_bfloat162 p = __floats2bfloat162_rn(a, b);
    return *reinterpret_cast<uint32_t*>(&p);
}
__device__ __forceinline__ float bflo(float v) {
    return v - __bfloat162float(__float2bfloat16_rn(v));
}
__device__ __forceinline__ void bf_split(float v, __nv_bfloat16& h, __nv_bfloat16& l) {
    h = __float2bfloat16_rn(v);
    l = __float2bfloat16_rn(v - __bfloat162float(h));
}
__device__ __forceinline__ void cp16(uint32_t smem_addr, const void* gptr) {
    asm volatile("cp.async.cg.shared.global [%0], [%1], 16;"
                 :: "r"(smem_addr), "l"(gptr) : "memory");
}
#define CP_COMMIT() asm volatile("cp.async.commit_group;" ::: "memory")
#define CP_WAIT0()  asm volatile("cp.async.wait_group 0;" ::: "memory")

// ---------------- LayerNorm (+ bf16 hi/lo split of xnorm) --------------------
__global__ void ln_kernel(const float* __restrict__ x,
                          const float* __restrict__ w,
                          const float* __restrict__ bvec) {
    int row = blockIdx.x, tid = threadIdx.x;
    float4 v = ((const float4*)(x + (size_t)row*DIM))[tid];
    float s  = v.x+v.y+v.z+v.w;
    float ss = v.x*v.x+v.y*v.y+v.z*v.z+v.w*v.w;
    #pragma unroll
    for (int o = 16; o > 0; o >>= 1) {
        s  += __shfl_xor_sync(~0u, s, o);
        ss += __shfl_xor_sync(~0u, ss, o);
    }
    __shared__ float rs[8], rss[8];
    int wid = tid >> 5, lane = tid & 31;
    if (lane == 0) { rs[wid] = s; rss[wid] = ss; }
    __syncthreads();
    s = 0.f; ss = 0.f;
    #pragma unroll
    for (int i = 0; i < 8; i++) { s += rs[i]; ss += rss[i]; }
    float mean = s*(1.f/DIM), var = ss*(1.f/DIM) - mean*mean;
    float rstd = rsqrtf(var + 1e-5f);
    float4 wv = ((const float4*)w)[tid], bv = ((const float4*)bvec)[tid];
    float4 o;
    o.x = (v.x-mean)*rstd*wv.x + bv.x;  o.y = (v.y-mean)*rstd*wv.y + bv.y;
    o.z = (v.z-mean)*rstd*wv.z + bv.z;  o.w = (v.w-mean)*rstd*wv.w + bv.w;
    uint2 hw = make_uint2(bfpack2(o.x, o.y), bfpack2(o.z, o.w));
    uint2 lw = make_uint2(bfpack2(bflo(o.x), bflo(o.y)), bfpack2(bflo(o.z), bflo(o.w)));
    *(uint2*)&d_Xnh[(size_t)row*DIM + tid*4] = hw;
    *(uint2*)&d_Xnl[(size_t)row*DIM + tid*4] = lw;
}

// ---------------- split x into bf16 hi/lo ----------------
__global__ void split_x(const float* __restrict__ x) {
    int i = (blockIdx.x*256 + threadIdx.x)*4;
    float4 v = *(const float4*)(x + i);
    *(uint2*)&d_Xh[i] = make_uint2(bfpack2(v.x, v.y), bfpack2(v.z, v.w));
    *(uint2*)&d_Xl[i] = make_uint2(bfpack2(bflo(v.x), bflo(v.y)), bfpack2(bflo(v.z), bflo(v.w)));
}

// ---------------- weight transpose + split: Wt[z][n][k] ----------------------
__global__ void wsplit(const float* __restrict__ Wq, const float* __restrict__ Wk,
                       const float* __restrict__ Wv, const float* __restrict__ Wo) {
    __shared__ float tile[32][33];
    int z = blockIdx.z;
    const float* W = (z==0) ? Wq : (z==1) ? Wk : (z==2) ? Wv : Wo;
    int n0 = blockIdx.x*32, k0 = blockIdx.y*32;
    int tx = threadIdx.x, ty = threadIdx.y;
    #pragma unroll
    for (int i = 0; i < 4; i++)
        tile[ty+8*i][tx] = W[(size_t)(k0+ty+8*i)*DIM + n0 + tx];
    __syncthreads();
    #pragma unroll
    for (int i = 0; i < 4; i++) {
        float v = tile[tx][ty+8*i];
        __nv_bfloat16 h, l;
        bf_split(v, h, l);
        d_Wth[z][(size_t)(n0+ty+8*i)*DIM + k0 + tx] = h;
        d_Wtl[z][(size_t)(n0+ty+8*i)*DIM + k0 + tx] = l;
    }
}

// -------- bf16x3 GEMM: pre-split operands, cp.async 2-stage, ldmatrix --------
// smem word layout per stage: AH[128][20] | AL | BH[128][20] | BL
#define GT_ST 20
#define TILEW (128*GT_ST)
#define SSTAGE (4*TILEW)
#define GEMM_SMEM (2*SSTAGE*4)   // 81920 B

template<int MODE>   // 0: QKV (z = blockIdx.z), 1: out = coll@Wo + bo
__global__ __launch_bounds__(256, 2)
void gemm_ts(const float* __restrict__ bo, float* __restrict__ outp) {
    extern __shared__ uint32_t smw[];
    int tid = threadIdx.x, lane = tid & 31;
    int warp = tid >> 5, warpM = warp >> 1, warpN = warp & 1;
    int z = (MODE == 0) ? (int)blockIdx.z : 3;
    int m0 = blockIdx.y*128, n0 = blockIdx.x*128;
    const __nv_bfloat16* Agh = (MODE == 0) ? ((z == 2) ? d_Xh : d_Xnh) : d_Ch;
    const __nv_bfloat16* Agl = (MODE == 0) ? ((z == 2) ? d_Xl : d_Xnl) : d_Cl;
    const __nv_bfloat16* Bgh = d_Wth[z];
    const __nv_bfloat16* Bgl = d_Wtl[z];
    uint32_t smbase = (uint32_t)__cvta_generic_to_shared(smw);

    int g = lane >> 3;
    int rowsel = (g >> 1)*8 + (lane & 7);
    int colsel = (g & 1)*4;

    float c[2][8][4];
    #pragma unroll
    for (int mt = 0; mt < 2; mt++)
        #pragma unroll
        for (int nt = 0; nt < 8; nt++)
            #pragma unroll
            for (int i = 0; i < 4; i++) c[mt][nt][i] = 0.f;

    // cp.async indexing: (row, 16B-seg); 128 rows x 4 segs, 2 iters x 256 thr
    int e0 = tid, e1 = tid + 256;
    int r0i = e0 >> 2, s0i = e0 & 3, r1i = e1 >> 2, s1i = e1 & 3;
    uint32_t w0 = (r0i*GT_ST + s0i*4)*4, w1 = (r1i*GT_ST + s1i*4)*4;
    size_t a0g = (size_t)(m0 + r0i)*DIM + s0i*8, a1g = (size_t)(m0 + r1i)*DIM + s1i*8;
    size_t b0g = (size_t)(n0 + r0i)*DIM + s0i*8, b1g = (size_t)(n0 + r1i)*DIM + s1i*8;

    // prologue: stage 0 (k0 = 0)
    {
        uint32_t sb = smbase;
        cp16(sb + w0, Agh + a0g);                 cp16(sb + w1, Agh + a1g);
        cp16(sb + TILEW*4 + w0, Agl + a0g);       cp16(sb + TILEW*4 + w1, Agl + a1g);
        cp16(sb + 2*TILEW*4 + w0, Bgh + b0g);     cp16(sb + 2*TILEW*4 + w1, Bgh + b1g);
        cp16(sb + 3*TILEW*4 + w0, Bgl + b0g);     cp16(sb + 3*TILEW*4 + w1, Bgl + b1g);
        CP_COMMIT();
    }

    for (int ch = 0; ch < DIM/32; ch++) {
        CP_WAIT0();
        __syncthreads();

        if (ch + 1 < DIM/32) {
            int k0 = (ch + 1)*32;
            uint32_t sb = smbase + ((ch + 1) & 1)*SSTAGE*4;
            cp16(sb + w0, Agh + a0g + k0);             cp16(sb + w1, Agh + a1g + k0);
            cp16(sb + TILEW*4 + w0, Agl + a0g + k0);   cp16(sb + TILEW*4 + w1, Agl + a1g + k0);
            cp16(sb + 2*TILEW*4 + w0, Bgh + b0g + k0); cp16(sb + 2*TILEW*4 + w1, Bgh + b1g + k0);
            cp16(sb + 3*TILEW*4 + w0, Bgl + b0g + k0); cp16(sb + 3*TILEW*4 + w1, Bgl + b1g + k0);
            CP_COMMIT();
        }

        uint32_t st = smbase + (ch & 1)*SSTAGE*4;
        uint32_t AHb = st, ALb = st + TILEW*4, BHb = st + 2*TILEW*4, BLb = st + 3*TILEW*4;

        #pragma unroll
        for (int k16 = 0; k16 < 2; k16++) {
            uint32_t koff = (k16*8 + colsel)*4;
            uint32_t ah[2][4], al[2][4];
            #pragma unroll
            for (int mt = 0; mt < 2; mt++) {
                uint32_t aoff = ((warpM*32 + mt*16 + rowsel)*GT_ST)*4 + koff;
                uint32_t t4[4];
                ldsm4(t4, AHb + aoff);
                ah[mt][0] = t4[0]; ah[mt][1] = t4[2]; ah[mt][2] = t4[1]; ah[mt][3] = t4[3];
                ldsm4(t4, ALb + aoff);
                al[mt][0] = t4[0]; al[mt][1] = t4[2]; al[mt][2] = t4[1]; al[mt][3] = t4[3];
            }
            #pragma unroll
            for (int ntp = 0; ntp < 4; ntp++) {
                uint32_t boff = ((warpN*64 + ntp*16 + rowsel)*GT_ST)*4 + koff;
                uint32_t bh[4], bl[4];
                ldsm4(bh, BHb + boff);
                ldsm4(bl, BLb + boff);
                #pragma unroll
                for (int mt = 0; mt < 2; mt++) {
                    mma_bf16(c[mt][2*ntp],   ah[mt], bh);
                    mma_bf16(c[mt][2*ntp],   ah[mt], bl);
                    mma_bf16(c[mt][2*ntp],   al[mt], bh);
                    mma_bf16(c[mt][2*ntp+1], ah[mt], bh + 2);
                    mma_bf16(c[mt][2*ntp+1], ah[mt], bl + 2);
                    mma_bf16(c[mt][2*ntp+1], al[mt], bh + 2);
                }
            }
        }
        __syncthreads();
    }

    #pragma unroll
    for (int mt = 0; mt < 2; mt++) {
        #pragma unroll
        for (int nt = 0; nt < 8; nt++) {
            int row = m0 + warpM*32 + mt*16 + (lane >> 2);
            int col = n0 + warpN*64 + nt*8 + (lane & 3)*2;
            #pragma unroll
            for (int half = 0; half < 2; half++) {
                int r = row + half*8;
                float2 v = make_float2(c[mt][nt][half*2], c[mt][nt][half*2+1]);
                if (MODE == 0) {
                    float* dst = (z == 0) ? d_Q : (z == 1) ? d_K : d_V;
                    int b = r >> 11, t = r & 2047;
                    int h = col >> 6, dd = col & 63;
                    *(float2*)&dst[(((size_t)(b*HEADS + h))*TLEN + t)*HD + dd] = v;
                } else {
                    v.x += bo[col]; v.y += bo[col+1];
                    *(float2*)&outp[(size_t)r*DIM + col] = v;
                }
            }
        }
    }
}

// ------- L2 normalize + gates + bf16 hi/lo split (validated R7) --------------
__global__ void normgate_kernel(const float* __restrict__ gqv,
                                const float* __restrict__ gkv) {
    int r = (blockIdx.x*blockDim.x + threadIdx.x) >> 5;
    int lane = threadIdx.x & 31;
    if (r >= HROWS) return;
    const float* q = d_Q + (size_t)r*HD;
    const float* k = d_K + (size_t)r*HD;
    const float* v = d_V + (size_t)r*HD;

    float q0 = q[lane], q1 = q[lane+32];
    float ss = q0*q0 + q1*q1;
    #pragma unroll
    for (int o = 16; o > 0; o >>= 1) ss += __shfl_xor_sync(~0u, ss, o);
    float inv = 1.0f / fmaxf(sqrtf(ss), 1e-12f);
    q0 *= inv; q1 *= inv;
    __nv_bfloat16 h0, l0, h1, l1;
    bf_split(q0, h0, l0); bf_split(q1, h1, l1);
    d_Qh[(size_t)r*HD + lane] = h0;       d_Ql[(size_t)r*HD + lane] = l0;
    d_Qh[(size_t)r*HD + lane + 32] = h1;  d_Ql[(size_t)r*HD + lane + 32] = l1;
    float g = q0*gqv[lane] + q1*gqv[lane+32];
    #pragma unroll
    for (int o = 16; o > 0; o >>= 1) g += __shfl_xor_sync(~0u, g, o);
    if (lane == 0) d_gq[r] = g;

    float k0 = k[lane], k1 = k[lane+32];
    ss = k0*k0 + k1*k1;
    #pragma unroll
    for (int o = 16; o > 0; o >>= 1) ss += __shfl_xor_sync(~0u, ss, o);
    inv = 1.0f / fmaxf(sqrtf(ss), 1e-12f);
    k0 *= inv; k1 *= inv;
    bf_split(k0, h0, l0); bf_split(k1, h1, l1);
    d_Kh[(size_t)r*HD + lane] = h0;       d_Kl[(size_t)r*HD + lane] = l0;
    d_Kh[(size_t)r*HD + lane + 32] = h1;  d_Kl[(size_t)r*HD + lane + 32] = l1;
    float gk = k0*gkv[lane] + k1*gkv[lane+32];
    #pragma unroll
    for (int o = 16; o > 0; o >>= 1) gk += __shfl_xor_sync(~0u, gk, o);

    int head = r >> 11, sl = r & 2047;
    size_t vbase = (size_t)head*HD*TLEN;
    float v0 = v[lane]*gk, v1 = v[lane+32]*gk;
    bf_split(v0, h0, l0); bf_split(v1, h1, l1);
    d_Vth[vbase + (size_t)lane*TLEN + sl] = h0;
    d_Vtl[vbase + (size_t)lane*TLEN + sl] = l0;
    d_Vth[vbase + (size_t)(lane+32)*TLEN + sl] = h1;
    d_Vtl[vbase + (size_t)(lane+32)*TLEN + sl] = l1;
}

// --- bf16x3 attention (validated R12), epilogue writes coll bf16 hi/lo -------
#define ST 36
#define WQH 0
#define WQL (128*ST)
#define KV0 (2*128*ST)
#define KVSTAGE (4*64*ST)
#define ATT_SMEM ((2*128*ST + 2*KVSTAGE)*4)

__global__ __launch_bounds__(256, 2)
void attn_tc() {
    extern __shared__ uint32_t smw[];
    __shared__ float gqs[128];
    int tid = threadIdx.x, lane = tid & 31;
    int warp = tid >> 5;
    int h = blockIdx.y, b = blockIdx.z;
    int t0 = blockIdx.x * 128;
    int head = b*HEADS + h;
    size_t base = (size_t)head*TLEN;
    uint32_t smbase = (uint32_t)__cvta_generic_to_shared(smw);

    int g = lane >> 3;
    int rowsel = (g >> 1)*8 + (lane & 7);
    int colsel = (g & 1)*4;

    {
        const uint4* qh = (const uint4*)(d_Qh + (base + t0)*HD);
        const uint4* ql = (const uint4*)(d_Ql + (base + t0)*HD);
        #pragma unroll
        for (int j = 0; j < 4; j++) {
            int e = tid + 256*j;
            int t = e >> 3, q4 = (e & 7)*4;
            *(uint4*)&smw[WQH + t*ST + q4] = qh[e];
            *(uint4*)&smw[WQL + t*ST + q4] = ql[e];
        }
    }
    if (tid < 128) gqs[tid] = d_gq[base + t0 + tid];

    const char* khg = (const char*)(d_Kh + base*HD);
    const char* klg = (const char*)(d_Kl + base*HD);
    const char* vhg = (const char*)(d_Vth + (size_t)head*HD*TLEN);
    const char* vlg = (const char*)(d_Vtl + (size_t)head*HD*TLEN);
    int e0 = tid, e1 = tid + 256;
    int rr0 = e0 >> 3, q40 = (e0 & 7), rr1 = e1 >> 3, q41 = (e1 & 7);
    uint32_t soff0 = (rr0*ST + q40*4)*4, soff1 = (rr1*ST + q41*4)*4;
    size_t voff0 = ((size_t)rr0*(TLEN/8) + q40)*16;
    size_t voff1 = ((size_t)rr1*(TLEN/8) + q41)*16;

    {
        uint32_t kvb = smbase + KV0*4;
        cp16(kvb + soff0, khg + (size_t)e0*16);
        cp16(kvb + soff1, khg + (size_t)e1*16);
        cp16(kvb + 64*ST*4 + soff0, klg + (size_t)e0*16);
        cp16(kvb + 64*ST*4 + soff1, klg + (size_t)e1*16);
        cp16(kvb + 2*64*ST*4 + soff0, vhg + voff0);
        cp16(kvb + 2*64*ST*4 + soff1, vhg + voff1);
        cp16(kvb + 3*64*ST*4 + soff0, vlg + voff0);
        cp16(kvb + 3*64*ST*4 + soff1, vlg + voff1);
        CP_COMMIT();
    }
    __syncthreads();

    int rA = warp*16 + (lane >> 2);
    uint32_t qfh[4][4], qfl[4][4];
    #pragma unroll
    for (int k16 = 0; k16 < 4; k16++) {
        int cw = k16*8 + (lane & 3);
        qfh[k16][0] = smw[WQH + rA*ST + cw];
        qfh[k16][1] = smw[WQH + (rA+8)*ST + cw];
        qfh[k16][2] = smw[WQH + rA*ST + cw + 4];
        qfh[k16][3] = smw[WQH + (rA+8)*ST + cw + 4];
        qfl[k16][0] = smw[WQL + rA*ST + cw];
        qfl[k16][1] = smw[WQL + (rA+8)*ST + cw];
        qfl[k16][2] = smw[WQL + rA*ST + cw + 4];
        qfl[k16][3] = smw[WQL + (rA+8)*ST + cw + 4];
    }

    float acc[8][4];
    #pragma unroll
    for (int nt = 0; nt < 8; nt++)
        #pragma unroll
        for (int i = 0; i < 4; i++) acc[nt][i] = 0.f;

    const float ZOFF = -THRESH * SHARP;

    for (int it = 0; it < TLEN/64; it++) {
        CP_WAIT0();
        __syncthreads();

        if (it + 1 < TLEN/64) {
            size_t s0n = (size_t)(it + 1)*64;
            uint32_t kvb = smbase + (KV0 + ((it+1)&1)*KVSTAGE)*4;
            size_t koff = s0n*HD*2;
            cp16(kvb + soff0, khg + koff + (size_t)e0*16);
            cp16(kvb + soff1, khg + koff + (size_t)e1*16);
            cp16(kvb + 64*ST*4 + soff0, klg + koff + (size_t)e0*16);
            cp16(kvb + 64*ST*4 + soff1, klg + koff + (size_t)e1*16);
            size_t vcoff = s0n*2;
            cp16(kvb + 2*64*ST*4 + soff0, vhg + vcoff + voff0);
            cp16(kvb + 2*64*ST*4 + soff1, vhg + vcoff + voff1);
            cp16(kvb + 3*64*ST*4 + soff0, vlg + vcoff + voff0);
            cp16(kvb + 3*64*ST*4 + soff1, vlg + vcoff + voff1);
            CP_COMMIT();
        }

        int kvw = KV0 + (it & 1)*KVSTAGE;
        uint32_t KHb = smbase + kvw*4;
        uint32_t KLb = KHb + 64*ST*4;
        uint32_t VHb = KHb + 2*64*ST*4;
        uint32_t VLb = KHb + 3*64*ST*4;

        float c[8][4];
        #pragma unroll
        for (int nt = 0; nt < 8; nt++)
            #pragma unroll
            for (int i = 0; i < 4; i++) c[nt][i] = 0.f;

        #pragma unroll
        for (int k16 = 0; k16 < 4; k16++) {
            #pragma unroll
            for (int ntp = 0; ntp < 4; ntp++) {
                uint32_t aoff = ((ntp*16 + rowsel)*ST + k16*8 + colsel)*4;
                uint32_t bh[4], bl[4];
                ldsm4(bh, KHb + aoff);
                ldsm4(bl, KLb + aoff);
                mma_bf16(c[2*ntp],   qfh[k16], bh);
                mma_bf16(c[2*ntp],   qfh[k16], bl);
                mma_bf16(c[2*ntp],   qfl[k16], bh);
                mma_bf16(c[2*ntp+1], qfh[k16], bh + 2);
                mma_bf16(c[2*ntp+1], qfh[k16], bl + 2);
                mma_bf16(c[2*ntp+1], qfl[k16], bh + 2);
            }
        }

        uint32_t ph[8][2], pl[8][2];
        #pragma unroll
        for (int nt = 0; nt < 8; nt++)
            #pragma unroll
            for (int half = 0; half < 2; half++) {
                float z0 = fmaf(c[nt][half*2],   SHARP, ZOFF);
                float z1 = fmaf(c[nt][half*2+1], SHARP, ZOFF);
                float p0 = __fdividef(1.0f, 1.0f + __expf(-z0));
                float p1 = __fdividef(1.0f, 1.0f + __expf(-z1));
                ph[nt][half] = bfpack2(p0, p1);
                pl[nt][half] = bfpack2(bflo(p0), bflo(p1));
            }

        #pragma unroll
        for (int k16 = 0; k16 < 4; k16++) {
            uint32_t ah[4] = { ph[2*k16][0], ph[2*k16][1], ph[2*k16+1][0], ph[2*k16+1][1] };
            uint32_t al[4] = { pl[2*k16][0], pl[2*k16][1], pl[2*k16+1][0], pl[2*k16+1][1] };
            #pragma unroll
            for (int ntp = 0; ntp < 4; ntp++) {
                uint32_t aoff = ((ntp*16 + rowsel)*ST + k16*8 + colsel)*4;
                uint32_t bh[4], bl[4];
                ldsm4(bh, VHb + aoff);
                ldsm4(bl, VLb + aoff);
                mma_bf16(acc[2*ntp],   ah, bh);
                mma_bf16(acc[2*ntp],   ah, bl);
                mma_bf16(acc[2*ntp],   al, bh);
                mma_bf16(acc[2*ntp+1], ah, bh + 2);
                mma_bf16(acc[2*ntp+1], ah, bl + 2);
                mma_bf16(acc[2*ntp+1], al, bh + 2);
            }
        }
    }

    // epilogue: * gq -> collapse bf16 hi/lo at [b][t][h*64+d]
    size_t cb = ((size_t)(b*TLEN) + t0)*DIM + h*HD;
    #pragma unroll
    for (int nt = 0; nt < 8; nt++)
        #pragma unroll
        for (int half = 0; half < 2; half++) {
            int row = warp*16 + (lane >> 2) + half*8;
            int col = nt*8 + (lane & 3)*2;
            float g2 = gqs[row];
            float v0 = acc[nt][half*2]*g2, v1 = acc[nt][half*2+1]*g2;
            size_t off = cb + (size_t)row*DIM + col;
            *(uint32_t*)&d_Ch[off] = bfpack2(v0, v1);
            *(uint32_t*)&d_Cl[off] = bfpack2(bflo(v0), bflo(v1));
        }
}

// ---------------- launch ------------------------------------------------------
extern "C" void kernel_launch(void* const* d_in, const int* in_sizes, int n_in,
                              void* d_out, int out_size) {
    const float* x   = (const float*)d_in[0];
    const float* Wq  = (const float*)d_in[1];
    const float* Wk  = (const float*)d_in[2];
    const float* Wv  = (const float*)d_in[3];
    const float* gqv = (const float*)d_in[4];
    const float* gkv = (const float*)d_in[5];
    const float* Wo  = (const float*)d_in[6];
    const float* bo  = (const float*)d_in[7];
    const float* lnw = (const float*)d_in[8];
    const float* lnb = (const float*)d_in[9];
    float* out = (float*)d_out;

    cudaFuncSetAttribute(attn_tc, cudaFuncAttributeMaxDynamicSharedMemorySize, ATT_SMEM);
    cudaFuncSetAttribute(gemm_ts<0>, cudaFuncAttributeMaxDynamicSharedMemorySize, GEMM_SMEM);
    cudaFuncSetAttribute(gemm_ts<1>, cudaFuncAttributeMaxDynamicSharedMemorySize, GEMM_SMEM);

    ln_kernel<<<ROWS, 256>>>(x, lnw, lnb);
    split_x<<<ROWS*DIM/1024, 256>>>(x);
    wsplit<<<dim3(32, 32, 4), dim3(32, 8)>>>(Wq, Wk, Wv, Wo);
    gemm_ts<0><<<dim3(8, 32, 3), 256, GEMM_SMEM>>>(nullptr, nullptr);
    normgate_kernel<<<HROWS*32/256, 256>>>(gqv, gkv);
    attn_tc<<<dim3(TLEN/128, HEADS, BATCH), 256, ATT_SMEM>>>();
    gemm_ts<1><<<dim3(8, 32), 256, GEMM_SMEM>>>(bo, out);
}